// round 1
// baseline (speedup 1.0000x reference)
#include <cuda_runtime.h>
#include <cuda_bf16.h>
#include <cstdint>

#define NMAX   100000
#define BMAX   2048
#define NSPLIT 4
#define LDQ 72
#define LDH 72
#define LDV 72

// ---------------- scratch (static device globals; no runtime allocation) ----------------
__device__ __nv_bfloat16 g_keys_bf[2][NMAX * 64];    // bf16 keys per layer (0: items, 1: users)
__device__ __nv_bfloat16 g_hidden_bf[2][NMAX * 64];  // bf16 hidden per layer
__device__ float         g_S[2][64];                 // column sums of keys
__device__ float         g_q[2][BMAX * 64];          // gathered queries fp32
__device__ __nv_bfloat16 g_qbf[2][BMAX * 64];        // gathered queries bf16
__device__ float         g_num[2][NSPLIT][BMAX * 64];// partial attention numerators
__device__ float         g_den[2][NSPLIT][BMAX];     // partial softmax denominators
__device__ float         g_og[2][BMAX * 128];        // concat(q, out)

// ---------------- helpers ----------------
__device__ __forceinline__ void mma16816(float c[4],
                                         uint32_t a0, uint32_t a1, uint32_t a2, uint32_t a3,
                                         uint32_t b0, uint32_t b1) {
    asm volatile(
        "mma.sync.aligned.m16n8k16.row.col.f32.bf16.bf16.f32 "
        "{%0,%1,%2,%3}, {%4,%5,%6,%7}, {%8,%9}, {%0,%1,%2,%3};"
        : "+f"(c[0]), "+f"(c[1]), "+f"(c[2]), "+f"(c[3])
        : "r"(a0), "r"(a1), "r"(a2), "r"(a3), "r"(b0), "r"(b1));
}

__device__ __forceinline__ uint32_t pack_bf2(float lo, float hi) {
    __nv_bfloat162 h = __floats2bfloat162_rn(lo, hi);
    return *reinterpret_cast<uint32_t*>(&h);
}

// ---------------- kernel 1: zero S ----------------
__global__ void zero_kernel() {
    int t = threadIdx.x;
    if (t < 128) ((float*)g_S)[t] = 0.f;
}

// ---------------- kernel 2: hidden = relu(K @ W^T + b), bf16 copies, S sums ----------------
__global__ void __launch_bounds__(256) hidden_kernel(
    const float* __restrict__ user_emb, const float* __restrict__ item_emb,
    const int* __restrict__ all_user_ids, const int* __restrict__ all_item_ids,
    const float* __restrict__ uW, const float* __restrict__ ub,
    const float* __restrict__ iW, const float* __restrict__ ib,
    int Ni, int Nu)
{
    int l = blockIdx.y;
    const float* emb = (l == 0) ? item_emb : user_emb;
    const int*   ids = (l == 0) ? all_item_ids : all_user_ids;
    const float* W   = (l == 0) ? uW : iW;
    const float* bb  = (l == 0) ? ub : ib;
    int Nk = (l == 0) ? Ni : Nu;

    __shared__ float sW[64 * 68];   // sW[o][d], padded row stride 68 (16B aligned, conflict-free f4)
    __shared__ float sBias[64];
    __shared__ float sK[16 * 64];
    __shared__ float sred[256];

    int tid = threadIdx.x;
    for (int e = tid; e < 64 * 64; e += 256) {
        int o = e >> 6, d = e & 63;
        sW[o * 68 + d] = W[e];
    }
    if (tid < 64) sBias[tid] = bb[tid];

    float sacc = 0.f;
    int ntiles = (Nk + 15) / 16;
    int o = tid & 63;
    int rl0 = tid >> 6;

    for (int t = blockIdx.x; t < ntiles; t += gridDim.x) {
        int base = t * 16;
        __syncthreads();
        for (int e = tid; e < 16 * 64; e += 256) {
            int rl = e >> 6, d = e & 63;
            int j = base + rl;
            float v = 0.f;
            if (j < Nk) {
                v = emb[(size_t)ids[j] * 64 + d];
                g_keys_bf[l][(size_t)j * 64 + d] = __float2bfloat16(v);
                sacc += v;
            }
            sK[e] = v;
        }
        __syncthreads();
        const float4* wv = (const float4*)&sW[o * 68];
        for (int rl = rl0; rl < 16; rl += 4) {
            int j = base + rl;
            if (j < Nk) {
                float acc = sBias[o];
                const float4* kv4 = (const float4*)&sK[rl * 64];
                #pragma unroll
                for (int d4 = 0; d4 < 16; d4++) {
                    float4 k4 = kv4[d4];
                    float4 w4 = wv[d4];
                    acc += k4.x * w4.x + k4.y * w4.y + k4.z * w4.z + k4.w * w4.w;
                }
                g_hidden_bf[l][(size_t)j * 64 + o] = __float2bfloat16(fmaxf(acc, 0.f));
            }
        }
    }
    __syncthreads();
    sred[tid] = sacc;
    __syncthreads();
    if (tid < 64)
        atomicAdd(&g_S[l][tid], sred[tid] + sred[tid + 64] + sred[tid + 128] + sred[tid + 192]);
}

// ---------------- kernel 3: gather queries ----------------
__global__ void gather_q_kernel(
    const float* __restrict__ user_emb, const float* __restrict__ item_emb,
    const int* __restrict__ user_id, const int* __restrict__ item_id,
    const int* __restrict__ all_user_ids, const int* __restrict__ all_item_ids, int B)
{
    int idx = blockIdx.x * blockDim.x + threadIdx.x;
    int total = B * 64;
    if (idx < 2 * total) {
        int l = idx / total;
        int e = idx - l * total;
        int b = e >> 6, d = e & 63;
        float v;
        if (l == 0) v = user_emb[(size_t)all_user_ids[user_id[b]] * 64 + d];
        else        v = item_emb[(size_t)all_item_ids[item_id[b]] * 64 + d];
        g_q[l][e]   = v;
        g_qbf[l][e] = __float2bfloat16(v);
    }
}

// ---------------- kernel 4: flash attention (no-max softmax) ----------------
__global__ void __launch_bounds__(256) flash_kernel(int B, int Ni, int Nu) {
    int l  = blockIdx.z;
    int Nk = (l == 0) ? Ni : Nu;
    int qb = blockIdx.x, split = blockIdx.y;

    const __nv_bfloat16* __restrict__ Hs = g_hidden_bf[l];
    const __nv_bfloat16* __restrict__ Ks = g_keys_bf[l];
    const __nv_bfloat16* __restrict__ Qs = g_qbf[l];

    __shared__ __nv_bfloat16 sQ[128 * LDQ];
    __shared__ __nv_bfloat16 sH[64 * LDH];
    __shared__ __nv_bfloat16 sV[64 * LDV];  // transposed: sV[dim][key]

    int tid = threadIdx.x;

    // load Q tile (bf16)
    for (int e = tid; e < 128 * 64; e += 256) {
        int r = e >> 6, d = e & 63;
        int qrow = qb * 128 + r;
        sQ[r * LDQ + d] = (qrow < B) ? Qs[(size_t)qrow * 64 + d] : __float2bfloat16(0.f);
    }

    int chunk = (Nk + NSPLIT - 1) / NSPLIT;
    int kv0   = split * chunk;
    int kvend = min(kv0 + chunk, Nk);

    int lane = tid & 31, warp = tid >> 5;
    int gid  = lane >> 2, tig = lane & 3;
    int moff = warp * 16;

    float o_acc[8][4];
    #pragma unroll
    for (int j = 0; j < 8; j++)
        #pragma unroll
        for (int q = 0; q < 4; q++) o_acc[j][q] = 0.f;
    float den0 = 0.f, den1 = 0.f;

    for (int kv = kv0; kv < kvend; kv += 64) {
        __syncthreads();
        // load H tile + V tile (transposed)
        for (int e = tid; e < 64 * 64; e += 256) {
            int r = e >> 6, d = e & 63;
            int krow = kv + r;
            __nv_bfloat16 hv, vv;
            if (krow < kvend) {
                hv = Hs[(size_t)krow * 64 + d];
                vv = Ks[(size_t)krow * 64 + d];
            } else {
                hv = __float2bfloat16(0.f);
                vv = __float2bfloat16(0.f);
            }
            sH[r * LDH + d] = hv;
            sV[d * LDV + r] = vv;
        }
        __syncthreads();

        // S = Q @ H^T
        float s[8][4];
        #pragma unroll
        for (int j = 0; j < 8; j++)
            #pragma unroll
            for (int q = 0; q < 4; q++) s[j][q] = 0.f;

        #pragma unroll
        for (int kk = 0; kk < 4; kk++) {
            int kc = kk * 16 + 2 * tig;
            uint32_t a0 = *(const uint32_t*)&sQ[(moff + gid)     * LDQ + kc];
            uint32_t a1 = *(const uint32_t*)&sQ[(moff + gid + 8) * LDQ + kc];
            uint32_t a2 = *(const uint32_t*)&sQ[(moff + gid)     * LDQ + kc + 8];
            uint32_t a3 = *(const uint32_t*)&sQ[(moff + gid + 8) * LDQ + kc + 8];
            #pragma unroll
            for (int j = 0; j < 8; j++) {
                uint32_t b0 = *(const uint32_t*)&sH[(8 * j + gid) * LDH + kc];
                uint32_t b1 = *(const uint32_t*)&sH[(8 * j + gid) * LDH + kc + 8];
                mma16816(s[j], a0, a1, a2, a3, b0, b1);
            }
        }

        // exp + mask + denominator; keep P as packed bf16 A-fragments
        uint32_t p0[8], p1[8];
        #pragma unroll
        for (int j = 0; j < 8; j++) {
            int col = kv + 8 * j + 2 * tig;
            float e0 = (col     < kvend) ? __expf(s[j][0]) : 0.f;
            float e1 = (col + 1 < kvend) ? __expf(s[j][1]) : 0.f;
            float e2 = (col     < kvend) ? __expf(s[j][2]) : 0.f;
            float e3 = (col + 1 < kvend) ? __expf(s[j][3]) : 0.f;
            den0 += e0 + e1;
            den1 += e2 + e3;
            p0[j] = pack_bf2(e0, e1);
            p1[j] = pack_bf2(e2, e3);
        }

        // O += P @ V
        #pragma unroll
        for (int kk = 0; kk < 4; kk++) {
            uint32_t a0 = p0[2 * kk],     a1 = p1[2 * kk];
            uint32_t a2 = p0[2 * kk + 1], a3 = p1[2 * kk + 1];
            int kc = kk * 16 + 2 * tig;
            #pragma unroll
            for (int j = 0; j < 8; j++) {
                uint32_t b0 = *(const uint32_t*)&sV[(8 * j + gid) * LDV + kc];
                uint32_t b1 = *(const uint32_t*)&sV[(8 * j + gid) * LDV + kc + 8];
                mma16816(o_acc[j], a0, a1, a2, a3, b0, b1);
            }
        }
    }

    // reduce denominator across the 4 lanes sharing a row
    den0 += __shfl_xor_sync(0xffffffffu, den0, 1);
    den0 += __shfl_xor_sync(0xffffffffu, den0, 2);
    den1 += __shfl_xor_sync(0xffffffffu, den1, 1);
    den1 += __shfl_xor_sync(0xffffffffu, den1, 2);

    int r0 = qb * 128 + moff + gid;
    if (tig == 0) {
        if (r0 < B)     g_den[l][split][r0]     = den0;
        if (r0 + 8 < B) g_den[l][split][r0 + 8] = den1;
    }
    #pragma unroll
    for (int j = 0; j < 8; j++) {
        int c = 8 * j + 2 * tig;
        if (r0 < B) {
            g_num[l][split][r0 * 64 + c]     = o_acc[j][0];
            g_num[l][split][r0 * 64 + c + 1] = o_acc[j][1];
        }
        if (r0 + 8 < B) {
            g_num[l][split][(r0 + 8) * 64 + c]     = o_acc[j][2];
            g_num[l][split][(r0 + 8) * 64 + c + 1] = o_acc[j][3];
        }
    }
}

// ---------------- kernel 5: combine splits + epilogue + build og ----------------
__global__ void __launch_bounds__(256) epilogue_kernel(
    const float* __restrict__ uW1, const float* __restrict__ uW2,
    const float* __restrict__ iW1, const float* __restrict__ iW2, int B)
{
    int l = blockIdx.y;
    const float* W1 = (l == 0) ? uW1 : iW1;
    const float* W2 = (l == 0) ? uW2 : iW2;

    __shared__ float sW1[64 * 68];
    __shared__ float sW2[64 * 68];
    __shared__ float sS[64];
    __shared__ float st1[16 * 64];
    __shared__ float st2[16 * 64];
    __shared__ float sden[16];

    int tid = threadIdx.x;
    for (int e = tid; e < 64 * 64; e += 256) {
        int o = e >> 6, d = e & 63;
        sW1[o * 68 + d] = W1[e];
        sW2[o * 68 + d] = W2[e];
    }
    if (tid < 64) sS[tid] = g_S[l][tid];

    int r0 = blockIdx.x * 16;
    if (tid < 16) {
        float dsum = 0.f;
        #pragma unroll
        for (int s = 0; s < NSPLIT; s++) dsum += g_den[l][s][r0 + tid];
        sden[tid] = dsum;
    }
    __syncthreads();

    for (int e = tid; e < 16 * 64; e += 256) {
        int rl = e >> 6, d = e & 63;
        int r = r0 + rl;
        float nsum = 0.f;
        #pragma unroll
        for (int s = 0; s < NSPLIT; s++) nsum += g_num[l][s][r * 64 + d];
        float q  = g_q[l][r * 64 + d];
        float q2 = q + nsum / sden[rl];
        st1[e] = q2 + sS[d];
        st2[e] = q2 * sS[d];
        g_og[l][r * 128 + d] = q;       // first half of og = original embedding
    }
    __syncthreads();

    int o = tid & 63, rl0 = tid >> 6;
    for (int rl = rl0; rl < 16; rl += 4) {
        float acc = 0.f;
        const float4* t1 = (const float4*)&st1[rl * 64];
        const float4* t2 = (const float4*)&st2[rl * 64];
        const float4* w1 = (const float4*)&sW1[o * 68];
        const float4* w2 = (const float4*)&sW2[o * 68];
        #pragma unroll
        for (int d4 = 0; d4 < 16; d4++) {
            float4 a = t1[d4], b = w1[d4], c = t2[d4], e4 = w2[d4];
            acc += a.x * b.x + a.y * b.y + a.z * b.z + a.w * b.w
                 + c.x * e4.x + c.y * e4.y + c.z * e4.z + c.w * e4.w;
        }
        float out = (acc > 0.f) ? acc : 0.01f * acc;   // leaky_relu(0.01)
        g_og[l][(r0 + rl) * 128 + 64 + o] = out;
    }
}

// ---------------- kernel 6: C = og_user^T @ og_item  [128 x 128] ----------------
__global__ void __launch_bounds__(256) final_kernel(float* __restrict__ out, int B) {
    int bi = blockIdx.x & 7, bj = blockIdx.x >> 3;
    __shared__ float sU[64 * 16];
    __shared__ float sI[64 * 16];
    int tid = threadIdx.x;
    int ty = tid >> 4, tx = tid & 15;
    float acc = 0.f;
    for (int k0 = 0; k0 < B; k0 += 64) {
        __syncthreads();
        for (int e = tid; e < 64 * 16; e += 256) {
            int kk = e >> 4, c = e & 15;
            sU[e] = g_og[0][(k0 + kk) * 128 + bi * 16 + c];
            sI[e] = g_og[1][(k0 + kk) * 128 + bj * 16 + c];
        }
        __syncthreads();
        #pragma unroll
        for (int kk = 0; kk < 64; kk++)
            acc += sU[kk * 16 + ty] * sI[kk * 16 + tx];
    }
    out[(bi * 16 + ty) * 128 + bj * 16 + tx] = acc;
}

// ---------------- launch ----------------
extern "C" void kernel_launch(void* const* d_in, const int* in_sizes, int n_in,
                              void* d_out, int out_size) {
    const float* user_emb  = (const float*)d_in[0];
    const float* item_emb  = (const float*)d_in[1];
    const float* u_attn_W  = (const float*)d_in[2];
    const float* u_attn_b  = (const float*)d_in[3];
    const float* u_W1      = (const float*)d_in[4];
    const float* u_W2      = (const float*)d_in[5];
    const float* i_attn_W  = (const float*)d_in[6];
    const float* i_attn_b  = (const float*)d_in[7];
    const float* i_W1      = (const float*)d_in[8];
    const float* i_W2      = (const float*)d_in[9];
    const int*   user_id   = (const int*)d_in[10];
    const int*   item_id   = (const int*)d_in[11];
    const int*   all_user_ids = (const int*)d_in[12];
    const int*   all_item_ids = (const int*)d_in[13];

    int B  = in_sizes[10]; if (B > BMAX) B = BMAX;
    int Nu = in_sizes[12]; if (Nu > NMAX) Nu = NMAX;
    int Ni = in_sizes[13]; if (Ni > NMAX) Ni = NMAX;
    float* out = (float*)d_out;

    zero_kernel<<<1, 128>>>();
    hidden_kernel<<<dim3(256, 2), 256>>>(user_emb, item_emb, all_user_ids, all_item_ids,
                                         u_attn_W, u_attn_b, i_attn_W, i_attn_b, Ni, Nu);
    int total = B * 64;
    gather_q_kernel<<<(2 * total + 255) / 256, 256>>>(user_emb, item_emb, user_id, item_id,
                                                      all_user_ids, all_item_ids, B);
    int qblocks = (B + 127) / 128;
    flash_kernel<<<dim3(qblocks, NSPLIT, 2), 256>>>(B, Ni, Nu);
    epilogue_kernel<<<dim3(B / 16, 2), 256>>>(u_W1, u_W2, i_W1, i_W2, B);
    final_kernel<<<64, 256>>>(out, B);
}

// round 2
// speedup vs baseline: 2.7546x; 2.7546x over previous
#include <cuda_runtime.h>
#include <cuda_bf16.h>
#include <cstdint>

#define NMAX   100000
#define BMAX   2048
#define NSPLIT 9
#define LDH 72   // bf16 elems; 144B row stride -> conflict-free ldmatrix
#define LDV 72

// ---------------- scratch (static device globals; no runtime allocation) ----------------
__device__ __nv_bfloat16 g_keys_bf[2][NMAX * 64];    // bf16 keys per layer
__device__ __nv_bfloat16 g_hidden_bf[2][NMAX * 64];  // bf16 hidden per layer
__device__ float         g_S[2][64];                 // column sums of keys
__device__ float         g_q[2][BMAX * 64];          // gathered queries fp32
__device__ __nv_bfloat16 g_qbf[2][BMAX * 64];        // gathered queries bf16
__device__ float         g_num[2][NSPLIT][BMAX * 64];// partial attention numerators
__device__ float         g_den[2][NSPLIT][BMAX];     // partial softmax denominators
__device__ float         g_og[2][BMAX * 128];        // concat(q, out)

// ---------------- PTX helpers ----------------
__device__ __forceinline__ void mma16816(float c[4],
                                         uint32_t a0, uint32_t a1, uint32_t a2, uint32_t a3,
                                         uint32_t b0, uint32_t b1) {
    asm volatile(
        "mma.sync.aligned.m16n8k16.row.col.f32.bf16.bf16.f32 "
        "{%0,%1,%2,%3}, {%4,%5,%6,%7}, {%8,%9}, {%0,%1,%2,%3};"
        : "+f"(c[0]), "+f"(c[1]), "+f"(c[2]), "+f"(c[3])
        : "r"(a0), "r"(a1), "r"(a2), "r"(a3), "r"(b0), "r"(b1));
}

__device__ __forceinline__ uint32_t pack_bf2(float lo, float hi) {
    __nv_bfloat162 h = __floats2bfloat162_rn(lo, hi);
    return *reinterpret_cast<uint32_t*>(&h);
}

__device__ __forceinline__ uint32_t smem_u32(const void* p) {
    return (uint32_t)__cvta_generic_to_shared(p);
}

__device__ __forceinline__ void ldsm_x4(uint32_t& d0, uint32_t& d1, uint32_t& d2, uint32_t& d3,
                                        uint32_t a) {
    asm volatile("ldmatrix.sync.aligned.m8n8.x4.shared.b16 {%0,%1,%2,%3}, [%4];"
                 : "=r"(d0), "=r"(d1), "=r"(d2), "=r"(d3) : "r"(a));
}

__device__ __forceinline__ void ldsm_x4t(uint32_t& d0, uint32_t& d1, uint32_t& d2, uint32_t& d3,
                                         uint32_t a) {
    asm volatile("ldmatrix.sync.aligned.m8n8.x4.trans.shared.b16 {%0,%1,%2,%3}, [%4];"
                 : "=r"(d0), "=r"(d1), "=r"(d2), "=r"(d3) : "r"(a));
}

__device__ __forceinline__ void cp16(uint32_t saddr, const void* g, int sz) {
    asm volatile("cp.async.cg.shared.global [%0], [%1], 16, %2;"
                 :: "r"(saddr), "l"(g), "r"(sz));
}
__device__ __forceinline__ void cp_commit() {
    asm volatile("cp.async.commit_group;" ::: "memory");
}
__device__ __forceinline__ void cp_wait1() {
    asm volatile("cp.async.wait_group 1;" ::: "memory");
}

// ---------------- kernel 1: zero S ----------------
__global__ void zero_kernel() {
    int t = threadIdx.x;
    if (t < 128) ((float*)g_S)[t] = 0.f;
}

// ---------------- kernel 2: hidden = relu(K @ W^T + b), bf16 copies, S sums ----------------
__global__ void __launch_bounds__(256) hidden_kernel(
    const float* __restrict__ user_emb, const float* __restrict__ item_emb,
    const int* __restrict__ all_user_ids, const int* __restrict__ all_item_ids,
    const float* __restrict__ uW, const float* __restrict__ ub,
    const float* __restrict__ iW, const float* __restrict__ ib,
    int Ni, int Nu)
{
    int l = blockIdx.y;
    const float* emb = (l == 0) ? item_emb : user_emb;
    const int*   ids = (l == 0) ? all_item_ids : all_user_ids;
    const float* W   = (l == 0) ? uW : iW;
    const float* bb  = (l == 0) ? ub : ib;
    int Nk = (l == 0) ? Ni : Nu;

    __shared__ float sW[64 * 68];
    __shared__ float sBias[64];
    __shared__ float sK[16 * 64];
    __shared__ float sred[256];

    int tid = threadIdx.x;
    for (int e = tid; e < 64 * 64; e += 256) {
        int o = e >> 6, d = e & 63;
        sW[o * 68 + d] = W[e];
    }
    if (tid < 64) sBias[tid] = bb[tid];

    float sacc = 0.f;
    int ntiles = (Nk + 15) / 16;
    int o = tid & 63;
    int rl0 = tid >> 6;

    for (int t = blockIdx.x; t < ntiles; t += gridDim.x) {
        int base = t * 16;
        __syncthreads();
        for (int e = tid; e < 16 * 64; e += 256) {
            int rl = e >> 6, d = e & 63;
            int j = base + rl;
            float v = 0.f;
            if (j < Nk) {
                v = emb[(size_t)ids[j] * 64 + d];
                g_keys_bf[l][(size_t)j * 64 + d] = __float2bfloat16(v);
                sacc += v;
            }
            sK[e] = v;
        }
        __syncthreads();
        const float4* wv = (const float4*)&sW[o * 68];
        for (int rl = rl0; rl < 16; rl += 4) {
            int j = base + rl;
            if (j < Nk) {
                float acc = sBias[o];
                const float4* kv4 = (const float4*)&sK[rl * 64];
                #pragma unroll
                for (int d4 = 0; d4 < 16; d4++) {
                    float4 k4 = kv4[d4];
                    float4 w4 = wv[d4];
                    acc += k4.x * w4.x + k4.y * w4.y + k4.z * w4.z + k4.w * w4.w;
                }
                g_hidden_bf[l][(size_t)j * 64 + o] = __float2bfloat16(fmaxf(acc, 0.f));
            }
        }
    }
    __syncthreads();
    sred[tid] = sacc;
    __syncthreads();
    if (tid < 64)
        atomicAdd(&g_S[l][tid], sred[tid] + sred[tid + 64] + sred[tid + 128] + sred[tid + 192]);
}

// ---------------- kernel 3: gather queries ----------------
__global__ void gather_q_kernel(
    const float* __restrict__ user_emb, const float* __restrict__ item_emb,
    const int* __restrict__ user_id, const int* __restrict__ item_id,
    const int* __restrict__ all_user_ids, const int* __restrict__ all_item_ids, int B)
{
    int idx = blockIdx.x * blockDim.x + threadIdx.x;
    int total = B * 64;
    if (idx < 2 * total) {
        int l = idx / total;
        int e = idx - l * total;
        int b = e >> 6, d = e & 63;
        float v;
        if (l == 0) v = user_emb[(size_t)all_user_ids[user_id[b]] * 64 + d];
        else        v = item_emb[(size_t)all_item_ids[item_id[b]] * 64 + d];
        g_q[l][e]   = v;
        g_qbf[l][e] = __float2bfloat16(v);
    }
}

// ---------------- kernel 4: flash attention (double-buffered cp.async + ldmatrix) -------
__device__ __forceinline__ void load_tile(const __nv_bfloat16* __restrict__ Hs,
                                          const __nv_bfloat16* __restrict__ Ks,
                                          __nv_bfloat16* sH, __nv_bfloat16* sV,
                                          int kv, int kvend, int tid)
{
    #pragma unroll
    for (int i = 0; i < 2; i++) {
        int c = tid + i * 256;          // 512 16B-chunks per 64x64 tile
        int row = c >> 3, col16 = c & 7;
        int rg = kv + row;
        bool valid = rg < kvend;
        int rr = valid ? rg : 0;
        int sz = valid ? 16 : 0;
        const void* gH = &Hs[(size_t)rr * 64 + col16 * 8];
        const void* gK = &Ks[(size_t)rr * 64 + col16 * 8];
        cp16(smem_u32(&sH[row * LDH + col16 * 8]), gH, sz);
        cp16(smem_u32(&sV[row * LDV + col16 * 8]), gK, sz);
    }
}

__global__ void __launch_bounds__(256, 2) flash_kernel(int B, int Ni, int Nu) {
    int l  = blockIdx.z;
    int Nk = (l == 0) ? Ni : Nu;
    int qb = blockIdx.x, split = blockIdx.y;

    const __nv_bfloat16* __restrict__ Hs = g_hidden_bf[l];
    const __nv_bfloat16* __restrict__ Ks = g_keys_bf[l];
    const __nv_bfloat16* __restrict__ Qs = g_qbf[l];

    __shared__ __nv_bfloat16 sH[2][64 * LDH];
    __shared__ __nv_bfloat16 sV[2][64 * LDV];

    int tid = threadIdx.x;
    int lane = tid & 31, warp = tid >> 5;
    int gid  = lane >> 2, tig = lane & 3;
    int moff = warp * 16;

    // ---- preload Q fragments (reused across the whole KV sweep) ----
    int qrow0 = qb * 128 + moff + gid;
    int qrow1 = qrow0 + 8;
    uint32_t qa[4][4];
    #pragma unroll
    for (int kk = 0; kk < 4; kk++) {
        int kc = kk * 16 + 2 * tig;
        qa[kk][0] = (qrow0 < B) ? *(const uint32_t*)&Qs[(size_t)qrow0 * 64 + kc] : 0u;
        qa[kk][1] = (qrow1 < B) ? *(const uint32_t*)&Qs[(size_t)qrow1 * 64 + kc] : 0u;
        qa[kk][2] = (qrow0 < B) ? *(const uint32_t*)&Qs[(size_t)qrow0 * 64 + kc + 8] : 0u;
        qa[kk][3] = (qrow1 < B) ? *(const uint32_t*)&Qs[(size_t)qrow1 * 64 + kc + 8] : 0u;
    }

    int chunk = (Nk + NSPLIT - 1) / NSPLIT;
    int kv0   = split * chunk;
    int kvend = min(kv0 + chunk, Nk);
    int ntile = (kvend > kv0) ? ((kvend - kv0 + 63) >> 6) : 0;

    // prologue: two stages in flight
    load_tile(Hs, Ks, sH[0], sV[0], kv0,      kvend, tid); cp_commit();
    load_tile(Hs, Ks, sH[1], sV[1], kv0 + 64, kvend, tid); cp_commit();

    float o_acc[8][4];
    #pragma unroll
    for (int j = 0; j < 8; j++)
        #pragma unroll
        for (int q = 0; q < 4; q++) o_acc[j][q] = 0.f;
    float den0 = 0.f, den1 = 0.f;

    // ldmatrix lane addressing: matrix m = lane/8, row r = lane%8
    int lm_m = lane >> 3, lm_r = lane & 7;

    for (int t = 0; t < ntile; t++) {
        int stage = t & 1;
        int kv = kv0 + t * 64;
        cp_wait1();
        __syncthreads();

        const __nv_bfloat16* tH = sH[stage];
        const __nv_bfloat16* tV = sV[stage];

        // ---- S = Q @ H^T ----
        float s[8][4];
        #pragma unroll
        for (int j = 0; j < 8; j++) {
            uint32_t hb0, hb1, hb2, hb3, hb4, hb5, hb6, hb7;
            uint32_t a0 = smem_u32(&tH[(8 * j + lm_r) * LDH + lm_m * 8]);
            ldsm_x4(hb0, hb1, hb2, hb3, a0);
            ldsm_x4(hb4, hb5, hb6, hb7, a0 + 32 * 2);
            #pragma unroll
            for (int q = 0; q < 4; q++) s[j][q] = 0.f;
            mma16816(s[j], qa[0][0], qa[0][1], qa[0][2], qa[0][3], hb0, hb1);
            mma16816(s[j], qa[1][0], qa[1][1], qa[1][2], qa[1][3], hb2, hb3);
            mma16816(s[j], qa[2][0], qa[2][1], qa[2][2], qa[2][3], hb4, hb5);
            mma16816(s[j], qa[3][0], qa[3][1], qa[3][2], qa[3][3], hb6, hb7);
        }

        // ---- exp (no max-subtraction; logits are tiny) + pack to bf16 A-fragments ----
        uint32_t p0[8], p1[8];
        #pragma unroll
        for (int j = 0; j < 8; j++) {
            int col = kv + 8 * j + 2 * tig;
            float e0 = (col     < kvend) ? __expf(s[j][0]) : 0.f;
            float e1 = (col + 1 < kvend) ? __expf(s[j][1]) : 0.f;
            float e2 = (col     < kvend) ? __expf(s[j][2]) : 0.f;
            float e3 = (col + 1 < kvend) ? __expf(s[j][3]) : 0.f;
            den0 += e0 + e1;
            den1 += e2 + e3;
            p0[j] = pack_bf2(e0, e1);
            p1[j] = pack_bf2(e2, e3);
        }

        // ---- O += P @ V  (V row-major, fragments via ldmatrix.trans) ----
        #pragma unroll
        for (int kk = 0; kk < 4; kk++) {
            uint32_t a0 = p0[2 * kk],     a1 = p1[2 * kk];
            uint32_t a2 = p0[2 * kk + 1], a3 = p1[2 * kk + 1];
            #pragma unroll
            for (int j0 = 0; j0 < 8; j0 += 2) {
                // x4: matrices {key-blk 2kk, dim j0}, {2kk+1, j0}, {2kk, j0+1}, {2kk+1, j0+1}
                uint32_t v0, v1, v2, v3;
                uint32_t a = smem_u32(&tV[(16 * kk + (lm_m & 1) * 8 + lm_r) * LDV
                                          + (j0 + (lm_m >> 1)) * 8]);
                ldsm_x4t(v0, v1, v2, v3, a);
                mma16816(o_acc[j0],     a0, a1, a2, a3, v0, v1);
                mma16816(o_acc[j0 + 1], a0, a1, a2, a3, v2, v3);
            }
        }

        __syncthreads();
        if (t + 2 < ntile)
            load_tile(Hs, Ks, sH[stage], sV[stage], kv + 128, kvend, tid);
        cp_commit();
    }

    // reduce denominator across the 4 lanes sharing a row
    den0 += __shfl_xor_sync(0xffffffffu, den0, 1);
    den0 += __shfl_xor_sync(0xffffffffu, den0, 2);
    den1 += __shfl_xor_sync(0xffffffffu, den1, 1);
    den1 += __shfl_xor_sync(0xffffffffu, den1, 2);

    int r0 = qb * 128 + moff + gid;
    if (tig == 0) {
        if (r0 < B)     g_den[l][split][r0]     = den0;
        if (r0 + 8 < B) g_den[l][split][r0 + 8] = den1;
    }
    #pragma unroll
    for (int j = 0; j < 8; j++) {
        int c = 8 * j + 2 * tig;
        if (r0 < B) {
            g_num[l][split][r0 * 64 + c]     = o_acc[j][0];
            g_num[l][split][r0 * 64 + c + 1] = o_acc[j][1];
        }
        if (r0 + 8 < B) {
            g_num[l][split][(r0 + 8) * 64 + c]     = o_acc[j][2];
            g_num[l][split][(r0 + 8) * 64 + c + 1] = o_acc[j][3];
        }
    }
}

// ---------------- kernel 5: combine splits + epilogue + build og ----------------
__global__ void __launch_bounds__(256) epilogue_kernel(
    const float* __restrict__ uW1, const float* __restrict__ uW2,
    const float* __restrict__ iW1, const float* __restrict__ iW2, int B)
{
    int l = blockIdx.y;
    const float* W1 = (l == 0) ? uW1 : iW1;
    const float* W2 = (l == 0) ? uW2 : iW2;

    __shared__ float sW1[64 * 68];
    __shared__ float sW2[64 * 68];
    __shared__ float sS[64];
    __shared__ float st1[16 * 64];
    __shared__ float st2[16 * 64];
    __shared__ float sden[16];

    int tid = threadIdx.x;
    for (int e = tid; e < 64 * 64; e += 256) {
        int o = e >> 6, d = e & 63;
        sW1[o * 68 + d] = W1[e];
        sW2[o * 68 + d] = W2[e];
    }
    if (tid < 64) sS[tid] = g_S[l][tid];

    int r0 = blockIdx.x * 16;
    if (tid < 16) {
        float dsum = 0.f;
        #pragma unroll
        for (int s = 0; s < NSPLIT; s++) dsum += g_den[l][s][r0 + tid];
        sden[tid] = dsum;
    }
    __syncthreads();

    for (int e = tid; e < 16 * 64; e += 256) {
        int rl = e >> 6, d = e & 63;
        int r = r0 + rl;
        float nsum = 0.f;
        #pragma unroll
        for (int s = 0; s < NSPLIT; s++) nsum += g_num[l][s][r * 64 + d];
        float q  = g_q[l][r * 64 + d];
        float q2 = q + nsum / sden[rl];
        st1[e] = q2 + sS[d];
        st2[e] = q2 * sS[d];
        g_og[l][r * 128 + d] = q;
    }
    __syncthreads();

    int o = tid & 63, rl0 = tid >> 6;
    for (int rl = rl0; rl < 16; rl += 4) {
        float acc = 0.f;
        const float4* t1 = (const float4*)&st1[rl * 64];
        const float4* t2 = (const float4*)&st2[rl * 64];
        const float4* w1 = (const float4*)&sW1[o * 68];
        const float4* w2 = (const float4*)&sW2[o * 68];
        #pragma unroll
        for (int d4 = 0; d4 < 16; d4++) {
            float4 a = t1[d4], b = w1[d4], c = t2[d4], e4 = w2[d4];
            acc += a.x * b.x + a.y * b.y + a.z * b.z + a.w * b.w
                 + c.x * e4.x + c.y * e4.y + c.z * e4.z + c.w * e4.w;
        }
        float out = (acc > 0.f) ? acc : 0.01f * acc;
        g_og[l][(r0 + rl) * 128 + 64 + o] = out;
    }
}

// ---------------- kernel 6: C = og_user^T @ og_item  [128 x 128] ----------------
__global__ void __launch_bounds__(256) final_kernel(float* __restrict__ out, int B) {
    int bi = blockIdx.x & 7, bj = blockIdx.x >> 3;
    __shared__ float sU[64 * 16];
    __shared__ float sI[64 * 16];
    int tid = threadIdx.x;
    int ty = tid >> 4, tx = tid & 15;
    float acc = 0.f;
    for (int k0 = 0; k0 < B; k0 += 64) {
        __syncthreads();
        for (int e = tid; e < 64 * 16; e += 256) {
            int kk = e >> 4, c = e & 15;
            sU[e] = g_og[0][(k0 + kk) * 128 + bi * 16 + c];
            sI[e] = g_og[1][(k0 + kk) * 128 + bj * 16 + c];
        }
        __syncthreads();
        #pragma unroll
        for (int kk = 0; kk < 64; kk++)
            acc += sU[kk * 16 + ty] * sI[kk * 16 + tx];
    }
    out[(bi * 16 + ty) * 128 + bj * 16 + tx] = acc;
}

// ---------------- launch ----------------
extern "C" void kernel_launch(void* const* d_in, const int* in_sizes, int n_in,
                              void* d_out, int out_size) {
    const float* user_emb  = (const float*)d_in[0];
    const float* item_emb  = (const float*)d_in[1];
    const float* u_attn_W  = (const float*)d_in[2];
    const float* u_attn_b  = (const float*)d_in[3];
    const float* u_W1      = (const float*)d_in[4];
    const float* u_W2      = (const float*)d_in[5];
    const float* i_attn_W  = (const float*)d_in[6];
    const float* i_attn_b  = (const float*)d_in[7];
    const float* i_W1      = (const float*)d_in[8];
    const float* i_W2      = (const float*)d_in[9];
    const int*   user_id   = (const int*)d_in[10];
    const int*   item_id   = (const int*)d_in[11];
    const int*   all_user_ids = (const int*)d_in[12];
    const int*   all_item_ids = (const int*)d_in[13];

    int B  = in_sizes[10]; if (B > BMAX) B = BMAX;
    int Nu = in_sizes[12]; if (Nu > NMAX) Nu = NMAX;
    int Ni = in_sizes[13]; if (Ni > NMAX) Ni = NMAX;
    float* out = (float*)d_out;

    zero_kernel<<<1, 128>>>();
    hidden_kernel<<<dim3(256, 2), 256>>>(user_emb, item_emb, all_user_ids, all_item_ids,
                                         u_attn_W, u_attn_b, i_attn_W, i_attn_b, Ni, Nu);
    int total = B * 64;
    gather_q_kernel<<<(2 * total + 255) / 256, 256>>>(user_emb, item_emb, user_id, item_id,
                                                      all_user_ids, all_item_ids, B);
    int qblocks = (B + 127) / 128;
    flash_kernel<<<dim3(qblocks, NSPLIT, 2), 256>>>(B, Ni, Nu);
    epilogue_kernel<<<dim3(B / 16, 2), 256>>>(u_W1, u_W2, i_W1, i_W2, B);
    final_kernel<<<64, 256>>>(out, B);
}

// round 3
// speedup vs baseline: 2.7562x; 1.0006x over previous
#include <cuda_runtime.h>
#include <cuda_bf16.h>
#include <cstdint>

#define NMAX   100000
#define BMAX   2048
#define NSPLIT 9
#define LDH 72   // bf16 elems; 144B row stride -> conflict-free ldmatrix
#define LDV 72

// ---------------- scratch (static device globals; no runtime allocation) ----------------
__device__ __nv_bfloat16 g_keys_bf[2][NMAX * 64];    // bf16 keys per layer
__device__ __nv_bfloat16 g_hidden_bf[2][NMAX * 64];  // bf16 hidden per layer
__device__ float         g_S[2][64];                 // column sums of keys
__device__ float         g_q[2][BMAX * 64];          // gathered queries fp32
__device__ __nv_bfloat16 g_qbf[2][BMAX * 64];        // gathered queries bf16
__device__ float         g_num[2][NSPLIT][BMAX * 64];// partial attention numerators
__device__ float         g_den[2][NSPLIT][BMAX];     // partial softmax denominators
__device__ float         g_og[2][BMAX * 128];        // concat(q, out)

// ---------------- PTX helpers ----------------
__device__ __forceinline__ void mma16816(float c[4],
                                         uint32_t a0, uint32_t a1, uint32_t a2, uint32_t a3,
                                         uint32_t b0, uint32_t b1) {
    asm volatile(
        "mma.sync.aligned.m16n8k16.row.col.f32.bf16.bf16.f32 "
        "{%0,%1,%2,%3}, {%4,%5,%6,%7}, {%8,%9}, {%0,%1,%2,%3};"
        : "+f"(c[0]), "+f"(c[1]), "+f"(c[2]), "+f"(c[3])
        : "r"(a0), "r"(a1), "r"(a2), "r"(a3), "r"(b0), "r"(b1));
}

__device__ __forceinline__ uint32_t pack_bf2(float lo, float hi) {
    __nv_bfloat162 h = __floats2bfloat162_rn(lo, hi);
    return *reinterpret_cast<uint32_t*>(&h);
}

__device__ __forceinline__ uint32_t smem_u32(const void* p) {
    return (uint32_t)__cvta_generic_to_shared(p);
}

__device__ __forceinline__ void ldsm_x4(uint32_t& d0, uint32_t& d1, uint32_t& d2, uint32_t& d3,
                                        uint32_t a) {
    asm volatile("ldmatrix.sync.aligned.m8n8.x4.shared.b16 {%0,%1,%2,%3}, [%4];"
                 : "=r"(d0), "=r"(d1), "=r"(d2), "=r"(d3) : "r"(a));
}

__device__ __forceinline__ void ldsm_x4t(uint32_t& d0, uint32_t& d1, uint32_t& d2, uint32_t& d3,
                                         uint32_t a) {
    asm volatile("ldmatrix.sync.aligned.m8n8.x4.trans.shared.b16 {%0,%1,%2,%3}, [%4];"
                 : "=r"(d0), "=r"(d1), "=r"(d2), "=r"(d3) : "r"(a));
}

__device__ __forceinline__ void cp16(uint32_t saddr, const void* g, int sz) {
    asm volatile("cp.async.cg.shared.global [%0], [%1], 16, %2;"
                 :: "r"(saddr), "l"(g), "r"(sz));
}
__device__ __forceinline__ void cp_commit() {
    asm volatile("cp.async.commit_group;" ::: "memory");
}
__device__ __forceinline__ void cp_wait1() {
    asm volatile("cp.async.wait_group 1;" ::: "memory");
}

// ---------------- kernel 1: zero S ----------------
__global__ void zero_kernel() {
    int t = threadIdx.x;
    if (t < 128) ((float*)g_S)[t] = 0.f;
}

// ---------------- kernel 2: hidden = relu(K @ W^T + b), bf16 copies, S sums ----------------
__global__ void __launch_bounds__(256) hidden_kernel(
    const float* __restrict__ user_emb, const float* __restrict__ item_emb,
    const int* __restrict__ all_user_ids, const int* __restrict__ all_item_ids,
    const float* __restrict__ uW, const float* __restrict__ ub,
    const float* __restrict__ iW, const float* __restrict__ ib,
    int Ni, int Nu)
{
    int l = blockIdx.y;
    const float* emb = (l == 0) ? item_emb : user_emb;
    const int*   ids = (l == 0) ? all_item_ids : all_user_ids;
    const float* W   = (l == 0) ? uW : iW;
    const float* bb  = (l == 0) ? ub : ib;
    int Nk = (l == 0) ? Ni : Nu;

    __shared__ float sW[64 * 68];
    __shared__ float sBias[64];
    __shared__ float sK[16 * 64];
    __shared__ float sred[256];

    int tid = threadIdx.x;
    for (int e = tid; e < 64 * 64; e += 256) {
        int o = e >> 6, d = e & 63;
        sW[o * 68 + d] = W[e];
    }
    if (tid < 64) sBias[tid] = bb[tid];

    float sacc = 0.f;
    int ntiles = (Nk + 15) / 16;
    int o = tid & 63;
    int rl0 = tid >> 6;

    for (int t = blockIdx.x; t < ntiles; t += gridDim.x) {
        int base = t * 16;
        __syncthreads();
        for (int e = tid; e < 16 * 64; e += 256) {
            int rl = e >> 6, d = e & 63;
            int j = base + rl;
            float v = 0.f;
            if (j < Nk) {
                v = emb[(size_t)ids[j] * 64 + d];
                g_keys_bf[l][(size_t)j * 64 + d] = __float2bfloat16(v);
                sacc += v;
            }
            sK[e] = v;
        }
        __syncthreads();
        const float4* wv = (const float4*)&sW[o * 68];
        for (int rl = rl0; rl < 16; rl += 4) {
            int j = base + rl;
            if (j < Nk) {
                float acc = sBias[o];
                const float4* kv4 = (const float4*)&sK[rl * 64];
                #pragma unroll
                for (int d4 = 0; d4 < 16; d4++) {
                    float4 k4 = kv4[d4];
                    float4 w4 = wv[d4];
                    acc += k4.x * w4.x + k4.y * w4.y + k4.z * w4.z + k4.w * w4.w;
                }
                g_hidden_bf[l][(size_t)j * 64 + o] = __float2bfloat16(fmaxf(acc, 0.f));
            }
        }
    }
    __syncthreads();
    sred[tid] = sacc;
    __syncthreads();
    if (tid < 64)
        atomicAdd(&g_S[l][tid], sred[tid] + sred[tid + 64] + sred[tid + 128] + sred[tid + 192]);
}

// ---------------- kernel 3: gather queries ----------------
__global__ void gather_q_kernel(
    const float* __restrict__ user_emb, const float* __restrict__ item_emb,
    const int* __restrict__ user_id, const int* __restrict__ item_id,
    const int* __restrict__ all_user_ids, const int* __restrict__ all_item_ids, int B)
{
    int idx = blockIdx.x * blockDim.x + threadIdx.x;
    int total = B * 64;
    if (idx < 2 * total) {
        int l = idx / total;
        int e = idx - l * total;
        int b = e >> 6, d = e & 63;
        float v;
        if (l == 0) v = user_emb[(size_t)all_user_ids[user_id[b]] * 64 + d];
        else        v = item_emb[(size_t)all_item_ids[item_id[b]] * 64 + d];
        g_q[l][e]   = v;
        g_qbf[l][e] = __float2bfloat16(v);
    }
}

// ---------------- kernel 4: flash attention (double-buffered cp.async + ldmatrix) -------
__device__ __forceinline__ void load_tile(const __nv_bfloat16* __restrict__ Hs,
                                          const __nv_bfloat16* __restrict__ Ks,
                                          __nv_bfloat16* sH, __nv_bfloat16* sV,
                                          int kv, int kvend, int tid)
{
    #pragma unroll
    for (int i = 0; i < 2; i++) {
        int c = tid + i * 256;          // 512 16B-chunks per 64x64 tile
        int row = c >> 3, col16 = c & 7;
        int rg = kv + row;
        bool valid = rg < kvend;
        int rr = valid ? rg : 0;
        int sz = valid ? 16 : 0;
        const void* gH = &Hs[(size_t)rr * 64 + col16 * 8];
        const void* gK = &Ks[(size_t)rr * 64 + col16 * 8];
        cp16(smem_u32(&sH[row * LDH + col16 * 8]), gH, sz);
        cp16(smem_u32(&sV[row * LDV + col16 * 8]), gK, sz);
    }
}

__global__ void __launch_bounds__(256, 2) flash_kernel(int B, int Ni, int Nu) {
    int l  = blockIdx.z;
    int Nk = (l == 0) ? Ni : Nu;
    int qb = blockIdx.x, split = blockIdx.y;

    const __nv_bfloat16* __restrict__ Hs = g_hidden_bf[l];
    const __nv_bfloat16* __restrict__ Ks = g_keys_bf[l];
    const __nv_bfloat16* __restrict__ Qs = g_qbf[l];

    __shared__ __nv_bfloat16 sH[2][64 * LDH];
    __shared__ __nv_bfloat16 sV[2][64 * LDV];

    int tid = threadIdx.x;
    int lane = tid & 31, warp = tid >> 5;
    int gid  = lane >> 2, tig = lane & 3;
    int moff = warp * 16;

    // ---- preload Q fragments (reused across the whole KV sweep) ----
    int qrow0 = qb * 128 + moff + gid;
    int qrow1 = qrow0 + 8;
    uint32_t qa[4][4];
    #pragma unroll
    for (int kk = 0; kk < 4; kk++) {
        int kc = kk * 16 + 2 * tig;
        qa[kk][0] = (qrow0 < B) ? *(const uint32_t*)&Qs[(size_t)qrow0 * 64 + kc] : 0u;
        qa[kk][1] = (qrow1 < B) ? *(const uint32_t*)&Qs[(size_t)qrow1 * 64 + kc] : 0u;
        qa[kk][2] = (qrow0 < B) ? *(const uint32_t*)&Qs[(size_t)qrow0 * 64 + kc + 8] : 0u;
        qa[kk][3] = (qrow1 < B) ? *(const uint32_t*)&Qs[(size_t)qrow1 * 64 + kc + 8] : 0u;
    }

    int chunk = (Nk + NSPLIT - 1) / NSPLIT;
    int kv0   = split * chunk;
    int kvend = min(kv0 + chunk, Nk);
    int ntile = (kvend > kv0) ? ((kvend - kv0 + 63) >> 6) : 0;

    // prologue: two stages in flight
    load_tile(Hs, Ks, sH[0], sV[0], kv0,      kvend, tid); cp_commit();
    load_tile(Hs, Ks, sH[1], sV[1], kv0 + 64, kvend, tid); cp_commit();

    float o_acc[8][4];
    #pragma unroll
    for (int j = 0; j < 8; j++)
        #pragma unroll
        for (int q = 0; q < 4; q++) o_acc[j][q] = 0.f;
    float den0 = 0.f, den1 = 0.f;

    // ldmatrix lane addressing: matrix m = lane/8, row r = lane%8
    int lm_m = lane >> 3, lm_r = lane & 7;

    for (int t = 0; t < ntile; t++) {
        int stage = t & 1;
        int kv = kv0 + t * 64;
        cp_wait1();
        __syncthreads();

        const __nv_bfloat16* tH = sH[stage];
        const __nv_bfloat16* tV = sV[stage];

        // ---- S = Q @ H^T ----
        float s[8][4];
        #pragma unroll
        for (int j = 0; j < 8; j++) {
            uint32_t hb0, hb1, hb2, hb3, hb4, hb5, hb6, hb7;
            uint32_t a0 = smem_u32(&tH[(8 * j + lm_r) * LDH + lm_m * 8]);
            ldsm_x4(hb0, hb1, hb2, hb3, a0);
            ldsm_x4(hb4, hb5, hb6, hb7, a0 + 32 * 2);
            #pragma unroll
            for (int q = 0; q < 4; q++) s[j][q] = 0.f;
            mma16816(s[j], qa[0][0], qa[0][1], qa[0][2], qa[0][3], hb0, hb1);
            mma16816(s[j], qa[1][0], qa[1][1], qa[1][2], qa[1][3], hb2, hb3);
            mma16816(s[j], qa[2][0], qa[2][1], qa[2][2], qa[2][3], hb4, hb5);
            mma16816(s[j], qa[3][0], qa[3][1], qa[3][2], qa[3][3], hb6, hb7);
        }

        // ---- exp (no max-subtraction; logits are tiny) + pack to bf16 A-fragments ----
        uint32_t p0[8], p1[8];
        #pragma unroll
        for (int j = 0; j < 8; j++) {
            int col = kv + 8 * j + 2 * tig;
            float e0 = (col     < kvend) ? __expf(s[j][0]) : 0.f;
            float e1 = (col + 1 < kvend) ? __expf(s[j][1]) : 0.f;
            float e2 = (col     < kvend) ? __expf(s[j][2]) : 0.f;
            float e3 = (col + 1 < kvend) ? __expf(s[j][3]) : 0.f;
            den0 += e0 + e1;
            den1 += e2 + e3;
            p0[j] = pack_bf2(e0, e1);
            p1[j] = pack_bf2(e2, e3);
        }

        // ---- O += P @ V  (V row-major, fragments via ldmatrix.trans) ----
        #pragma unroll
        for (int kk = 0; kk < 4; kk++) {
            uint32_t a0 = p0[2 * kk],     a1 = p1[2 * kk];
            uint32_t a2 = p0[2 * kk + 1], a3 = p1[2 * kk + 1];
            #pragma unroll
            for (int j0 = 0; j0 < 8; j0 += 2) {
                // x4: matrices {key-blk 2kk, dim j0}, {2kk+1, j0}, {2kk, j0+1}, {2kk+1, j0+1}
                uint32_t v0, v1, v2, v3;
                uint32_t a = smem_u32(&tV[(16 * kk + (lm_m & 1) * 8 + lm_r) * LDV
                                          + (j0 + (lm_m >> 1)) * 8]);
                ldsm_x4t(v0, v1, v2, v3, a);
                mma16816(o_acc[j0],     a0, a1, a2, a3, v0, v1);
                mma16816(o_acc[j0 + 1], a0, a1, a2, a3, v2, v3);
            }
        }

        __syncthreads();
        if (t + 2 < ntile)
            load_tile(Hs, Ks, sH[stage], sV[stage], kv + 128, kvend, tid);
        cp_commit();
    }

    // reduce denominator across the 4 lanes sharing a row
    den0 += __shfl_xor_sync(0xffffffffu, den0, 1);
    den0 += __shfl_xor_sync(0xffffffffu, den0, 2);
    den1 += __shfl_xor_sync(0xffffffffu, den1, 1);
    den1 += __shfl_xor_sync(0xffffffffu, den1, 2);

    int r0 = qb * 128 + moff + gid;
    if (tig == 0) {
        if (r0 < B)     g_den[l][split][r0]     = den0;
        if (r0 + 8 < B) g_den[l][split][r0 + 8] = den1;
    }
    #pragma unroll
    for (int j = 0; j < 8; j++) {
        int c = 8 * j + 2 * tig;
        if (r0 < B) {
            g_num[l][split][r0 * 64 + c]     = o_acc[j][0];
            g_num[l][split][r0 * 64 + c + 1] = o_acc[j][1];
        }
        if (r0 + 8 < B) {
            g_num[l][split][(r0 + 8) * 64 + c]     = o_acc[j][2];
            g_num[l][split][(r0 + 8) * 64 + c + 1] = o_acc[j][3];
        }
    }
}

// ---------------- kernel 5: combine splits + epilogue + build og ----------------
__global__ void __launch_bounds__(256) epilogue_kernel(
    const float* __restrict__ uW1, const float* __restrict__ uW2,
    const float* __restrict__ iW1, const float* __restrict__ iW2, int B)
{
    int l = blockIdx.y;
    const float* W1 = (l == 0) ? uW1 : iW1;
    const float* W2 = (l == 0) ? uW2 : iW2;

    __shared__ float sW1[64 * 68];
    __shared__ float sW2[64 * 68];
    __shared__ float sS[64];
    __shared__ float st1[16 * 64];
    __shared__ float st2[16 * 64];
    __shared__ float sden[16];

    int tid = threadIdx.x;
    for (int e = tid; e < 64 * 64; e += 256) {
        int o = e >> 6, d = e & 63;
        sW1[o * 68 + d] = W1[e];
        sW2[o * 68 + d] = W2[e];
    }
    if (tid < 64) sS[tid] = g_S[l][tid];

    int r0 = blockIdx.x * 16;
    if (tid < 16) {
        float dsum = 0.f;
        #pragma unroll
        for (int s = 0; s < NSPLIT; s++) dsum += g_den[l][s][r0 + tid];
        sden[tid] = dsum;
    }
    __syncthreads();

    for (int e = tid; e < 16 * 64; e += 256) {
        int rl = e >> 6, d = e & 63;
        int r = r0 + rl;
        float nsum = 0.f;
        #pragma unroll
        for (int s = 0; s < NSPLIT; s++) nsum += g_num[l][s][r * 64 + d];
        float q  = g_q[l][r * 64 + d];
        float q2 = q + nsum / sden[rl];
        st1[e] = q2 + sS[d];
        st2[e] = q2 * sS[d];
        g_og[l][r * 128 + d] = q;
    }
    __syncthreads();

    int o = tid & 63, rl0 = tid >> 6;
    for (int rl = rl0; rl < 16; rl += 4) {
        float acc = 0.f;
        const float4* t1 = (const float4*)&st1[rl * 64];
        const float4* t2 = (const float4*)&st2[rl * 64];
        const float4* w1 = (const float4*)&sW1[o * 68];
        const float4* w2 = (const float4*)&sW2[o * 68];
        #pragma unroll
        for (int d4 = 0; d4 < 16; d4++) {
            float4 a = t1[d4], b = w1[d4], c = t2[d4], e4 = w2[d4];
            acc += a.x * b.x + a.y * b.y + a.z * b.z + a.w * b.w
                 + c.x * e4.x + c.y * e4.y + c.z * e4.z + c.w * e4.w;
        }
        float out = (acc > 0.f) ? acc : 0.01f * acc;
        g_og[l][(r0 + rl) * 128 + 64 + o] = out;
    }
}

// ---------------- kernel 6: C = og_user^T @ og_item  [128 x 128] ----------------
__global__ void __launch_bounds__(256) final_kernel(float* __restrict__ out, int B) {
    int bi = blockIdx.x & 7, bj = blockIdx.x >> 3;
    __shared__ float sU[64 * 16];
    __shared__ float sI[64 * 16];
    int tid = threadIdx.x;
    int ty = tid >> 4, tx = tid & 15;
    float acc = 0.f;
    for (int k0 = 0; k0 < B; k0 += 64) {
        __syncthreads();
        for (int e = tid; e < 64 * 16; e += 256) {
            int kk = e >> 4, c = e & 15;
            sU[e] = g_og[0][(k0 + kk) * 128 + bi * 16 + c];
            sI[e] = g_og[1][(k0 + kk) * 128 + bj * 16 + c];
        }
        __syncthreads();
        #pragma unroll
        for (int kk = 0; kk < 64; kk++)
            acc += sU[kk * 16 + ty] * sI[kk * 16 + tx];
    }
    out[(bi * 16 + ty) * 128 + bj * 16 + tx] = acc;
}

// ---------------- launch ----------------
extern "C" void kernel_launch(void* const* d_in, const int* in_sizes, int n_in,
                              void* d_out, int out_size) {
    const float* user_emb  = (const float*)d_in[0];
    const float* item_emb  = (const float*)d_in[1];
    const float* u_attn_W  = (const float*)d_in[2];
    const float* u_attn_b  = (const float*)d_in[3];
    const float* u_W1      = (const float*)d_in[4];
    const float* u_W2      = (const float*)d_in[5];
    const float* i_attn_W  = (const float*)d_in[6];
    const float* i_attn_b  = (const float*)d_in[7];
    const float* i_W1      = (const float*)d_in[8];
    const float* i_W2      = (const float*)d_in[9];
    const int*   user_id   = (const int*)d_in[10];
    const int*   item_id   = (const int*)d_in[11];
    const int*   all_user_ids = (const int*)d_in[12];
    const int*   all_item_ids = (const int*)d_in[13];

    int B  = in_sizes[10]; if (B > BMAX) B = BMAX;
    int Nu = in_sizes[12]; if (Nu > NMAX) Nu = NMAX;
    int Ni = in_sizes[13]; if (Ni > NMAX) Ni = NMAX;
    float* out = (float*)d_out;

    zero_kernel<<<1, 128>>>();
    hidden_kernel<<<dim3(256, 2), 256>>>(user_emb, item_emb, all_user_ids, all_item_ids,
                                         u_attn_W, u_attn_b, i_attn_W, i_attn_b, Ni, Nu);
    int total = B * 64;
    gather_q_kernel<<<(2 * total + 255) / 256, 256>>>(user_emb, item_emb, user_id, item_id,
                                                      all_user_ids, all_item_ids, B);
    int qblocks = (B + 127) / 128;
    flash_kernel<<<dim3(qblocks, NSPLIT, 2), 256>>>(B, Ni, Nu);
    epilogue_kernel<<<dim3(B / 16, 2), 256>>>(u_W1, u_W2, i_W1, i_W2, B);
    final_kernel<<<64, 256>>>(out, B);
}

// round 6
// speedup vs baseline: 2.8956x; 1.0506x over previous
#include <cuda_runtime.h>
#include <cuda_bf16.h>
#include <cstdint>

#define NMAX   100000
#define NPADH  (NMAX + 64)
#define NPADT  (NMAX + 128)
#define BMAX   2048
#define NSPLIT 9

// ---------------- scratch ----------------
__device__ __align__(16) unsigned char g_hidden8[2][NPADH * 64]; // fp8 hidden [key][dim]
__device__ __align__(16) unsigned char g_keysT8[2][64][NPADT];   // fp8 keys   [dim][key]
__device__ float g_S[2][64];
__device__ float g_q[2][BMAX * 64];
__device__ float g_num[2][NSPLIT][BMAX * 64];
__device__ float g_den[2][NSPLIT][BMAX];
__device__ float g_og[2][BMAX * 128];

// ---------------- helpers ----------------
__device__ __forceinline__ uint32_t smem_u32(const void* p) {
    return (uint32_t)__cvta_generic_to_shared(p);
}
__device__ __forceinline__ uint32_t pack_bf2(float lo, float hi) {
    __nv_bfloat162 h = __floats2bfloat162_rn(lo, hi);
    return *reinterpret_cast<uint32_t*>(&h);
}
// e4m3x2 pack: byte0 = lo, byte1 = hi
__device__ __forceinline__ uint16_t pk8(float hi, float lo) {
    uint16_t d;
    asm("cvt.rn.satfinite.e4m3x2.f32 %0, %1, %2;" : "=h"(d) : "f"(hi), "f"(lo));
    return d;
}
__device__ __forceinline__ uint32_t pk8x4(float a, float b, float c, float d) {
    return (uint32_t)pk8(b, a) | ((uint32_t)pk8(d, c) << 16);
}
__device__ __forceinline__ void mma16816(float c[4],
                                         uint32_t a0, uint32_t a1, uint32_t a2, uint32_t a3,
                                         uint32_t b0, uint32_t b1) {
    asm volatile(
        "mma.sync.aligned.m16n8k16.row.col.f32.bf16.bf16.f32 "
        "{%0,%1,%2,%3}, {%4,%5,%6,%7}, {%8,%9}, {%0,%1,%2,%3};"
        : "+f"(c[0]), "+f"(c[1]), "+f"(c[2]), "+f"(c[3])
        : "r"(a0), "r"(a1), "r"(a2), "r"(a3), "r"(b0), "r"(b1));
}
__device__ __forceinline__ void mma16832f8(float c[4],
                                           uint32_t a0, uint32_t a1, uint32_t a2, uint32_t a3,
                                           uint32_t b0, uint32_t b1) {
    asm volatile(
        "mma.sync.aligned.m16n8k32.row.col.f32.e4m3.e4m3.f32 "
        "{%0,%1,%2,%3}, {%4,%5,%6,%7}, {%8,%9}, {%0,%1,%2,%3};"
        : "+f"(c[0]), "+f"(c[1]), "+f"(c[2]), "+f"(c[3])
        : "r"(a0), "r"(a1), "r"(a2), "r"(a3), "r"(b0), "r"(b1));
}
__device__ __forceinline__ void ldsm_x4(uint32_t& d0, uint32_t& d1, uint32_t& d2, uint32_t& d3,
                                        uint32_t a) {
    asm volatile("ldmatrix.sync.aligned.m8n8.x4.shared.b16 {%0,%1,%2,%3}, [%4];"
                 : "=r"(d0), "=r"(d1), "=r"(d2), "=r"(d3) : "r"(a));
}
__device__ __forceinline__ void cp16(uint32_t saddr, const void* g) {
    asm volatile("cp.async.cg.shared.global [%0], [%1], 16;" :: "r"(saddr), "l"(g));
}
#define CP_COMMIT() asm volatile("cp.async.commit_group;" ::: "memory")
#define CP_WAIT1()  asm volatile("cp.async.wait_group 1;" ::: "memory")

// key permutation: pi(8j+2t+e) = 32(j>>2) + 16((j>>1)&1) + 4t + 2(j&1) + e
__device__ __forceinline__ int pi_of(int n) {
    int j = n >> 3, t = (n >> 1) & 3, e = n & 1;
    return ((j >> 2) << 5) | (((j >> 1) & 1) << 4) | (t << 2) | ((j & 1) << 1) | e;
}

// ---------------- kernel 1 ----------------
__global__ void zero_kernel() {
    int t = threadIdx.x;
    if (t < 128) ((float*)g_S)[t] = 0.f;
}

// ---------------- kernel 2: hidden (mma.sync bf16) -> fp8 hidden + fp8 keysT + S ----------
__global__ void __launch_bounds__(256) hidden_kernel(
    const float* __restrict__ user_emb, const float* __restrict__ item_emb,
    const int* __restrict__ all_user_ids, const int* __restrict__ all_item_ids,
    const float* __restrict__ uW, const float* __restrict__ ub,
    const float* __restrict__ iW, const float* __restrict__ ib,
    int Ni, int Nu)
{
    int l = blockIdx.y;
    const float* emb = (l == 0) ? item_emb : user_emb;
    const int*   ids = (l == 0) ? all_item_ids : all_user_ids;
    const float* W   = (l == 0) ? uW : iW;
    const float* bb  = (l == 0) ? ub : ib;
    int Nk = (l == 0) ? Ni : Nu;

    __shared__ __nv_bfloat16 sW[64 * 72];
    __shared__ __nv_bfloat16 sK[128 * 72];
    __shared__ float sSum[8][64];
    __shared__ float sB[64];

    int tid = threadIdx.x, lane = tid & 31, warp = tid >> 5;
    for (int e = tid; e < 64 * 64; e += 256) {
        int o = e >> 6, d = e & 63;
        sW[o * 72 + d] = __float2bfloat16(W[e]);
    }
    if (tid < 64) sB[tid] = bb[tid];

    int c4 = lane & 15, r0 = lane >> 4;
    float4 csum = make_float4(0.f, 0.f, 0.f, 0.f);

    int ntiles = (Nk + 127) >> 7;
    for (int t = blockIdx.x; t < ntiles; t += gridDim.x) {
        int base = t << 7;
        __syncthreads();
        #pragma unroll
        for (int k = 0; k < 8; k++) {
            int rl = warp * 16 + r0 + 2 * k;
            int j = base + rl;
            float4 v = make_float4(0.f, 0.f, 0.f, 0.f);
            if (j < Nk) v = *(const float4*)&emb[(size_t)ids[j] * 64 + c4 * 4];
            csum.x += v.x; csum.y += v.y; csum.z += v.z; csum.w += v.w;
            uint2 u; u.x = pack_bf2(v.x, v.y); u.y = pack_bf2(v.z, v.w);
            *(uint2*)&sK[rl * 72 + c4 * 4] = u;
        }
        __syncthreads();
        { // transposed fp8 keys write: g_keysT8[dim][key]
            int d = tid & 63, rseg = tid >> 6;
            #pragma unroll
            for (int s = 0; s < 4; s++) {
                uint16_t h[4];
                #pragma unroll
                for (int q = 0; q < 4; q++) {
                    float f0 = __bfloat162float(sK[(rseg * 32 + s * 8 + 2 * q)     * 72 + d]);
                    float f1 = __bfloat162float(sK[(rseg * 32 + s * 8 + 2 * q + 1) * 72 + d]);
                    h[q] = pk8(f1, f0);
                }
                uint2 o; o.x = (uint32_t)h[0] | ((uint32_t)h[1] << 16);
                o.y = (uint32_t)h[2] | ((uint32_t)h[3] << 16);
                *(uint2*)&g_keysT8[l][d][base + rseg * 32 + s * 8] = o;
            }
        }
        uint32_t afr[4][4];
        #pragma unroll
        for (int kk = 0; kk < 4; kk++) {
            uint32_t a = smem_u32(&sK[(warp * 16 + (lane & 15)) * 72 + kk * 16 + (lane >> 4) * 8]);
            ldsm_x4(afr[kk][0], afr[kk][1], afr[kk][2], afr[kk][3], a);
        }
        int gid = lane >> 2, tig = lane & 3;
        int row0 = base + warp * 16 + gid, row1 = row0 + 8;
        #pragma unroll
        for (int j = 0; j < 8; j++) {
            float acc[4] = {0.f, 0.f, 0.f, 0.f};
            uint32_t b0, b1, b2, b3, b4, b5, b6, b7;
            uint32_t a = smem_u32(&sW[(8 * j + (lane & 7)) * 72 + (lane >> 3) * 8]);
            ldsm_x4(b0, b1, b2, b3, a);
            ldsm_x4(b4, b5, b6, b7, a + 32 * 2);
            mma16816(acc, afr[0][0], afr[0][1], afr[0][2], afr[0][3], b0, b1);
            mma16816(acc, afr[1][0], afr[1][1], afr[1][2], afr[1][3], b2, b3);
            mma16816(acc, afr[2][0], afr[2][1], afr[2][2], afr[2][3], b4, b5);
            mma16816(acc, afr[3][0], afr[3][1], afr[3][2], afr[3][3], b6, b7);
            int c = 8 * j + 2 * tig;
            float bz0 = sB[c], bz1 = sB[c + 1];
            if (row0 < Nk)
                *(uint16_t*)&g_hidden8[l][(size_t)row0 * 64 + c] =
                    pk8(fmaxf(acc[1] + bz1, 0.f), fmaxf(acc[0] + bz0, 0.f));
            if (row1 < Nk)
                *(uint16_t*)&g_hidden8[l][(size_t)row1 * 64 + c] =
                    pk8(fmaxf(acc[3] + bz1, 0.f), fmaxf(acc[2] + bz0, 0.f));
        }
    }
    csum.x += __shfl_xor_sync(0xffffffffu, csum.x, 16);
    csum.y += __shfl_xor_sync(0xffffffffu, csum.y, 16);
    csum.z += __shfl_xor_sync(0xffffffffu, csum.z, 16);
    csum.w += __shfl_xor_sync(0xffffffffu, csum.w, 16);
    if (lane < 16) *(float4*)&sSum[warp][c4 * 4] = csum;
    __syncthreads();
    if (tid < 64) {
        float s = 0.f;
        #pragma unroll
        for (int w = 0; w < 8; w++) s += sSum[w][tid];
        atomicAdd(&g_S[l][tid], s);
    }
}

// ---------------- kernel 3: gather queries ----------------
__global__ void gather_q_kernel(
    const float* __restrict__ user_emb, const float* __restrict__ item_emb,
    const int* __restrict__ user_id, const int* __restrict__ item_id,
    const int* __restrict__ all_user_ids, const int* __restrict__ all_item_ids, int B)
{
    int idx = blockIdx.x * blockDim.x + threadIdx.x;
    int total = B * 64;
    if (idx < 2 * total) {
        int l = idx / total;
        int e = idx - l * total;
        int b = e >> 6, d = e & 63;
        float v;
        if (l == 0) v = user_emb[(size_t)all_user_ids[user_id[b]] * 64 + d];
        else        v = item_emb[(size_t)all_item_ids[item_id[b]] * 64 + d];
        g_q[l][e] = v;
    }
}

// ---------------- kernel 4: flash attention (fp8 mma.sync) ----------------
#define LDT 80   // byte stride of fp8 tile rows: conflict-free ldsm

// H tile: smem row r <- global key kv + pi(r)
__device__ __forceinline__ void load_h(uint32_t sb, const unsigned char* g, int kv, int tid) {
    int row = tid >> 2, ch = tid & 3;
    cp16(sb + row * LDT + ch * 16, g + (size_t)(kv + pi_of(row)) * 64 + ch * 16);
}
// V tile: rows = dim, cols = 64 keys (unpermuted); kv is 64-aligned -> 16B-aligned src
__device__ __forceinline__ void load_v(uint32_t sb, const unsigned char* g, int kv, int tid) {
    int row = tid >> 2, ch = tid & 3;
    cp16(sb + row * LDT + ch * 16, g + (size_t)row * NPADT + kv + ch * 16);
}

__global__ void __launch_bounds__(256, 2) flash_kernel(int B, int Ni, int Nu) {
    int l  = blockIdx.z;
    int Nk = (l == 0) ? Ni : Nu;
    int qb = blockIdx.x, split = blockIdx.y;

    const unsigned char* __restrict__ Hs = g_hidden8[l];
    const unsigned char* __restrict__ Vs = &g_keysT8[l][0][0];

    __shared__ __align__(16) unsigned char sH[2][64 * LDT];
    __shared__ __align__(16) unsigned char sV[2][64 * LDT];

    int tid = threadIdx.x, lane = tid & 31, warp = tid >> 5;
    int gid = lane >> 2, tig = lane & 3;
    int lm_r = lane & 7, lm_m = lane >> 3;
    int moff = warp * 16;

    // ---- preload Q as fp8 A-fragments ----
    int qrow0 = qb * 128 + moff + gid, qrow1 = qrow0 + 8;
    uint32_t qa[2][4];
    #pragma unroll
    for (int c = 0; c < 2; c++) {
        #pragma unroll
        for (int h = 0; h < 2; h++) {
            float4 v0 = make_float4(0.f, 0.f, 0.f, 0.f), v1 = v0;
            int f4 = 8 * c + 4 * h + tig;
            if (qrow0 < B) v0 = *(const float4*)&g_q[l][(size_t)qrow0 * 64 + f4 * 4];
            if (qrow1 < B) v1 = *(const float4*)&g_q[l][(size_t)qrow1 * 64 + f4 * 4];
            qa[c][0 + 2 * h] = pk8x4(v0.x, v0.y, v0.z, v0.w);
            qa[c][1 + 2 * h] = pk8x4(v1.x, v1.y, v1.z, v1.w);
        }
    }

    // split bounds: chunk rounded to 64-key tiles so kv0 is 64-aligned (cp.async alignment)
    int ntiles_all = (Nk + 63) >> 6;
    int tiles_per  = (ntiles_all + NSPLIT - 1) / NSPLIT;
    int chunk = tiles_per << 6;
    int kv0   = split * chunk;
    int kvend = min(kv0 + chunk, Nk);
    int ntile = (kvend > kv0) ? ((kvend - kv0 + 63) >> 6) : 0;

    float o_acc[8][4];
    #pragma unroll
    for (int j = 0; j < 8; j++)
        #pragma unroll
        for (int q = 0; q < 4; q++) o_acc[j][q] = 0.f;
    float den0 = 0.f, den1 = 0.f;

    if (ntile > 0) {
        load_h(smem_u32(sH[0]), Hs, kv0, tid);
        load_v(smem_u32(sV[0]), Vs, kv0, tid);
        CP_COMMIT();
        if (ntile > 1) {
            load_h(smem_u32(sH[1]), Hs, kv0 + 64, tid);
            load_v(smem_u32(sV[1]), Vs, kv0 + 64, tid);
        }
        CP_COMMIT();
    }

    for (int t = 0; t < ntile; t++) {
        int stage = t & 1;
        int kv = kv0 + t * 64;
        CP_WAIT1();
        __syncthreads();

        uint32_t hb = smem_u32(sH[stage]);
        uint32_t vb = smem_u32(sV[stage]);

        // ---- S = Q @ H^T (pi-permuted keys); exp+mask; pack P fp8 ----
        uint16_t tlo[8], thi[8];
        #pragma unroll
        for (int j = 0; j < 8; j++) {
            uint32_t b0, b1, b2, b3;
            ldsm_x4(b0, b1, b2, b3, hb + (8 * j + lm_r) * LDT + lm_m * 16);
            float s[4] = {0.f, 0.f, 0.f, 0.f};
            mma16832f8(s, qa[0][0], qa[0][1], qa[0][2], qa[0][3], b0, b1);
            mma16832f8(s, qa[1][0], qa[1][1], qa[1][2], qa[1][3], b2, b3);
            int kap = ((j >> 2) << 5) + (((j >> 1) & 1) << 4) + (tig << 2) + ((j & 1) << 1);
            int key0 = kv + kap;
            float e0 = (key0     < kvend) ? __expf(s[0]) : 0.f;
            float e1 = (key0 + 1 < kvend) ? __expf(s[1]) : 0.f;
            float e2 = (key0     < kvend) ? __expf(s[2]) : 0.f;
            float e3 = (key0 + 1 < kvend) ? __expf(s[3]) : 0.f;
            den0 += e0 + e1;
            den1 += e2 + e3;
            tlo[j] = pk8(e1, e0);
            thi[j] = pk8(e3, e2);
        }
        uint32_t pa0[4], pa1[4];
        pa0[0] = (uint32_t)tlo[0] | ((uint32_t)tlo[1] << 16);
        pa0[1] = (uint32_t)thi[0] | ((uint32_t)thi[1] << 16);
        pa0[2] = (uint32_t)tlo[2] | ((uint32_t)tlo[3] << 16);
        pa0[3] = (uint32_t)thi[2] | ((uint32_t)thi[3] << 16);
        pa1[0] = (uint32_t)tlo[4] | ((uint32_t)tlo[5] << 16);
        pa1[1] = (uint32_t)thi[4] | ((uint32_t)thi[5] << 16);
        pa1[2] = (uint32_t)tlo[6] | ((uint32_t)tlo[7] << 16);
        pa1[3] = (uint32_t)thi[6] | ((uint32_t)thi[7] << 16);

        // ---- O += P @ V ----
        #pragma unroll
        for (int j = 0; j < 8; j++) {
            uint32_t v0, v1, v2, v3;
            ldsm_x4(v0, v1, v2, v3, vb + (8 * j + lm_r) * LDT + lm_m * 16);
            mma16832f8(o_acc[j], pa0[0], pa0[1], pa0[2], pa0[3], v0, v1);
            mma16832f8(o_acc[j], pa1[0], pa1[1], pa1[2], pa1[3], v2, v3);
        }

        __syncthreads();
        if (t + 2 < ntile) {
            load_h(smem_u32(sH[stage]), Hs, kv + 128, tid);
            load_v(smem_u32(sV[stage]), Vs, kv + 128, tid);
        }
        CP_COMMIT();
    }

    den0 += __shfl_xor_sync(0xffffffffu, den0, 1);
    den0 += __shfl_xor_sync(0xffffffffu, den0, 2);
    den1 += __shfl_xor_sync(0xffffffffu, den1, 1);
    den1 += __shfl_xor_sync(0xffffffffu, den1, 2);

    int r0 = qb * 128 + moff + gid;
    if (tig == 0) {
        if (r0 < B)     g_den[l][split][r0]     = den0;
        if (r0 + 8 < B) g_den[l][split][r0 + 8] = den1;
    }
    #pragma unroll
    for (int j = 0; j < 8; j++) {
        int c = 8 * j + 2 * tig;
        if (r0 < B) {
            g_num[l][split][r0 * 64 + c]     = o_acc[j][0];
            g_num[l][split][r0 * 64 + c + 1] = o_acc[j][1];
        }
        if (r0 + 8 < B) {
            g_num[l][split][(r0 + 8) * 64 + c]     = o_acc[j][2];
            g_num[l][split][(r0 + 8) * 64 + c + 1] = o_acc[j][3];
        }
    }
}

// ---------------- kernel 5: combine + epilogue ----------------
__global__ void __launch_bounds__(256) epilogue_kernel(
    const float* __restrict__ uW1, const float* __restrict__ uW2,
    const float* __restrict__ iW1, const float* __restrict__ iW2, int B)
{
    int l = blockIdx.y;
    const float* W1 = (l == 0) ? uW1 : iW1;
    const float* W2 = (l == 0) ? uW2 : iW2;

    __shared__ float sW1[64 * 68];
    __shared__ float sW2[64 * 68];
    __shared__ float sS[64];
    __shared__ float st1[16 * 64];
    __shared__ float st2[16 * 64];
    __shared__ float sden[16];

    int tid = threadIdx.x;
    for (int e = tid; e < 64 * 64; e += 256) {
        int o = e >> 6, d = e & 63;
        sW1[o * 68 + d] = W1[e];
        sW2[o * 68 + d] = W2[e];
    }
    if (tid < 64) sS[tid] = g_S[l][tid];

    int r0 = blockIdx.x * 16;
    if (tid < 16) {
        float dsum = 0.f;
        #pragma unroll
        for (int s = 0; s < NSPLIT; s++) dsum += g_den[l][s][r0 + tid];
        sden[tid] = dsum;
    }
    __syncthreads();

    for (int e = tid; e < 16 * 64; e += 256) {
        int rl = e >> 6, d = e & 63;
        int r = r0 + rl;
        float nsum = 0.f;
        #pragma unroll
        for (int s = 0; s < NSPLIT; s++) nsum += g_num[l][s][r * 64 + d];
        float q  = g_q[l][r * 64 + d];
        float q2 = q + nsum / sden[rl];
        st1[e] = q2 + sS[d];
        st2[e] = q2 * sS[d];
        g_og[l][r * 128 + d] = q;
    }
    __syncthreads();

    int o = tid & 63, rl0 = tid >> 6;
    for (int rl = rl0; rl < 16; rl += 4) {
        float acc = 0.f;
        const float4* t1 = (const float4*)&st1[rl * 64];
        const float4* t2 = (const float4*)&st2[rl * 64];
        const float4* w1 = (const float4*)&sW1[o * 68];
        const float4* w2 = (const float4*)&sW2[o * 68];
        #pragma unroll
        for (int d4 = 0; d4 < 16; d4++) {
            float4 a = t1[d4], b = w1[d4], c = t2[d4], e4 = w2[d4];
            acc += a.x*b.x + a.y*b.y + a.z*b.z + a.w*b.w
                 + c.x*e4.x + c.y*e4.y + c.z*e4.z + c.w*e4.w;
        }
        float out = (acc > 0.f) ? acc : 0.01f * acc;
        g_og[l][(r0 + rl) * 128 + 64 + o] = out;
    }
}

// ---------------- kernel 6: final 128x128 GEMM ----------------
__global__ void __launch_bounds__(256) final_kernel(float* __restrict__ out, int B) {
    int bi = blockIdx.x & 7, bj = blockIdx.x >> 3;
    __shared__ float sU[64 * 16];
    __shared__ float sI[64 * 16];
    int tid = threadIdx.x;
    int ty = tid >> 4, tx = tid & 15;
    float acc = 0.f;
    for (int k0 = 0; k0 < B; k0 += 64) {
        __syncthreads();
        for (int e = tid; e < 64 * 16; e += 256) {
            int kk = e >> 4, c = e & 15;
            sU[e] = g_og[0][(k0 + kk) * 128 + bi * 16 + c];
            sI[e] = g_og[1][(k0 + kk) * 128 + bj * 16 + c];
        }
        __syncthreads();
        #pragma unroll
        for (int kk = 0; kk < 64; kk++)
            acc += sU[kk * 16 + ty] * sI[kk * 16 + tx];
    }
    out[(bi * 16 + ty) * 128 + bj * 16 + tx] = acc;
}

// ---------------- launch ----------------
extern "C" void kernel_launch(void* const* d_in, const int* in_sizes, int n_in,
                              void* d_out, int out_size) {
    const float* user_emb  = (const float*)d_in[0];
    const float* item_emb  = (const float*)d_in[1];
    const float* u_attn_W  = (const float*)d_in[2];
    const float* u_attn_b  = (const float*)d_in[3];
    const float* u_W1      = (const float*)d_in[4];
    const float* u_W2      = (const float*)d_in[5];
    const float* i_attn_W  = (const float*)d_in[6];
    const float* i_attn_b  = (const float*)d_in[7];
    const float* i_W1      = (const float*)d_in[8];
    const float* i_W2      = (const float*)d_in[9];
    const int*   user_id   = (const int*)d_in[10];
    const int*   item_id   = (const int*)d_in[11];
    const int*   all_user_ids = (const int*)d_in[12];
    const int*   all_item_ids = (const int*)d_in[13];

    int B  = in_sizes[10]; if (B > BMAX) B = BMAX;
    int Nu = in_sizes[12]; if (Nu > NMAX) Nu = NMAX;
    int Ni = in_sizes[13]; if (Ni > NMAX) Ni = NMAX;
    float* out = (float*)d_out;

    zero_kernel<<<1, 128>>>();
    hidden_kernel<<<dim3(148, 2), 256>>>(user_emb, item_emb, all_user_ids, all_item_ids,
                                         u_attn_W, u_attn_b, i_attn_W, i_attn_b, Ni, Nu);
    int total = B * 64;
    gather_q_kernel<<<(2 * total + 255) / 256, 256>>>(user_emb, item_emb, user_id, item_id,
                                                      all_user_ids, all_item_ids, B);
    int qblocks = (B + 127) / 128;
    flash_kernel<<<dim3(qblocks, NSPLIT, 2), 256>>>(B, Ni, Nu);
    epilogue_kernel<<<dim3(B / 16, 2), 256>>>(u_W1, u_W2, i_W1, i_W2, B);
    final_kernel<<<64, 256>>>(out, B);
}

// round 8
// speedup vs baseline: 3.8040x; 1.3137x over previous
#include <cuda_runtime.h>
#include <cuda_bf16.h>
#include <cuda_fp16.h>
#include <cstdint>

#define NMAX   100000
#define NPADH  (NMAX + 128)
#define NPADT  (NMAX + 256)
#define BMAX   2048
#define NSPLIT 9
#define LDH 72
#define LDV 72

// ---------------- scratch (zero-initialized device globals; padding never written) -------
__device__ __align__(16) __nv_bfloat16 g_hidden_bf[2][NPADH * 64]; // [key][dim] bf16
__device__ __align__(16) __half        g_keysT[2][64][NPADT];      // [dim][key] f16 (PV B-operand)
__device__ float g_S[2][64];
__device__ float g_q[2][BMAX * 64];
__device__ __align__(16) __nv_bfloat16 g_qbf[2][BMAX * 64];        // Q * log2(e), bf16
__device__ float g_num[2][NSPLIT][BMAX * 64];
__device__ float g_den[2][NSPLIT][BMAX];
__device__ float g_og[2][BMAX * 128];

// ---------------- helpers ----------------
__device__ __forceinline__ uint32_t smem_u32(const void* p) {
    return (uint32_t)__cvta_generic_to_shared(p);
}
__device__ __forceinline__ uint32_t pack_bf2(float lo, float hi) {
    __nv_bfloat162 h = __floats2bfloat162_rn(lo, hi);
    return *reinterpret_cast<uint32_t*>(&h);
}
__device__ __forceinline__ void mma16816(float c[4],
                                         uint32_t a0, uint32_t a1, uint32_t a2, uint32_t a3,
                                         uint32_t b0, uint32_t b1) {
    asm volatile(
        "mma.sync.aligned.m16n8k16.row.col.f32.bf16.bf16.f32 "
        "{%0,%1,%2,%3}, {%4,%5,%6,%7}, {%8,%9}, {%0,%1,%2,%3};"
        : "+f"(c[0]), "+f"(c[1]), "+f"(c[2]), "+f"(c[3])
        : "r"(a0), "r"(a1), "r"(a2), "r"(a3), "r"(b0), "r"(b1));
}
__device__ __forceinline__ void mma16816h(float c[4],
                                          uint32_t a0, uint32_t a1, uint32_t a2, uint32_t a3,
                                          uint32_t b0, uint32_t b1) {
    asm volatile(
        "mma.sync.aligned.m16n8k16.row.col.f32.f16.f16.f32 "
        "{%0,%1,%2,%3}, {%4,%5,%6,%7}, {%8,%9}, {%0,%1,%2,%3};"
        : "+f"(c[0]), "+f"(c[1]), "+f"(c[2]), "+f"(c[3])
        : "r"(a0), "r"(a1), "r"(a2), "r"(a3), "r"(b0), "r"(b1));
}
__device__ __forceinline__ void ldsm_x4(uint32_t& d0, uint32_t& d1, uint32_t& d2, uint32_t& d3,
                                        uint32_t a) {
    asm volatile("ldmatrix.sync.aligned.m8n8.x4.shared.b16 {%0,%1,%2,%3}, [%4];"
                 : "=r"(d0), "=r"(d1), "=r"(d2), "=r"(d3) : "r"(a));
}
__device__ __forceinline__ void cp16(uint32_t saddr, const void* g) {
    asm volatile("cp.async.cg.shared.global [%0], [%1], 16;" :: "r"(saddr), "l"(g));
}
#define CP_COMMIT() asm volatile("cp.async.commit_group;" ::: "memory")
#define CP_WAIT1()  asm volatile("cp.async.wait_group 1;" ::: "memory")

// f16x2 2^x on MUFU; input/output packed half2 as u32
__device__ __forceinline__ uint32_t ex2_h2(uint32_t x) {
    uint32_t r;
    asm("ex2.approx.f16x2 %0, %1;" : "=r"(r) : "r"(x));
    return r;
}
__device__ __forceinline__ uint32_t h2_from_f2(float lo, float hi) {
    __half2 h = __floats2half2_rn(lo, hi);
    return *reinterpret_cast<uint32_t*>(&h);
}
__device__ __forceinline__ uint32_t hadd2u(uint32_t a, uint32_t b) {
    __half2 r = __hadd2(*reinterpret_cast<__half2*>(&a), *reinterpret_cast<__half2*>(&b));
    return *reinterpret_cast<uint32_t*>(&r);
}
__device__ __forceinline__ float h2sum_f32(uint32_t a) {
    __half2 h = *reinterpret_cast<__half2*>(&a);
    return __low2float(h) + __high2float(h);
}

// ---------------- kernel 1 ----------------
__global__ void zero_kernel() {
    int t = threadIdx.x;
    if (t < 128) ((float*)g_S)[t] = 0.f;
}

// ---------------- kernel 2: hidden (mma.sync bf16) + keysT(f16) + S ----------------
__global__ void __launch_bounds__(256) hidden_kernel(
    const float* __restrict__ user_emb, const float* __restrict__ item_emb,
    const int* __restrict__ all_user_ids, const int* __restrict__ all_item_ids,
    const float* __restrict__ uW, const float* __restrict__ ub,
    const float* __restrict__ iW, const float* __restrict__ ib,
    int Ni, int Nu)
{
    int l = blockIdx.y;
    const float* emb = (l == 0) ? item_emb : user_emb;
    const int*   ids = (l == 0) ? all_item_ids : all_user_ids;
    const float* W   = (l == 0) ? uW : iW;
    const float* bb  = (l == 0) ? ub : ib;
    int Nk = (l == 0) ? Ni : Nu;

    __shared__ __nv_bfloat16 sW[64 * 72];
    __shared__ __nv_bfloat16 sK[128 * 72];
    __shared__ float sSum[8][64];
    __shared__ float sB[64];

    int tid = threadIdx.x, lane = tid & 31, warp = tid >> 5;
    for (int e = tid; e < 64 * 64; e += 256) {
        int o = e >> 6, d = e & 63;
        sW[o * 72 + d] = __float2bfloat16(W[e]);
    }
    if (tid < 64) sB[tid] = bb[tid];

    int c4 = lane & 15, r0 = lane >> 4;
    float4 csum = make_float4(0.f, 0.f, 0.f, 0.f);

    int ntiles = (Nk + 127) >> 7;
    for (int t = blockIdx.x; t < ntiles; t += gridDim.x) {
        int base = t << 7;
        __syncthreads();
        #pragma unroll
        for (int k = 0; k < 8; k++) {
            int rl = warp * 16 + r0 + 2 * k;
            int j = base + rl;
            float4 v = make_float4(0.f, 0.f, 0.f, 0.f);
            if (j < Nk) v = *(const float4*)&emb[(size_t)ids[j] * 64 + c4 * 4];
            csum.x += v.x; csum.y += v.y; csum.z += v.z; csum.w += v.w;
            uint2 u; u.x = pack_bf2(v.x, v.y); u.y = pack_bf2(v.z, v.w);
            *(uint2*)&sK[rl * 72 + c4 * 4] = u;
        }
        __syncthreads();
        { // transposed keys write as f16: g_keysT[dim][key]
            int d = tid & 63, rseg = tid >> 6;
            #pragma unroll
            for (int s = 0; s < 4; s++) {
                union { uint4 u; __half h[8]; } pk;
                #pragma unroll
                for (int q = 0; q < 8; q++)
                    pk.h[q] = __float2half(__bfloat162float(sK[(rseg * 32 + s * 8 + q) * 72 + d]));
                *(uint4*)&g_keysT[l][d][base + rseg * 32 + s * 8] = pk.u;
            }
        }
        uint32_t afr[4][4];
        #pragma unroll
        for (int kk = 0; kk < 4; kk++) {
            uint32_t a = smem_u32(&sK[(warp * 16 + (lane & 15)) * 72 + kk * 16 + (lane >> 4) * 8]);
            ldsm_x4(afr[kk][0], afr[kk][1], afr[kk][2], afr[kk][3], a);
        }
        int gid = lane >> 2, tig = lane & 3;
        int row0 = base + warp * 16 + gid, row1 = row0 + 8;
        #pragma unroll
        for (int j = 0; j < 8; j++) {
            float acc[4] = {0.f, 0.f, 0.f, 0.f};
            uint32_t b0, b1, b2, b3, b4, b5, b6, b7;
            uint32_t a = smem_u32(&sW[(8 * j + (lane & 7)) * 72 + (lane >> 3) * 8]);
            ldsm_x4(b0, b1, b2, b3, a);
            ldsm_x4(b4, b5, b6, b7, a + 32 * 2);
            mma16816(acc, afr[0][0], afr[0][1], afr[0][2], afr[0][3], b0, b1);
            mma16816(acc, afr[1][0], afr[1][1], afr[1][2], afr[1][3], b2, b3);
            mma16816(acc, afr[2][0], afr[2][1], afr[2][2], afr[2][3], b4, b5);
            mma16816(acc, afr[3][0], afr[3][1], afr[3][2], afr[3][3], b6, b7);
            int c = 8 * j + 2 * tig;
            float bz0 = sB[c], bz1 = sB[c + 1];
            if (row0 < Nk)
                *(uint32_t*)&g_hidden_bf[l][(size_t)row0 * 64 + c] =
                    pack_bf2(fmaxf(acc[0] + bz0, 0.f), fmaxf(acc[1] + bz1, 0.f));
            if (row1 < Nk)
                *(uint32_t*)&g_hidden_bf[l][(size_t)row1 * 64 + c] =
                    pack_bf2(fmaxf(acc[2] + bz0, 0.f), fmaxf(acc[3] + bz1, 0.f));
        }
    }
    csum.x += __shfl_xor_sync(0xffffffffu, csum.x, 16);
    csum.y += __shfl_xor_sync(0xffffffffu, csum.y, 16);
    csum.z += __shfl_xor_sync(0xffffffffu, csum.z, 16);
    csum.w += __shfl_xor_sync(0xffffffffu, csum.w, 16);
    if (lane < 16) *(float4*)&sSum[warp][c4 * 4] = csum;
    __syncthreads();
    if (tid < 64) {
        float s = 0.f;
        #pragma unroll
        for (int w = 0; w < 8; w++) s += sSum[w][tid];
        atomicAdd(&g_S[l][tid], s);
    }
}

// ---------------- kernel 3: gather queries (bf16 copy scaled by log2e) ----------------
__global__ void gather_q_kernel(
    const float* __restrict__ user_emb, const float* __restrict__ item_emb,
    const int* __restrict__ user_id, const int* __restrict__ item_id,
    const int* __restrict__ all_user_ids, const int* __restrict__ all_item_ids, int B)
{
    int idx = blockIdx.x * blockDim.x + threadIdx.x;
    int total = B * 64;
    if (idx < 2 * total) {
        int l = idx / total;
        int e = idx - l * total;
        int b = e >> 6, d = e & 63;
        float v;
        if (l == 0) v = user_emb[(size_t)all_user_ids[user_id[b]] * 64 + d];
        else        v = item_emb[(size_t)all_item_ids[item_id[b]] * 64 + d];
        g_q[l][e]   = v;
        g_qbf[l][e] = __float2bfloat16(v * 1.4426950408889634f);  // log2(e)
    }
}

// ---------------- kernel 4: flash attention (bf16 QK, f16 PV, ex2 softmax) --------------
__device__ __forceinline__ void load_tiles(const __nv_bfloat16* __restrict__ Hs,
                                           const __half* __restrict__ Vs,
                                           __nv_bfloat16* sH, __half* sV,
                                           int kv, int tid)
{
    // H: 64 keys x 64 dims; V(=keysT): 64 dims x 64 keys. 512 chunks each, 256 threads.
    #pragma unroll
    for (int i = 0; i < 2; i++) {
        int c = tid + i * 256;
        int row = c >> 3, ch = c & 7;
        cp16(smem_u32(&sH[row * LDH + ch * 8]), Hs + (size_t)(kv + row) * 64 + ch * 8);
        cp16(smem_u32(&sV[row * LDV + ch * 8]), Vs + (size_t)row * NPADT + kv + ch * 8);
    }
}

__global__ void __launch_bounds__(256, 2) flash_kernel(int B, int Ni, int Nu) {
    int l  = blockIdx.z;
    int Nk = (l == 0) ? Ni : Nu;
    int qb = blockIdx.x, split = blockIdx.y;

    const __nv_bfloat16* __restrict__ Hs = g_hidden_bf[l];
    const __half* __restrict__ Vs = &g_keysT[l][0][0];
    const __nv_bfloat16* __restrict__ Qs = g_qbf[l];

    __shared__ __nv_bfloat16 sH[2][64 * LDH];
    __shared__ __half sV[2][64 * LDV];

    int tid = threadIdx.x, lane = tid & 31, warp = tid >> 5;
    int gid = lane >> 2, tig = lane & 3;
    int lm_r = lane & 7, lm_m = lane >> 3;
    int moff = warp * 16;

    // ---- preload Q fragments (bf16, log2e-scaled) ----
    int qrow0 = qb * 128 + moff + gid, qrow1 = qrow0 + 8;
    uint32_t qa[4][4];
    #pragma unroll
    for (int kk = 0; kk < 4; kk++) {
        int kc = kk * 16 + 2 * tig;
        qa[kk][0] = (qrow0 < B) ? *(const uint32_t*)&Qs[(size_t)qrow0 * 64 + kc] : 0u;
        qa[kk][1] = (qrow1 < B) ? *(const uint32_t*)&Qs[(size_t)qrow1 * 64 + kc] : 0u;
        qa[kk][2] = (qrow0 < B) ? *(const uint32_t*)&Qs[(size_t)qrow0 * 64 + kc + 8] : 0u;
        qa[kk][3] = (qrow1 < B) ? *(const uint32_t*)&Qs[(size_t)qrow1 * 64 + kc + 8] : 0u;
    }

    // split bounds: 64-aligned chunks (cp.async alignment)
    int ntiles_all = (Nk + 63) >> 6;
    int tiles_per  = (ntiles_all + NSPLIT - 1) / NSPLIT;
    int chunk = tiles_per << 6;
    int kv0   = split * chunk;
    int kvend = min(kv0 + chunk, Nk);
    int ntile = (kvend > kv0) ? ((kvend - kv0 + 63) >> 6) : 0;

    float o_acc[8][4];
    #pragma unroll
    for (int j = 0; j < 8; j++)
        #pragma unroll
        for (int q = 0; q < 4; q++) o_acc[j][q] = 0.f;
    float den0 = 0.f, den1 = 0.f;

    if (ntile > 0) {
        load_tiles(Hs, Vs, sH[0], sV[0], kv0, tid);
        CP_COMMIT();
        if (ntile > 1) load_tiles(Hs, Vs, sH[1], sV[1], kv0 + 64, tid);
        CP_COMMIT();
    }

    for (int t = 0; t < ntile; t++) {
        int stage = t & 1;
        CP_WAIT1();
        __syncthreads();

        const __nv_bfloat16* tH = sH[stage];
        const __half* tV = sV[stage];

        // ---- S = (Q*log2e) @ H^T  (no masking: padding rows are exact zeros) ----
        float s[8][4];
        #pragma unroll
        for (int j = 0; j < 8; j++) {
            uint32_t hb0, hb1, hb2, hb3, hb4, hb5, hb6, hb7;
            uint32_t a0 = smem_u32(&tH[(8 * j + lm_r) * LDH + lm_m * 8]);
            ldsm_x4(hb0, hb1, hb2, hb3, a0);
            ldsm_x4(hb4, hb5, hb6, hb7, a0 + 32 * 2);
            #pragma unroll
            for (int q = 0; q < 4; q++) s[j][q] = 0.f;
            mma16816(s[j], qa[0][0], qa[0][1], qa[0][2], qa[0][3], hb0, hb1);
            mma16816(s[j], qa[1][0], qa[1][1], qa[1][2], qa[1][3], hb2, hb3);
            mma16816(s[j], qa[2][0], qa[2][1], qa[2][2], qa[2][3], hb4, hb5);
            mma16816(s[j], qa[3][0], qa[3][1], qa[3][2], qa[3][3], hb6, hb7);
        }

        // ---- P = 2^S in f16x2 (directly the PV A-fragments) ----
        uint32_t plo[8], phi[8];
        #pragma unroll
        for (int j = 0; j < 8; j++) {
            plo[j] = ex2_h2(h2_from_f2(s[j][0], s[j][1]));
            phi[j] = ex2_h2(h2_from_f2(s[j][2], s[j][3]));
        }

        // ---- den: f16x2 tree then fp32 ----
        {
            uint32_t tl = hadd2u(hadd2u(hadd2u(plo[0], plo[1]), hadd2u(plo[2], plo[3])),
                                 hadd2u(hadd2u(plo[4], plo[5]), hadd2u(plo[6], plo[7])));
            uint32_t th = hadd2u(hadd2u(hadd2u(phi[0], phi[1]), hadd2u(phi[2], phi[3])),
                                 hadd2u(hadd2u(phi[4], phi[5]), hadd2u(phi[6], phi[7])));
            den0 += h2sum_f32(tl);
            den1 += h2sum_f32(th);
        }

        // ---- O += P @ V   (V = keysT tile, f16 B[dim][key], plain ldsm) ----
        #pragma unroll
        for (int j = 0; j < 8; j++) {
            uint32_t v0, v1, v2, v3, w0, w1, w2, w3;
            uint32_t a0 = smem_u32(&tV[(8 * j + lm_r) * LDV + lm_m * 8]);
            ldsm_x4(v0, v1, v2, v3, a0);
            ldsm_x4(w0, w1, w2, w3, a0 + 32 * 2);
            mma16816h(o_acc[j], plo[0], phi[0], plo[1], phi[1], v0, v1);
            mma16816h(o_acc[j], plo[2], phi[2], plo[3], phi[3], v2, v3);
            mma16816h(o_acc[j], plo[4], phi[4], plo[5], phi[5], w0, w1);
            mma16816h(o_acc[j], plo[6], phi[6], plo[7], phi[7], w2, w3);
        }

        __syncthreads();
        if (t + 2 < ntile) load_tiles(Hs, Vs, sH[stage], sV[stage], kv0 + (t + 2) * 64, tid);
        CP_COMMIT();
    }

    // reduce den across the 4 lanes sharing a row; subtract exact padding count
    den0 += __shfl_xor_sync(0xffffffffu, den0, 1);
    den0 += __shfl_xor_sync(0xffffffffu, den0, 2);
    den1 += __shfl_xor_sync(0xffffffffu, den1, 1);
    den1 += __shfl_xor_sync(0xffffffffu, den1, 2);
    float npad = (float)(ntile * 64 - (kvend - kv0));   // padded keys contribute exactly 1.0 each
    den0 -= npad;
    den1 -= npad;

    int r0 = qb * 128 + moff + gid;
    if (tig == 0) {
        if (r0 < B)     g_den[l][split][r0]     = den0;
        if (r0 + 8 < B) g_den[l][split][r0 + 8] = den1;
    }
    #pragma unroll
    for (int j = 0; j < 8; j++) {
        int c = 8 * j + 2 * tig;
        if (r0 < B) {
            g_num[l][split][r0 * 64 + c]     = o_acc[j][0];
            g_num[l][split][r0 * 64 + c + 1] = o_acc[j][1];
        }
        if (r0 + 8 < B) {
            g_num[l][split][(r0 + 8) * 64 + c]     = o_acc[j][2];
            g_num[l][split][(r0 + 8) * 64 + c + 1] = o_acc[j][3];
        }
    }
}

// ---------------- kernel 5: combine + epilogue ----------------
__global__ void __launch_bounds__(256) epilogue_kernel(
    const float* __restrict__ uW1, const float* __restrict__ uW2,
    const float* __restrict__ iW1, const float* __restrict__ iW2, int B)
{
    int l = blockIdx.y;
    const float* W1 = (l == 0) ? uW1 : iW1;
    const float* W2 = (l == 0) ? uW2 : iW2;

    __shared__ float sW1[64 * 68];
    __shared__ float sW2[64 * 68];
    __shared__ float sS[64];
    __shared__ float st1[16 * 64];
    __shared__ float st2[16 * 64];
    __shared__ float sden[16];

    int tid = threadIdx.x;
    for (int e = tid; e < 64 * 64; e += 256) {
        int o = e >> 6, d = e & 63;
        sW1[o * 68 + d] = W1[e];
        sW2[o * 68 + d] = W2[e];
    }
    if (tid < 64) sS[tid] = g_S[l][tid];

    int r0 = blockIdx.x * 16;
    if (tid < 16) {
        float dsum = 0.f;
        #pragma unroll
        for (int s = 0; s < NSPLIT; s++) dsum += g_den[l][s][r0 + tid];
        sden[tid] = dsum;
    }
    __syncthreads();

    for (int e = tid; e < 16 * 64; e += 256) {
        int rl = e >> 6, d = e & 63;
        int r = r0 + rl;
        float nsum = 0.f;
        #pragma unroll
        for (int s = 0; s < NSPLIT; s++) nsum += g_num[l][s][r * 64 + d];
        float q  = g_q[l][r * 64 + d];
        float q2 = q + nsum / sden[rl];
        st1[e] = q2 + sS[d];
        st2[e] = q2 * sS[d];
        g_og[l][r * 128 + d] = q;
    }
    __syncthreads();

    int o = tid & 63, rl0 = tid >> 6;
    for (int rl = rl0; rl < 16; rl += 4) {
        float acc = 0.f;
        const float4* t1 = (const float4*)&st1[rl * 64];
        const float4* t2 = (const float4*)&st2[rl * 64];
        const float4* w1 = (const float4*)&sW1[o * 68];
        const float4* w2 = (const float4*)&sW2[o * 68];
        #pragma unroll
        for (int d4 = 0; d4 < 16; d4++) {
            float4 a = t1[d4], b = w1[d4], c = t2[d4], e4 = w2[d4];
            acc += a.x*b.x + a.y*b.y + a.z*b.z + a.w*b.w
                 + c.x*e4.x + c.y*e4.y + c.z*e4.z + c.w*e4.w;
        }
        float out = (acc > 0.f) ? acc : 0.01f * acc;
        g_og[l][(r0 + rl) * 128 + 64 + o] = out;
    }
}

// ---------------- kernel 6: final 128x128 GEMM ----------------
__global__ void __launch_bounds__(256) final_kernel(float* __restrict__ out, int B) {
    int bi = blockIdx.x & 7, bj = blockIdx.x >> 3;
    __shared__ float sU[64 * 16];
    __shared__ float sI[64 * 16];
    int tid = threadIdx.x;
    int ty = tid >> 4, tx = tid & 15;
    float acc = 0.f;
    for (int k0 = 0; k0 < B; k0 += 64) {
        __syncthreads();
        for (int e = tid; e < 64 * 16; e += 256) {
            int kk = e >> 4, c = e & 15;
            sU[e] = g_og[0][(k0 + kk) * 128 + bi * 16 + c];
            sI[e] = g_og[1][(k0 + kk) * 128 + bj * 16 + c];
        }
        __syncthreads();
        #pragma unroll
        for (int kk = 0; kk < 64; kk++)
            acc += sU[kk * 16 + ty] * sI[kk * 16 + tx];
    }
    out[(bi * 16 + ty) * 128 + bj * 16 + tx] = acc;
}

// ---------------- launch ----------------
extern "C" void kernel_launch(void* const* d_in, const int* in_sizes, int n_in,
                              void* d_out, int out_size) {
    const float* user_emb  = (const float*)d_in[0];
    const float* item_emb  = (const float*)d_in[1];
    const float* u_attn_W  = (const float*)d_in[2];
    const float* u_attn_b  = (const float*)d_in[3];
    const float* u_W1      = (const float*)d_in[4];
    const float* u_W2      = (const float*)d_in[5];
    const float* i_attn_W  = (const float*)d_in[6];
    const float* i_attn_b  = (const float*)d_in[7];
    const float* i_W1      = (const float*)d_in[8];
    const float* i_W2      = (const float*)d_in[9];
    const int*   user_id   = (const int*)d_in[10];
    const int*   item_id   = (const int*)d_in[11];
    const int*   all_user_ids = (const int*)d_in[12];
    const int*   all_item_ids = (const int*)d_in[13];

    int B  = in_sizes[10]; if (B > BMAX) B = BMAX;
    int Nu = in_sizes[12]; if (Nu > NMAX) Nu = NMAX;
    int Ni = in_sizes[13]; if (Ni > NMAX) Ni = NMAX;
    float* out = (float*)d_out;

    zero_kernel<<<1, 128>>>();
    hidden_kernel<<<dim3(148, 2), 256>>>(user_emb, item_emb, all_user_ids, all_item_ids,
                                         u_attn_W, u_attn_b, i_attn_W, i_attn_b, Ni, Nu);
    int total = B * 64;
    gather_q_kernel<<<(2 * total + 255) / 256, 256>>>(user_emb, item_emb, user_id, item_id,
                                                      all_user_ids, all_item_ids, B);
    int qblocks = (B + 127) / 128;
    flash_kernel<<<dim3(qblocks, NSPLIT, 2), 256>>>(B, Ni, Nu);
    epilogue_kernel<<<dim3(B / 16, 2), 256>>>(u_W1, u_W2, i_W1, i_W2, B);
    final_kernel<<<64, 256>>>(out, B);
}

// round 10
// speedup vs baseline: 3.8187x; 1.0039x over previous
#include <cuda_runtime.h>
#include <cuda_bf16.h>
#include <cuda_fp16.h>
#include <cstdint>

#define NMAX   100000
#define NPADH  (NMAX + 128)
#define NPADT  (NMAX + 256)
#define BMAX   2048
#define NSPLIT 13
#define LDH 72
#define LDV 72

// ---------------- scratch (zero-initialized device globals; padding never written) -------
__device__ __align__(16) __nv_bfloat16 g_hidden_bf[2][NPADH * 64]; // [key][dim] bf16
__device__ __align__(16) __half        g_keysT[2][64][NPADT];      // [dim][key] f16
__device__ float g_S[2][64];
__device__ float g_q[2][BMAX * 64];
__device__ __align__(16) __nv_bfloat16 g_qbf[2][BMAX * 64];        // Q * log2(e), bf16
__device__ float g_num[2][NSPLIT][BMAX * 64];
__device__ float g_den[2][NSPLIT][BMAX];
__device__ float g_og[2][BMAX * 128];

// ---------------- helpers ----------------
__device__ __forceinline__ uint32_t smem_u32(const void* p) {
    return (uint32_t)__cvta_generic_to_shared(p);
}
__device__ __forceinline__ uint32_t pack_bf2(float lo, float hi) {
    __nv_bfloat162 h = __floats2bfloat162_rn(lo, hi);
    return *reinterpret_cast<uint32_t*>(&h);
}
__device__ __forceinline__ void mma16816(float c[4],
                                         uint32_t a0, uint32_t a1, uint32_t a2, uint32_t a3,
                                         uint32_t b0, uint32_t b1) {
    asm volatile(
        "mma.sync.aligned.m16n8k16.row.col.f32.bf16.bf16.f32 "
        "{%0,%1,%2,%3}, {%4,%5,%6,%7}, {%8,%9}, {%0,%1,%2,%3};"
        : "+f"(c[0]), "+f"(c[1]), "+f"(c[2]), "+f"(c[3])
        : "r"(a0), "r"(a1), "r"(a2), "r"(a3), "r"(b0), "r"(b1));
}
__device__ __forceinline__ void mma16816h(float c[4],
                                          uint32_t a0, uint32_t a1, uint32_t a2, uint32_t a3,
                                          uint32_t b0, uint32_t b1) {
    asm volatile(
        "mma.sync.aligned.m16n8k16.row.col.f32.f16.f16.f32 "
        "{%0,%1,%2,%3}, {%4,%5,%6,%7}, {%8,%9}, {%0,%1,%2,%3};"
        : "+f"(c[0]), "+f"(c[1]), "+f"(c[2]), "+f"(c[3])
        : "r"(a0), "r"(a1), "r"(a2), "r"(a3), "r"(b0), "r"(b1));
}
__device__ __forceinline__ void ldsm_x4(uint32_t& d0, uint32_t& d1, uint32_t& d2, uint32_t& d3,
                                        uint32_t a) {
    asm volatile("ldmatrix.sync.aligned.m8n8.x4.shared.b16 {%0,%1,%2,%3}, [%4];"
                 : "=r"(d0), "=r"(d1), "=r"(d2), "=r"(d3) : "r"(a));
}
__device__ __forceinline__ void cp16(uint32_t saddr, const void* g) {
    asm volatile("cp.async.cg.shared.global [%0], [%1], 16;" :: "r"(saddr), "l"(g));
}
#define CP_COMMIT() asm volatile("cp.async.commit_group;" ::: "memory")
#define CP_WAIT1()  asm volatile("cp.async.wait_group 1;" ::: "memory")

__device__ __forceinline__ uint32_t ex2_h2(uint32_t x) {
    uint32_t r;
    asm("ex2.approx.f16x2 %0, %1;" : "=r"(r) : "r"(x));
    return r;
}
__device__ __forceinline__ uint32_t h2_from_f2(float lo, float hi) {
    __half2 h = __floats2half2_rn(lo, hi);
    return *reinterpret_cast<uint32_t*>(&h);
}
__device__ __forceinline__ uint32_t hadd2u(uint32_t a, uint32_t b) {
    __half2 r = __hadd2(*reinterpret_cast<__half2*>(&a), *reinterpret_cast<__half2*>(&b));
    return *reinterpret_cast<uint32_t*>(&r);
}
__device__ __forceinline__ float h2sum_f32(uint32_t a) {
    __half2 h = *reinterpret_cast<__half2*>(&a);
    return __low2float(h) + __high2float(h);
}

// ---------------- kernel 1 ----------------
__global__ void zero_kernel() {
    int t = threadIdx.x;
    if (t < 128) ((float*)g_S)[t] = 0.f;
}

// ---------------- kernel 2: hidden (mma.sync bf16) + keysT(f16) + S ----------------
__global__ void __launch_bounds__(256) hidden_kernel(
    const float* __restrict__ user_emb, const float* __restrict__ item_emb,
    const int* __restrict__ all_user_ids, const int* __restrict__ all_item_ids,
    const float* __restrict__ uW, const float* __restrict__ ub,
    const float* __restrict__ iW, const float* __restrict__ ib,
    int Ni, int Nu)
{
    int l = blockIdx.y;
    const float* emb = (l == 0) ? item_emb : user_emb;
    const int*   ids = (l == 0) ? all_item_ids : all_user_ids;
    const float* W   = (l == 0) ? uW : iW;
    const float* bb  = (l == 0) ? ub : ib;
    int Nk = (l == 0) ? Ni : Nu;

    __shared__ __nv_bfloat16 sW[64 * 72];
    __shared__ __nv_bfloat16 sK[128 * 72];
    __shared__ float sSum[8][64];
    __shared__ float sB[64];

    int tid = threadIdx.x, lane = tid & 31, warp = tid >> 5;
    for (int e = tid; e < 64 * 64; e += 256) {
        int o = e >> 6, d = e & 63;
        sW[o * 72 + d] = __float2bfloat16(W[e]);
    }
    if (tid < 64) sB[tid] = bb[tid];

    int c4 = lane & 15, r0 = lane >> 4;
    float4 csum = make_float4(0.f, 0.f, 0.f, 0.f);

    int ntiles = (Nk + 127) >> 7;
    for (int t = blockIdx.x; t < ntiles; t += gridDim.x) {
        int base = t << 7;
        __syncthreads();
        #pragma unroll
        for (int k = 0; k < 8; k++) {
            int rl = warp * 16 + r0 + 2 * k;
            int j = base + rl;
            float4 v = make_float4(0.f, 0.f, 0.f, 0.f);
            if (j < Nk) v = *(const float4*)&emb[(size_t)ids[j] * 64 + c4 * 4];
            csum.x += v.x; csum.y += v.y; csum.z += v.z; csum.w += v.w;
            uint2 u; u.x = pack_bf2(v.x, v.y); u.y = pack_bf2(v.z, v.w);
            *(uint2*)&sK[rl * 72 + c4 * 4] = u;
        }
        __syncthreads();
        { // transposed keys write as f16: g_keysT[dim][key]
            int d = tid & 63, rseg = tid >> 6;
            #pragma unroll
            for (int s = 0; s < 4; s++) {
                union { uint4 u; __half h[8]; } pk;
                #pragma unroll
                for (int q = 0; q < 8; q++)
                    pk.h[q] = __float2half(__bfloat162float(sK[(rseg * 32 + s * 8 + q) * 72 + d]));
                *(uint4*)&g_keysT[l][d][base + rseg * 32 + s * 8] = pk.u;
            }
        }
        uint32_t afr[4][4];
        #pragma unroll
        for (int kk = 0; kk < 4; kk++) {
            uint32_t a = smem_u32(&sK[(warp * 16 + (lane & 15)) * 72 + kk * 16 + (lane >> 4) * 8]);
            ldsm_x4(afr[kk][0], afr[kk][1], afr[kk][2], afr[kk][3], a);
        }
        int gid = lane >> 2, tig = lane & 3;
        int row0 = base + warp * 16 + gid, row1 = row0 + 8;
        #pragma unroll
        for (int j = 0; j < 8; j++) {
            float acc[4] = {0.f, 0.f, 0.f, 0.f};
            uint32_t b0, b1, b2, b3, b4, b5, b6, b7;
            uint32_t a = smem_u32(&sW[(8 * j + (lane & 7)) * 72 + (lane >> 3) * 8]);
            ldsm_x4(b0, b1, b2, b3, a);
            ldsm_x4(b4, b5, b6, b7, a + 32 * 2);
            mma16816(acc, afr[0][0], afr[0][1], afr[0][2], afr[0][3], b0, b1);
            mma16816(acc, afr[1][0], afr[1][1], afr[1][2], afr[1][3], b2, b3);
            mma16816(acc, afr[2][0], afr[2][1], afr[2][2], afr[2][3], b4, b5);
            mma16816(acc, afr[3][0], afr[3][1], afr[3][2], afr[3][3], b6, b7);
            int c = 8 * j + 2 * tig;
            float bz0 = sB[c], bz1 = sB[c + 1];
            if (row0 < Nk)
                *(uint32_t*)&g_hidden_bf[l][(size_t)row0 * 64 + c] =
                    pack_bf2(fmaxf(acc[0] + bz0, 0.f), fmaxf(acc[1] + bz1, 0.f));
            if (row1 < Nk)
                *(uint32_t*)&g_hidden_bf[l][(size_t)row1 * 64 + c] =
                    pack_bf2(fmaxf(acc[2] + bz0, 0.f), fmaxf(acc[3] + bz1, 0.f));
        }
    }
    csum.x += __shfl_xor_sync(0xffffffffu, csum.x, 16);
    csum.y += __shfl_xor_sync(0xffffffffu, csum.y, 16);
    csum.z += __shfl_xor_sync(0xffffffffu, csum.z, 16);
    csum.w += __shfl_xor_sync(0xffffffffu, csum.w, 16);
    if (lane < 16) *(float4*)&sSum[warp][c4 * 4] = csum;
    __syncthreads();
    if (tid < 64) {
        float s = 0.f;
        #pragma unroll
        for (int w = 0; w < 8; w++) s += sSum[w][tid];
        atomicAdd(&g_S[l][tid], s);
    }
}

// ---------------- kernel 3: gather queries (bf16 copy scaled by log2e) ----------------
__global__ void gather_q_kernel(
    const float* __restrict__ user_emb, const float* __restrict__ item_emb,
    const int* __restrict__ user_id, const int* __restrict__ item_id,
    const int* __restrict__ all_user_ids, const int* __restrict__ all_item_ids, int B)
{
    int idx = blockIdx.x * blockDim.x + threadIdx.x;
    int total = B * 64;
    if (idx < 2 * total) {
        int l = idx / total;
        int e = idx - l * total;
        int b = e >> 6, d = e & 63;
        float v;
        if (l == 0) v = user_emb[(size_t)all_user_ids[user_id[b]] * 64 + d];
        else        v = item_emb[(size_t)all_item_ids[item_id[b]] * 64 + d];
        g_q[l][e]   = v;
        g_qbf[l][e] = __float2bfloat16(v * 1.4426950408889634f);  // log2(e)
    }
}

// ---------------- kernel 4: flash attention (M=32/warp, 128 rows/CTA) -------------------
__device__ __forceinline__ void load_tiles(const __nv_bfloat16* __restrict__ Hs,
                                           const __half* __restrict__ Vs,
                                           __nv_bfloat16* sH, __half* sV,
                                           int kv, int tid)
{
    #pragma unroll
    for (int i = 0; i < 4; i++) {
        int c = tid + i * 128;          // 512 chunks per tile
        int row = c >> 3, ch = c & 7;
        cp16(smem_u32(&sH[row * LDH + ch * 8]), Hs + (size_t)(kv + row) * 64 + ch * 8);
        cp16(smem_u32(&sV[row * LDV + ch * 8]), Vs + (size_t)row * NPADT + kv + ch * 8);
    }
}

__global__ void __launch_bounds__(128, 3) flash_kernel(int B, int Ni, int Nu) {
    int l  = blockIdx.z;
    int Nk = (l == 0) ? Ni : Nu;
    int qb = blockIdx.x, split = blockIdx.y;

    const __nv_bfloat16* __restrict__ Hs = g_hidden_bf[l];
    const __half* __restrict__ Vs = &g_keysT[l][0][0];
    const __nv_bfloat16* __restrict__ Qs = g_qbf[l];

    __shared__ __nv_bfloat16 sH[2][64 * LDH];
    __shared__ __half sV[2][64 * LDV];

    int tid = threadIdx.x, lane = tid & 31, warp = tid >> 5;   // 4 warps
    int gid = lane >> 2, tig = lane & 3;
    int lm_r = lane & 7, lm_m = lane >> 3;

    // CTA covers 128 query rows; each warp covers 32 (two m16 tiles A/B)
    int rowA0 = qb * 128 + warp * 32 + gid;
    int rowA1 = rowA0 + 8;
    int rowB0 = rowA0 + 16;
    int rowB1 = rowA0 + 24;

    uint32_t qaA[4][4], qaB[4][4];
    #pragma unroll
    for (int kk = 0; kk < 4; kk++) {
        int kc = kk * 16 + 2 * tig;
        qaA[kk][0] = (rowA0 < B) ? *(const uint32_t*)&Qs[(size_t)rowA0 * 64 + kc]     : 0u;
        qaA[kk][1] = (rowA1 < B) ? *(const uint32_t*)&Qs[(size_t)rowA1 * 64 + kc]     : 0u;
        qaA[kk][2] = (rowA0 < B) ? *(const uint32_t*)&Qs[(size_t)rowA0 * 64 + kc + 8] : 0u;
        qaA[kk][3] = (rowA1 < B) ? *(const uint32_t*)&Qs[(size_t)rowA1 * 64 + kc + 8] : 0u;
        qaB[kk][0] = (rowB0 < B) ? *(const uint32_t*)&Qs[(size_t)rowB0 * 64 + kc]     : 0u;
        qaB[kk][1] = (rowB1 < B) ? *(const uint32_t*)&Qs[(size_t)rowB1 * 64 + kc]     : 0u;
        qaB[kk][2] = (rowB0 < B) ? *(const uint32_t*)&Qs[(size_t)rowB0 * 64 + kc + 8] : 0u;
        qaB[kk][3] = (rowB1 < B) ? *(const uint32_t*)&Qs[(size_t)rowB1 * 64 + kc + 8] : 0u;
    }

    // split bounds: 64-aligned chunks
    int ntiles_all = (Nk + 63) >> 6;
    int tiles_per  = (ntiles_all + NSPLIT - 1) / NSPLIT;
    int chunk = tiles_per << 6;
    int kv0   = split * chunk;
    int kvend = min(kv0 + chunk, Nk);
    int ntile = (kvend > kv0) ? ((kvend - kv0 + 63) >> 6) : 0;

    float oA[8][4], oB[8][4];
    #pragma unroll
    for (int j = 0; j < 8; j++)
        #pragma unroll
        for (int q = 0; q < 4; q++) { oA[j][q] = 0.f; oB[j][q] = 0.f; }
    float dA0 = 0.f, dA1 = 0.f, dB0 = 0.f, dB1 = 0.f;

    if (ntile > 0) {
        load_tiles(Hs, Vs, sH[0], sV[0], kv0, tid);
        CP_COMMIT();
        if (ntile > 1) load_tiles(Hs, Vs, sH[1], sV[1], kv0 + 64, tid);
        CP_COMMIT();
    }

    for (int t = 0; t < ntile; t++) {
        int stage = t & 1;
        CP_WAIT1();
        __syncthreads();

        const __nv_bfloat16* tH = sH[stage];
        const __half* tV = sV[stage];

        // ---- S = Q @ H^T for both m16 halves; ex2 -> f16x2 P fragments ----
        uint32_t pAlo[8], pAhi[8], pBlo[8], pBhi[8];
        #pragma unroll
        for (int j = 0; j < 8; j++) {
            uint32_t hb0, hb1, hb2, hb3, hb4, hb5, hb6, hb7;
            uint32_t a0 = smem_u32(&tH[(8 * j + lm_r) * LDH + lm_m * 8]);
            ldsm_x4(hb0, hb1, hb2, hb3, a0);
            ldsm_x4(hb4, hb5, hb6, hb7, a0 + 32 * 2);
            float sA[4] = {0.f, 0.f, 0.f, 0.f};
            mma16816(sA, qaA[0][0], qaA[0][1], qaA[0][2], qaA[0][3], hb0, hb1);
            mma16816(sA, qaA[1][0], qaA[1][1], qaA[1][2], qaA[1][3], hb2, hb3);
            mma16816(sA, qaA[2][0], qaA[2][1], qaA[2][2], qaA[2][3], hb4, hb5);
            mma16816(sA, qaA[3][0], qaA[3][1], qaA[3][2], qaA[3][3], hb6, hb7);
            float sB[4] = {0.f, 0.f, 0.f, 0.f};
            mma16816(sB, qaB[0][0], qaB[0][1], qaB[0][2], qaB[0][3], hb0, hb1);
            mma16816(sB, qaB[1][0], qaB[1][1], qaB[1][2], qaB[1][3], hb2, hb3);
            mma16816(sB, qaB[2][0], qaB[2][1], qaB[2][2], qaB[2][3], hb4, hb5);
            mma16816(sB, qaB[3][0], qaB[3][1], qaB[3][2], qaB[3][3], hb6, hb7);
            pAlo[j] = ex2_h2(h2_from_f2(sA[0], sA[1]));
            pAhi[j] = ex2_h2(h2_from_f2(sA[2], sA[3]));
            pBlo[j] = ex2_h2(h2_from_f2(sB[0], sB[1]));
            pBhi[j] = ex2_h2(h2_from_f2(sB[2], sB[3]));
        }

        // ---- den trees ----
        dA0 += h2sum_f32(hadd2u(hadd2u(hadd2u(pAlo[0], pAlo[1]), hadd2u(pAlo[2], pAlo[3])),
                                hadd2u(hadd2u(pAlo[4], pAlo[5]), hadd2u(pAlo[6], pAlo[7]))));
        dA1 += h2sum_f32(hadd2u(hadd2u(hadd2u(pAhi[0], pAhi[1]), hadd2u(pAhi[2], pAhi[3])),
                                hadd2u(hadd2u(pAhi[4], pAhi[5]), hadd2u(pAhi[6], pAhi[7]))));
        dB0 += h2sum_f32(hadd2u(hadd2u(hadd2u(pBlo[0], pBlo[1]), hadd2u(pBlo[2], pBlo[3])),
                                hadd2u(hadd2u(pBlo[4], pBlo[5]), hadd2u(pBlo[6], pBlo[7]))));
        dB1 += h2sum_f32(hadd2u(hadd2u(hadd2u(pBhi[0], pBhi[1]), hadd2u(pBhi[2], pBhi[3])),
                                hadd2u(hadd2u(pBhi[4], pBhi[5]), hadd2u(pBhi[6], pBhi[7]))));

        // ---- O += P @ V  (V fragments reused for both m16 halves) ----
        #pragma unroll
        for (int j = 0; j < 8; j++) {
            uint32_t v0, v1, v2, v3, w0, w1, w2, w3;
            uint32_t a0 = smem_u32(&tV[(8 * j + lm_r) * LDV + lm_m * 8]);
            ldsm_x4(v0, v1, v2, v3, a0);
            ldsm_x4(w0, w1, w2, w3, a0 + 32 * 2);
            mma16816h(oA[j], pAlo[0], pAhi[0], pAlo[1], pAhi[1], v0, v1);
            mma16816h(oA[j], pAlo[2], pAhi[2], pAlo[3], pAhi[3], v2, v3);
            mma16816h(oA[j], pAlo[4], pAhi[4], pAlo[5], pAhi[5], w0, w1);
            mma16816h(oA[j], pAlo[6], pAhi[6], pAlo[7], pAhi[7], w2, w3);
            mma16816h(oB[j], pBlo[0], pBhi[0], pBlo[1], pBhi[1], v0, v1);
            mma16816h(oB[j], pBlo[2], pBhi[2], pBlo[3], pBhi[3], v2, v3);
            mma16816h(oB[j], pBlo[4], pBhi[4], pBlo[5], pBhi[5], w0, w1);
            mma16816h(oB[j], pBlo[6], pBhi[6], pBlo[7], pBhi[7], w2, w3);
        }

        __syncthreads();
        if (t + 2 < ntile) load_tiles(Hs, Vs, sH[stage], sV[stage], kv0 + (t + 2) * 64, tid);
        CP_COMMIT();
    }

    // reduce den across the 4 lanes sharing a row; subtract exact padding count
    dA0 += __shfl_xor_sync(0xffffffffu, dA0, 1);
    dA0 += __shfl_xor_sync(0xffffffffu, dA0, 2);
    dA1 += __shfl_xor_sync(0xffffffffu, dA1, 1);
    dA1 += __shfl_xor_sync(0xffffffffu, dA1, 2);
    dB0 += __shfl_xor_sync(0xffffffffu, dB0, 1);
    dB0 += __shfl_xor_sync(0xffffffffu, dB0, 2);
    dB1 += __shfl_xor_sync(0xffffffffu, dB1, 1);
    dB1 += __shfl_xor_sync(0xffffffffu, dB1, 2);
    float npad = (float)(ntile * 64 - (kvend - kv0));
    dA0 -= npad; dA1 -= npad; dB0 -= npad; dB1 -= npad;

    if (tig == 0) {
        if (rowA0 < B) g_den[l][split][rowA0] = dA0;
        if (rowA1 < B) g_den[l][split][rowA1] = dA1;
        if (rowB0 < B) g_den[l][split][rowB0] = dB0;
        if (rowB1 < B) g_den[l][split][rowB1] = dB1;
    }
    #pragma unroll
    for (int j = 0; j < 8; j++) {
        int c = 8 * j + 2 * tig;
        if (rowA0 < B) {
            g_num[l][split][rowA0 * 64 + c]     = oA[j][0];
            g_num[l][split][rowA0 * 64 + c + 1] = oA[j][1];
        }
        if (rowA1 < B) {
            g_num[l][split][rowA1 * 64 + c]     = oA[j][2];
            g_num[l][split][rowA1 * 64 + c + 1] = oA[j][3];
        }
        if (rowB0 < B) {
            g_num[l][split][rowB0 * 64 + c]     = oB[j][0];
            g_num[l][split][rowB0 * 64 + c + 1] = oB[j][1];
        }
        if (rowB1 < B) {
            g_num[l][split][rowB1 * 64 + c]     = oB[j][2];
            g_num[l][split][rowB1 * 64 + c + 1] = oB[j][3];
        }
    }
}

// ---------------- kernel 5: combine + epilogue ----------------
__global__ void __launch_bounds__(256) epilogue_kernel(
    const float* __restrict__ uW1, const float* __restrict__ uW2,
    const float* __restrict__ iW1, const float* __restrict__ iW2, int B)
{
    int l = blockIdx.y;
    const float* W1 = (l == 0) ? uW1 : iW1;
    const float* W2 = (l == 0) ? uW2 : iW2;

    __shared__ float sW1[64 * 68];
    __shared__ float sW2[64 * 68];
    __shared__ float sS[64];
    __shared__ float st1[16 * 64];
    __shared__ float st2[16 * 64];
    __shared__ float sden[16];

    int tid = threadIdx.x;
    for (int e = tid; e < 64 * 64; e += 256) {
        int o = e >> 6, d = e & 63;
        sW1[o * 68 + d] = W1[e];
        sW2[o * 68 + d] = W2[e];
    }
    if (tid < 64) sS[tid] = g_S[l][tid];

    int r0 = blockIdx.x * 16;
    if (tid < 16) {
        float dsum = 0.f;
        #pragma unroll
        for (int s = 0; s < NSPLIT; s++) dsum += g_den[l][s][r0 + tid];
        sden[tid] = dsum;
    }
    __syncthreads();

    for (int e = tid; e < 16 * 64; e += 256) {
        int rl = e >> 6, d = e & 63;
        int r = r0 + rl;
        float nsum = 0.f;
        #pragma unroll
        for (int s = 0; s < NSPLIT; s++) nsum += g_num[l][s][r * 64 + d];
        float q  = g_q[l][r * 64 + d];
        float q2 = q + nsum / sden[rl];
        st1[e] = q2 + sS[d];
        st2[e] = q2 * sS[d];
        g_og[l][r * 128 + d] = q;
    }
    __syncthreads();

    int o = tid & 63, rl0 = tid >> 6;
    for (int rl = rl0; rl < 16; rl += 4) {
        float acc = 0.f;
        const float4* t1 = (const float4*)&st1[rl * 64];
        const float4* t2 = (const float4*)&st2[rl * 64];
        const float4* w1 = (const float4*)&sW1[o * 68];
        const float4* w2 = (const float4*)&sW2[o * 68];
        #pragma unroll
        for (int d4 = 0; d4 < 16; d4++) {
            float4 a = t1[d4], b = w1[d4], c = t2[d4], e4 = w2[d4];
            acc += a.x*b.x + a.y*b.y + a.z*b.z + a.w*b.w
                 + c.x*e4.x + c.y*e4.y + c.z*e4.z + c.w*e4.w;
        }
        float out = (acc > 0.f) ? acc : 0.01f * acc;
        g_og[l][(r0 + rl) * 128 + 64 + o] = out;
    }
}

// ---------------- kernel 6: final 128x128 GEMM ----------------
__global__ void __launch_bounds__(256) final_kernel(float* __restrict__ out, int B) {
    int bi = blockIdx.x & 7, bj = blockIdx.x >> 3;
    __shared__ float sU[64 * 16];
    __shared__ float sI[64 * 16];
    int tid = threadIdx.x;
    int ty = tid >> 4, tx = tid & 15;
    float acc = 0.f;
    for (int k0 = 0; k0 < B; k0 += 64) {
        __syncthreads();
        for (int e = tid; e < 64 * 16; e += 256) {
            int kk = e >> 4, c = e & 15;
            sU[e] = g_og[0][(k0 + kk) * 128 + bi * 16 + c];
            sI[e] = g_og[1][(k0 + kk) * 128 + bj * 16 + c];
        }
        __syncthreads();
        #pragma unroll
        for (int kk = 0; kk < 64; kk++)
            acc += sU[kk * 16 + ty] * sI[kk * 16 + tx];
    }
    out[(bi * 16 + ty) * 128 + bj * 16 + tx] = acc;
}

// ---------------- launch ----------------
extern "C" void kernel_launch(void* const* d_in, const int* in_sizes, int n_in,
                              void* d_out, int out_size) {
    const float* user_emb  = (const float*)d_in[0];
    const float* item_emb  = (const float*)d_in[1];
    const float* u_attn_W  = (const float*)d_in[2];
    const float* u_attn_b  = (const float*)d_in[3];
    const float* u_W1      = (const float*)d_in[4];
    const float* u_W2      = (const float*)d_in[5];
    const float* i_attn_W  = (const float*)d_in[6];
    const float* i_attn_b  = (const float*)d_in[7];
    const float* i_W1      = (const float*)d_in[8];
    const float* i_W2      = (const float*)d_in[9];
    const int*   user_id   = (const int*)d_in[10];
    const int*   item_id   = (const int*)d_in[11];
    const int*   all_user_ids = (const int*)d_in[12];
    const int*   all_item_ids = (const int*)d_in[13];

    int B  = in_sizes[10]; if (B > BMAX) B = BMAX;
    int Nu = in_sizes[12]; if (Nu > NMAX) Nu = NMAX;
    int Ni = in_sizes[13]; if (Ni > NMAX) Ni = NMAX;
    float* out = (float*)d_out;

    zero_kernel<<<1, 128>>>();
    hidden_kernel<<<dim3(148, 2), 256>>>(user_emb, item_emb, all_user_ids, all_item_ids,
                                         u_attn_W, u_attn_b, i_attn_W, i_attn_b, Ni, Nu);
    int total = B * 64;
    gather_q_kernel<<<(2 * total + 255) / 256, 256>>>(user_emb, item_emb, user_id, item_id,
                                                      all_user_ids, all_item_ids, B);
    int qblocks = (B + 127) / 128;   // CTA covers 128 query rows (4 warps x 32)
    flash_kernel<<<dim3(qblocks, NSPLIT, 2), 128>>>(B, Ni, Nu);
    epilogue_kernel<<<dim3(B / 16, 2), 256>>>(u_W1, u_W2, i_W1, i_W2, B);
    final_kernel<<<64, 256>>>(out, B);
}

// round 11
// speedup vs baseline: 3.9021x; 1.0218x over previous
#include <cuda_runtime.h>
#include <cuda_bf16.h>
#include <cuda_fp16.h>
#include <cstdint>

#define NMAX   100000
#define NPADH  (NMAX + 128)
#define NPADT  (NMAX + 256)
#define BMAX   2048
#define NSPLIT 13

// ---------------- scratch (zero-initialized device globals; padding never written) -------
__device__ __align__(16) __nv_bfloat16 g_hidden_bf[2][NPADH * 64]; // [key][dim] bf16
__device__ __align__(16) __half        g_keysT[2][64][NPADT];      // [dim][key] f16
__device__ float g_S[2][64];
__device__ float g_q[2][BMAX * 64];
__device__ __align__(16) __nv_bfloat16 g_qbf[2][BMAX * 64];        // Q * log2(e), bf16
__device__ float g_num[2][NSPLIT][BMAX * 64];
__device__ float g_den[2][NSPLIT][BMAX];
__device__ float g_og[2][BMAX * 128];

// ---------------- helpers ----------------
__device__ __forceinline__ uint32_t smem_u32(const void* p) {
    return (uint32_t)__cvta_generic_to_shared(p);
}
__device__ __forceinline__ uint32_t pack_bf2(float lo, float hi) {
    __nv_bfloat162 h = __floats2bfloat162_rn(lo, hi);
    return *reinterpret_cast<uint32_t*>(&h);
}
__device__ __forceinline__ void mma16816(float c[4],
                                         uint32_t a0, uint32_t a1, uint32_t a2, uint32_t a3,
                                         uint32_t b0, uint32_t b1) {
    asm volatile(
        "mma.sync.aligned.m16n8k16.row.col.f32.bf16.bf16.f32 "
        "{%0,%1,%2,%3}, {%4,%5,%6,%7}, {%8,%9}, {%0,%1,%2,%3};"
        : "+f"(c[0]), "+f"(c[1]), "+f"(c[2]), "+f"(c[3])
        : "r"(a0), "r"(a1), "r"(a2), "r"(a3), "r"(b0), "r"(b1));
}
__device__ __forceinline__ void mma16816h(float c[4],
                                          uint32_t a0, uint32_t a1, uint32_t a2, uint32_t a3,
                                          uint32_t b0, uint32_t b1) {
    asm volatile(
        "mma.sync.aligned.m16n8k16.row.col.f32.f16.f16.f32 "
        "{%0,%1,%2,%3}, {%4,%5,%6,%7}, {%8,%9}, {%0,%1,%2,%3};"
        : "+f"(c[0]), "+f"(c[1]), "+f"(c[2]), "+f"(c[3])
        : "r"(a0), "r"(a1), "r"(a2), "r"(a3), "r"(b0), "r"(b1));
}
__device__ __forceinline__ void ldsm_x4(uint32_t& d0, uint32_t& d1, uint32_t& d2, uint32_t& d3,
                                        uint32_t a) {
    asm volatile("ldmatrix.sync.aligned.m8n8.x4.shared.b16 {%0,%1,%2,%3}, [%4];"
                 : "=r"(d0), "=r"(d1), "=r"(d2), "=r"(d3) : "r"(a));
}
__device__ __forceinline__ void cp16(uint32_t saddr, const void* g) {
    asm volatile("cp.async.cg.shared.global [%0], [%1], 16;" :: "r"(saddr), "l"(g));
}
#define CP_COMMIT() asm volatile("cp.async.commit_group;" ::: "memory")
#define CP_WAIT1()  asm volatile("cp.async.wait_group 1;" ::: "memory")

__device__ __forceinline__ uint32_t ex2_h2(uint32_t x) {
    uint32_t r;
    asm("ex2.approx.f16x2 %0, %1;" : "=r"(r) : "r"(x));
    return r;
}
__device__ __forceinline__ uint32_t h2_from_f2(float lo, float hi) {
    __half2 h = __floats2half2_rn(lo, hi);
    return *reinterpret_cast<uint32_t*>(&h);
}
__device__ __forceinline__ uint32_t hadd2u(uint32_t a, uint32_t b) {
    __half2 r = __hadd2(*reinterpret_cast<__half2*>(&a), *reinterpret_cast<__half2*>(&b));
    return *reinterpret_cast<uint32_t*>(&r);
}
__device__ __forceinline__ float h2sum_f32(uint32_t a) {
    __half2 h = *reinterpret_cast<__half2*>(&a);
    return __low2float(h) + __high2float(h);
}

// ---------------- kernel 1 ----------------
__global__ void zero_kernel() {
    int t = threadIdx.x;
    if (t < 128) ((float*)g_S)[t] = 0.f;
}

// ---------------- kernel 2: hidden (mma.sync bf16) + keysT(f16) + S ----------------
__global__ void __launch_bounds__(256) hidden_kernel(
    const float* __restrict__ user_emb, const float* __restrict__ item_emb,
    const int* __restrict__ all_user_ids, const int* __restrict__ all_item_ids,
    const float* __restrict__ uW, const float* __restrict__ ub,
    const float* __restrict__ iW, const float* __restrict__ ib,
    int Ni, int Nu)
{
    int l = blockIdx.y;
    const float* emb = (l == 0) ? item_emb : user_emb;
    const int*   ids = (l == 0) ? all_item_ids : all_user_ids;
    const float* W   = (l == 0) ? uW : iW;
    const float* bb  = (l == 0) ? ub : ib;
    int Nk = (l == 0) ? Ni : Nu;

    __shared__ __nv_bfloat16 sW[64 * 72];
    __shared__ __nv_bfloat16 sK[128 * 72];
    __shared__ float sSum[8][64];
    __shared__ float sB[64];

    int tid = threadIdx.x, lane = tid & 31, warp = tid >> 5;
    for (int e = tid; e < 64 * 64; e += 256) {
        int o = e >> 6, d = e & 63;
        sW[o * 72 + d] = __float2bfloat16(W[e]);
    }
    if (tid < 64) sB[tid] = bb[tid];

    int c4 = lane & 15, r0 = lane >> 4;
    float4 csum = make_float4(0.f, 0.f, 0.f, 0.f);

    int ntiles = (Nk + 127) >> 7;
    for (int t = blockIdx.x; t < ntiles; t += gridDim.x) {
        int base = t << 7;
        __syncthreads();
        #pragma unroll
        for (int k = 0; k < 8; k++) {
            int rl = warp * 16 + r0 + 2 * k;
            int j = base + rl;
            float4 v = make_float4(0.f, 0.f, 0.f, 0.f);
            if (j < Nk) v = *(const float4*)&emb[(size_t)ids[j] * 64 + c4 * 4];
            csum.x += v.x; csum.y += v.y; csum.z += v.z; csum.w += v.w;
            uint2 u; u.x = pack_bf2(v.x, v.y); u.y = pack_bf2(v.z, v.w);
            *(uint2*)&sK[rl * 72 + c4 * 4] = u;
        }
        __syncthreads();
        { // transposed keys write as f16: g_keysT[dim][key]
            int d = tid & 63, rseg = tid >> 6;
            #pragma unroll
            for (int s = 0; s < 4; s++) {
                union { uint4 u; __half h[8]; } pk;
                #pragma unroll
                for (int q = 0; q < 8; q++)
                    pk.h[q] = __float2half(__bfloat162float(sK[(rseg * 32 + s * 8 + q) * 72 + d]));
                *(uint4*)&g_keysT[l][d][base + rseg * 32 + s * 8] = pk.u;
            }
        }
        uint32_t afr[4][4];
        #pragma unroll
        for (int kk = 0; kk < 4; kk++) {
            uint32_t a = smem_u32(&sK[(warp * 16 + (lane & 15)) * 72 + kk * 16 + (lane >> 4) * 8]);
            ldsm_x4(afr[kk][0], afr[kk][1], afr[kk][2], afr[kk][3], a);
        }
        int gid = lane >> 2, tig = lane & 3;
        int row0 = base + warp * 16 + gid, row1 = row0 + 8;
        #pragma unroll
        for (int j = 0; j < 8; j++) {
            float acc[4] = {0.f, 0.f, 0.f, 0.f};
            uint32_t b0, b1, b2, b3, b4, b5, b6, b7;
            uint32_t a = smem_u32(&sW[(8 * j + (lane & 7)) * 72 + (lane >> 3) * 8]);
            ldsm_x4(b0, b1, b2, b3, a);
            ldsm_x4(b4, b5, b6, b7, a + 32 * 2);
            mma16816(acc, afr[0][0], afr[0][1], afr[0][2], afr[0][3], b0, b1);
            mma16816(acc, afr[1][0], afr[1][1], afr[1][2], afr[1][3], b2, b3);
            mma16816(acc, afr[2][0], afr[2][1], afr[2][2], afr[2][3], b4, b5);
            mma16816(acc, afr[3][0], afr[3][1], afr[3][2], afr[3][3], b6, b7);
            int c = 8 * j + 2 * tig;
            float bz0 = sB[c], bz1 = sB[c + 1];
            if (row0 < Nk)
                *(uint32_t*)&g_hidden_bf[l][(size_t)row0 * 64 + c] =
                    pack_bf2(fmaxf(acc[0] + bz0, 0.f), fmaxf(acc[1] + bz1, 0.f));
            if (row1 < Nk)
                *(uint32_t*)&g_hidden_bf[l][(size_t)row1 * 64 + c] =
                    pack_bf2(fmaxf(acc[2] + bz0, 0.f), fmaxf(acc[3] + bz1, 0.f));
        }
    }
    csum.x += __shfl_xor_sync(0xffffffffu, csum.x, 16);
    csum.y += __shfl_xor_sync(0xffffffffu, csum.y, 16);
    csum.z += __shfl_xor_sync(0xffffffffu, csum.z, 16);
    csum.w += __shfl_xor_sync(0xffffffffu, csum.w, 16);
    if (lane < 16) *(float4*)&sSum[warp][c4 * 4] = csum;
    __syncthreads();
    if (tid < 64) {
        float s = 0.f;
        #pragma unroll
        for (int w = 0; w < 8; w++) s += sSum[w][tid];
        atomicAdd(&g_S[l][tid], s);
    }
}

// ---------------- kernel 3: gather queries (bf16 copy scaled by log2e) ----------------
__global__ void gather_q_kernel(
    const float* __restrict__ user_emb, const float* __restrict__ item_emb,
    const int* __restrict__ user_id, const int* __restrict__ item_id,
    const int* __restrict__ all_user_ids, const int* __restrict__ all_item_ids, int B)
{
    int idx = blockIdx.x * blockDim.x + threadIdx.x;
    int total = B * 64;
    if (idx < 2 * total) {
        int l = idx / total;
        int e = idx - l * total;
        int b = e >> 6, d = e & 63;
        float v;
        if (l == 0) v = user_emb[(size_t)all_user_ids[user_id[b]] * 64 + d];
        else        v = item_emb[(size_t)all_item_ids[item_id[b]] * 64 + d];
        g_q[l][e]   = v;
        g_qbf[l][e] = __float2bfloat16(v * 1.4426950408889634f);  // log2(e)
    }
}

// ---------------- kernel 4: flash attention (M=32/warp, 3-stage single-sync ring) -------
// tile = 64 rows x 128 bytes, XOR-swizzled 16B chunks: phys_chunk = ch ^ (row & 7)
#define TILE_B 8192
__device__ __forceinline__ uint32_t swz(int row, int ch) {
    return (uint32_t)(row * 128 + ((ch ^ (row & 7)) << 4));
}

__device__ __forceinline__ void load_tiles(const __nv_bfloat16* __restrict__ Hs,
                                           const __half* __restrict__ Vs,
                                           uint32_t sHb, uint32_t sVb,
                                           int kv, int tid)
{
    #pragma unroll
    for (int i = 0; i < 4; i++) {
        int c = tid + i * 128;          // 512 chunks per tile
        int row = c >> 3, ch = c & 7;
        uint32_t off = swz(row, ch);
        cp16(sHb + off, Hs + (size_t)(kv + row) * 64 + ch * 8);
        cp16(sVb + off, Vs + (size_t)row * NPADT + kv + ch * 8);
    }
}

__global__ void __launch_bounds__(128, 3) flash_kernel(int B, int Ni, int Nu) {
    int l  = blockIdx.z;
    int Nk = (l == 0) ? Ni : Nu;
    int qb = blockIdx.x, split = blockIdx.y;

    const __nv_bfloat16* __restrict__ Hs = g_hidden_bf[l];
    const __half* __restrict__ Vs = &g_keysT[l][0][0];
    const __nv_bfloat16* __restrict__ Qs = g_qbf[l];

    __shared__ __align__(128) unsigned char sH[3][TILE_B];
    __shared__ __align__(128) unsigned char sV[3][TILE_B];

    int tid = threadIdx.x, lane = tid & 31, warp = tid >> 5;   // 4 warps
    int gid = lane >> 2, tig = lane & 3;
    int lm_r = lane & 7, lm_m = lane >> 3;

    // CTA covers 128 query rows; each warp covers 32 (two m16 tiles A/B)
    int rowA0 = qb * 128 + warp * 32 + gid;
    int rowA1 = rowA0 + 8;
    int rowB0 = rowA0 + 16;
    int rowB1 = rowA0 + 24;

    uint32_t qaA[4][4], qaB[4][4];
    #pragma unroll
    for (int kk = 0; kk < 4; kk++) {
        int kc = kk * 16 + 2 * tig;
        qaA[kk][0] = (rowA0 < B) ? *(const uint32_t*)&Qs[(size_t)rowA0 * 64 + kc]     : 0u;
        qaA[kk][1] = (rowA1 < B) ? *(const uint32_t*)&Qs[(size_t)rowA1 * 64 + kc]     : 0u;
        qaA[kk][2] = (rowA0 < B) ? *(const uint32_t*)&Qs[(size_t)rowA0 * 64 + kc + 8] : 0u;
        qaA[kk][3] = (rowA1 < B) ? *(const uint32_t*)&Qs[(size_t)rowA1 * 64 + kc + 8] : 0u;
        qaB[kk][0] = (rowB0 < B) ? *(const uint32_t*)&Qs[(size_t)rowB0 * 64 + kc]     : 0u;
        qaB[kk][1] = (rowB1 < B) ? *(const uint32_t*)&Qs[(size_t)rowB1 * 64 + kc]     : 0u;
        qaB[kk][2] = (rowB0 < B) ? *(const uint32_t*)&Qs[(size_t)rowB0 * 64 + kc + 8] : 0u;
        qaB[kk][3] = (rowB1 < B) ? *(const uint32_t*)&Qs[(size_t)rowB1 * 64 + kc + 8] : 0u;
    }

    // split bounds: 64-aligned chunks
    int ntiles_all = (Nk + 63) >> 6;
    int tiles_per  = (ntiles_all + NSPLIT - 1) / NSPLIT;
    int chunk = tiles_per << 6;
    int kv0   = split * chunk;
    int kvend = min(kv0 + chunk, Nk);
    int ntile = (kvend > kv0) ? ((kvend - kv0 + 63) >> 6) : 0;

    float oA[8][4], oB[8][4];
    #pragma unroll
    for (int j = 0; j < 8; j++)
        #pragma unroll
        for (int q = 0; q < 4; q++) { oA[j][q] = 0.f; oB[j][q] = 0.f; }
    float dA0 = 0.f, dA1 = 0.f, dB0 = 0.f, dB1 = 0.f;

    // prologue: tiles 0 and 1 into stages 0 and 1 (always two commits)
    if (ntile > 0) load_tiles(Hs, Vs, smem_u32(sH[0]), smem_u32(sV[0]), kv0, tid);
    CP_COMMIT();
    if (ntile > 1) load_tiles(Hs, Vs, smem_u32(sH[1]), smem_u32(sV[1]), kv0 + 64, tid);
    CP_COMMIT();

    for (int t = 0; t < ntile; t++) {
        // tile t resident for THIS thread (commits 0..t+1 issued; allow newest 1 pending)
        CP_WAIT1();
        __syncthreads();   // all threads' tile-t copies visible; stage (t+2)%3 free of readers

        // prefetch tile t+2 (2-tile lead; overlaps the whole compute below)
        if (t + 2 < ntile) {
            int st = (t + 2) % 3;
            load_tiles(Hs, Vs, smem_u32(sH[st]), smem_u32(sV[st]), kv0 + (t + 2) * 64, tid);
        }
        CP_COMMIT();

        uint32_t hb = smem_u32(sH[t % 3]);
        uint32_t vb = smem_u32(sV[t % 3]);

        // ---- S = Q @ H^T for both m16 halves; ex2 -> f16x2 P fragments ----
        uint32_t pAlo[8], pAhi[8], pBlo[8], pBhi[8];
        #pragma unroll
        for (int j = 0; j < 8; j++) {
            uint32_t hb0, hb1, hb2, hb3, hb4, hb5, hb6, hb7;
            uint32_t rowoff = hb + (uint32_t)((8 * j + lm_r) * 128);
            ldsm_x4(hb0, hb1, hb2, hb3, rowoff + (uint32_t)(( lm_m      ^ lm_r) << 4));
            ldsm_x4(hb4, hb5, hb6, hb7, rowoff + (uint32_t)(((lm_m + 4) ^ lm_r) << 4));
            float sA[4] = {0.f, 0.f, 0.f, 0.f};
            mma16816(sA, qaA[0][0], qaA[0][1], qaA[0][2], qaA[0][3], hb0, hb1);
            mma16816(sA, qaA[1][0], qaA[1][1], qaA[1][2], qaA[1][3], hb2, hb3);
            mma16816(sA, qaA[2][0], qaA[2][1], qaA[2][2], qaA[2][3], hb4, hb5);
            mma16816(sA, qaA[3][0], qaA[3][1], qaA[3][2], qaA[3][3], hb6, hb7);
            float sB[4] = {0.f, 0.f, 0.f, 0.f};
            mma16816(sB, qaB[0][0], qaB[0][1], qaB[0][2], qaB[0][3], hb0, hb1);
            mma16816(sB, qaB[1][0], qaB[1][1], qaB[1][2], qaB[1][3], hb2, hb3);
            mma16816(sB, qaB[2][0], qaB[2][1], qaB[2][2], qaB[2][3], hb4, hb5);
            mma16816(sB, qaB[3][0], qaB[3][1], qaB[3][2], qaB[3][3], hb6, hb7);
            pAlo[j] = ex2_h2(h2_from_f2(sA[0], sA[1]));
            pAhi[j] = ex2_h2(h2_from_f2(sA[2], sA[3]));
            pBlo[j] = ex2_h2(h2_from_f2(sB[0], sB[1]));
            pBhi[j] = ex2_h2(h2_from_f2(sB[2], sB[3]));
        }

        // ---- den trees ----
        dA0 += h2sum_f32(hadd2u(hadd2u(hadd2u(pAlo[0], pAlo[1]), hadd2u(pAlo[2], pAlo[3])),
                                hadd2u(hadd2u(pAlo[4], pAlo[5]), hadd2u(pAlo[6], pAlo[7]))));
        dA1 += h2sum_f32(hadd2u(hadd2u(hadd2u(pAhi[0], pAhi[1]), hadd2u(pAhi[2], pAhi[3])),
                                hadd2u(hadd2u(pAhi[4], pAhi[5]), hadd2u(pAhi[6], pAhi[7]))));
        dB0 += h2sum_f32(hadd2u(hadd2u(hadd2u(pBlo[0], pBlo[1]), hadd2u(pBlo[2], pBlo[3])),
                                hadd2u(hadd2u(pBlo[4], pBlo[5]), hadd2u(pBlo[6], pBlo[7]))));
        dB1 += h2sum_f32(hadd2u(hadd2u(hadd2u(pBhi[0], pBhi[1]), hadd2u(pBhi[2], pBhi[3])),
                                hadd2u(hadd2u(pBhi[4], pBhi[5]), hadd2u(pBhi[6], pBhi[7]))));

        // ---- O += P @ V  (V fragments reused for both m16 halves) ----
        #pragma unroll
        for (int j = 0; j < 8; j++) {
            uint32_t v0, v1, v2, v3, w0, w1, w2, w3;
            uint32_t rowoff = vb + (uint32_t)((8 * j + lm_r) * 128);
            ldsm_x4(v0, v1, v2, v3, rowoff + (uint32_t)(( lm_m      ^ lm_r) << 4));
            ldsm_x4(w0, w1, w2, w3, rowoff + (uint32_t)(((lm_m + 4) ^ lm_r) << 4));
            mma16816h(oA[j], pAlo[0], pAhi[0], pAlo[1], pAhi[1], v0, v1);
            mma16816h(oA[j], pAlo[2], pAhi[2], pAlo[3], pAhi[3], v2, v3);
            mma16816h(oA[j], pAlo[4], pAhi[4], pAlo[5], pAhi[5], w0, w1);
            mma16816h(oA[j], pAlo[6], pAhi[6], pAlo[7], pAhi[7], w2, w3);
            mma16816h(oB[j], pBlo[0], pBhi[0], pBlo[1], pBhi[1], v0, v1);
            mma16816h(oB[j], pBlo[2], pBhi[2], pBlo[3], pBhi[3], v2, v3);
            mma16816h(oB[j], pBlo[4], pBhi[4], pBlo[5], pBhi[5], w0, w1);
            mma16816h(oB[j], pBlo[6], pBhi[6], pBlo[7], pBhi[7], w2, w3);
        }
    }

    // reduce den across the 4 lanes sharing a row; subtract exact padding count
    dA0 += __shfl_xor_sync(0xffffffffu, dA0, 1);
    dA0 += __shfl_xor_sync(0xffffffffu, dA0, 2);
    dA1 += __shfl_xor_sync(0xffffffffu, dA1, 1);
    dA1 += __shfl_xor_sync(0xffffffffu, dA1, 2);
    dB0 += __shfl_xor_sync(0xffffffffu, dB0, 1);
    dB0 += __shfl_xor_sync(0xffffffffu, dB0, 2);
    dB1 += __shfl_xor_sync(0xffffffffu, dB1, 1);
    dB1 += __shfl_xor_sync(0xffffffffu, dB1, 2);
    float npad = (float)(ntile * 64 - (kvend - kv0));
    dA0 -= npad; dA1 -= npad; dB0 -= npad; dB1 -= npad;

    if (tig == 0) {
        if (rowA0 < B) g_den[l][split][rowA0] = dA0;
        if (rowA1 < B) g_den[l][split][rowA1] = dA1;
        if (rowB0 < B) g_den[l][split][rowB0] = dB0;
        if (rowB1 < B) g_den[l][split][rowB1] = dB1;
    }
    #pragma unroll
    for (int j = 0; j < 8; j++) {
        int c = 8 * j + 2 * tig;
        if (rowA0 < B) {
            g_num[l][split][rowA0 * 64 + c]     = oA[j][0];
            g_num[l][split][rowA0 * 64 + c + 1] = oA[j][1];
        }
        if (rowA1 < B) {
            g_num[l][split][rowA1 * 64 + c]     = oA[j][2];
            g_num[l][split][rowA1 * 64 + c + 1] = oA[j][3];
        }
        if (rowB0 < B) {
            g_num[l][split][rowB0 * 64 + c]     = oB[j][0];
            g_num[l][split][rowB0 * 64 + c + 1] = oB[j][1];
        }
        if (rowB1 < B) {
            g_num[l][split][rowB1 * 64 + c]     = oB[j][2];
            g_num[l][split][rowB1 * 64 + c + 1] = oB[j][3];
        }
    }
}

// ---------------- kernel 5: combine + epilogue ----------------
__global__ void __launch_bounds__(256) epilogue_kernel(
    const float* __restrict__ uW1, const float* __restrict__ uW2,
    const float* __restrict__ iW1, const float* __restrict__ iW2, int B)
{
    int l = blockIdx.y;
    const float* W1 = (l == 0) ? uW1 : iW1;
    const float* W2 = (l == 0) ? uW2 : iW2;

    __shared__ float sW1[64 * 68];
    __shared__ float sW2[64 * 68];
    __shared__ float sS[64];
    __shared__ float st1[16 * 64];
    __shared__ float st2[16 * 64];
    __shared__ float sden[16];

    int tid = threadIdx.x;
    for (int e = tid; e < 64 * 64; e += 256) {
        int o = e >> 6, d = e & 63;
        sW1[o * 68 + d] = W1[e];
        sW2[o * 68 + d] = W2[e];
    }
    if (tid < 64) sS[tid] = g_S[l][tid];

    int r0 = blockIdx.x * 16;
    if (tid < 16) {
        float dsum = 0.f;
        #pragma unroll
        for (int s = 0; s < NSPLIT; s++) dsum += g_den[l][s][r0 + tid];
        sden[tid] = dsum;
    }
    __syncthreads();

    for (int e = tid; e < 16 * 64; e += 256) {
        int rl = e >> 6, d = e & 63;
        int r = r0 + rl;
        float nsum = 0.f;
        #pragma unroll
        for (int s = 0; s < NSPLIT; s++) nsum += g_num[l][s][r * 64 + d];
        float q  = g_q[l][r * 64 + d];
        float q2 = q + nsum / sden[rl];
        st1[e] = q2 + sS[d];
        st2[e] = q2 * sS[d];
        g_og[l][r * 128 + d] = q;
    }
    __syncthreads();

    int o = tid & 63, rl0 = tid >> 6;
    for (int rl = rl0; rl < 16; rl += 4) {
        float acc = 0.f;
        const float4* t1 = (const float4*)&st1[rl * 64];
        const float4* t2 = (const float4*)&st2[rl * 64];
        const float4* w1 = (const float4*)&sW1[o * 68];
        const float4* w2 = (const float4*)&sW2[o * 68];
        #pragma unroll
        for (int d4 = 0; d4 < 16; d4++) {
            float4 a = t1[d4], b = w1[d4], c = t2[d4], e4 = w2[d4];
            acc += a.x*b.x + a.y*b.y + a.z*b.z + a.w*b.w
                 + c.x*e4.x + c.y*e4.y + c.z*e4.z + c.w*e4.w;
        }
        float out = (acc > 0.f) ? acc : 0.01f * acc;
        g_og[l][(r0 + rl) * 128 + 64 + o] = out;
    }
}

// ---------------- kernel 6: final 128x128 GEMM ----------------
__global__ void __launch_bounds__(256) final_kernel(float* __restrict__ out, int B) {
    int bi = blockIdx.x & 7, bj = blockIdx.x >> 3;
    __shared__ float sU[64 * 16];
    __shared__ float sI[64 * 16];
    int tid = threadIdx.x;
    int ty = tid >> 4, tx = tid & 15;
    float acc = 0.f;
    for (int k0 = 0; k0 < B; k0 += 64) {
        __syncthreads();
        for (int e = tid; e < 64 * 16; e += 256) {
            int kk = e >> 4, c = e & 15;
            sU[e] = g_og[0][(k0 + kk) * 128 + bi * 16 + c];
            sI[e] = g_og[1][(k0 + kk) * 128 + bj * 16 + c];
        }
        __syncthreads();
        #pragma unroll
        for (int kk = 0; kk < 64; kk++)
            acc += sU[kk * 16 + ty] * sI[kk * 16 + tx];
    }
    out[(bi * 16 + ty) * 128 + bj * 16 + tx] = acc;
}

// ---------------- launch ----------------
extern "C" void kernel_launch(void* const* d_in, const int* in_sizes, int n_in,
                              void* d_out, int out_size) {
    const float* user_emb  = (const float*)d_in[0];
    const float* item_emb  = (const float*)d_in[1];
    const float* u_attn_W  = (const float*)d_in[2];
    const float* u_attn_b  = (const float*)d_in[3];
    const float* u_W1      = (const float*)d_in[4];
    const float* u_W2      = (const float*)d_in[5];
    const float* i_attn_W  = (const float*)d_in[6];
    const float* i_attn_b  = (const float*)d_in[7];
    const float* i_W1      = (const float*)d_in[8];
    const float* i_W2      = (const float*)d_in[9];
    const int*   user_id   = (const int*)d_in[10];
    const int*   item_id   = (const int*)d_in[11];
    const int*   all_user_ids = (const int*)d_in[12];
    const int*   all_item_ids = (const int*)d_in[13];

    int B  = in_sizes[10]; if (B > BMAX) B = BMAX;
    int Nu = in_sizes[12]; if (Nu > NMAX) Nu = NMAX;
    int Ni = in_sizes[13]; if (Ni > NMAX) Ni = NMAX;
    float* out = (float*)d_out;

    zero_kernel<<<1, 128>>>();
    hidden_kernel<<<dim3(148, 2), 256>>>(user_emb, item_emb, all_user_ids, all_item_ids,
                                         u_attn_W, u_attn_b, i_attn_W, i_attn_b, Ni, Nu);
    int total = B * 64;
    gather_q_kernel<<<(2 * total + 255) / 256, 256>>>(user_emb, item_emb, user_id, item_id,
                                                      all_user_ids, all_item_ids, B);
    int qblocks = (B + 127) / 128;   // CTA covers 128 query rows (4 warps x 32)
    flash_kernel<<<dim3(qblocks, NSPLIT, 2), 128>>>(B, Ni, Nu);
    epilogue_kernel<<<dim3(B / 16, 2), 256>>>(u_W1, u_W2, i_W1, i_W2, B);
    final_kernel<<<64, 256>>>(out, B);
}

// round 13
// speedup vs baseline: 3.9301x; 1.0072x over previous
#include <cuda_runtime.h>
#include <cuda_bf16.h>
#include <cuda_fp16.h>
#include <cstdint>

#define NMAX   100000
#define NPADH  (NMAX + 128)
#define BMAX   2048
#define NSPLIT 13

// ---------------- scratch (zero-initialized device globals; padding never written) -------
__device__ __align__(16) __nv_bfloat16 g_hidden_bf[2][NPADH * 64]; // [key][dim] bf16
__device__ __align__(16) __half        g_keys16[2][NPADH * 64];    // [key][dim] f16
__device__ float g_S[2][64];
__device__ float g_q[2][BMAX * 64];
__device__ __align__(16) __nv_bfloat16 g_qbf[2][BMAX * 64];        // Q * log2(e), bf16
__device__ float g_num[2][NSPLIT][BMAX * 64];
__device__ float g_den[2][NSPLIT][BMAX];
__device__ float g_og[2][BMAX * 128];

// ---------------- helpers ----------------
__device__ __forceinline__ uint32_t smem_u32(const void* p) {
    return (uint32_t)__cvta_generic_to_shared(p);
}
__device__ __forceinline__ uint32_t pack_bf2(float lo, float hi) {
    __nv_bfloat162 h = __floats2bfloat162_rn(lo, hi);
    return *reinterpret_cast<uint32_t*>(&h);
}
__device__ __forceinline__ uint32_t pack_h2(float lo, float hi) {
    __half2 h = __floats2half2_rn(lo, hi);
    return *reinterpret_cast<uint32_t*>(&h);
}
__device__ __forceinline__ void mma16816(float c[4],
                                         uint32_t a0, uint32_t a1, uint32_t a2, uint32_t a3,
                                         uint32_t b0, uint32_t b1) {
    asm volatile(
        "mma.sync.aligned.m16n8k16.row.col.f32.bf16.bf16.f32 "
        "{%0,%1,%2,%3}, {%4,%5,%6,%7}, {%8,%9}, {%0,%1,%2,%3};"
        : "+f"(c[0]), "+f"(c[1]), "+f"(c[2]), "+f"(c[3])
        : "r"(a0), "r"(a1), "r"(a2), "r"(a3), "r"(b0), "r"(b1));
}
__device__ __forceinline__ void mma16816h(float c[4],
                                          uint32_t a0, uint32_t a1, uint32_t a2, uint32_t a3,
                                          uint32_t b0, uint32_t b1) {
    asm volatile(
        "mma.sync.aligned.m16n8k16.row.col.f32.f16.f16.f32 "
        "{%0,%1,%2,%3}, {%4,%5,%6,%7}, {%8,%9}, {%0,%1,%2,%3};"
        : "+f"(c[0]), "+f"(c[1]), "+f"(c[2]), "+f"(c[3])
        : "r"(a0), "r"(a1), "r"(a2), "r"(a3), "r"(b0), "r"(b1));
}
__device__ __forceinline__ void ldsm_x4(uint32_t& d0, uint32_t& d1, uint32_t& d2, uint32_t& d3,
                                        uint32_t a) {
    asm volatile("ldmatrix.sync.aligned.m8n8.x4.shared.b16 {%0,%1,%2,%3}, [%4];"
                 : "=r"(d0), "=r"(d1), "=r"(d2), "=r"(d3) : "r"(a));
}
__device__ __forceinline__ void ldsm_x4t(uint32_t& d0, uint32_t& d1, uint32_t& d2, uint32_t& d3,
                                         uint32_t a) {
    asm volatile("ldmatrix.sync.aligned.m8n8.x4.trans.shared.b16 {%0,%1,%2,%3}, [%4];"
                 : "=r"(d0), "=r"(d1), "=r"(d2), "=r"(d3) : "r"(a));
}
__device__ __forceinline__ void cp16(uint32_t saddr, const void* g) {
    asm volatile("cp.async.cg.shared.global [%0], [%1], 16;" :: "r"(saddr), "l"(g));
}
#define CP_COMMIT() asm volatile("cp.async.commit_group;" ::: "memory")
#define CP_WAIT1()  asm volatile("cp.async.wait_group 1;" ::: "memory")

__device__ __forceinline__ uint32_t ex2_h2(uint32_t x) {
    uint32_t r;
    asm("ex2.approx.f16x2 %0, %1;" : "=r"(r) : "r"(x));
    return r;
}
__device__ __forceinline__ uint32_t h2_from_f2(float lo, float hi) {
    __half2 h = __floats2half2_rn(lo, hi);
    return *reinterpret_cast<uint32_t*>(&h);
}
__device__ __forceinline__ uint32_t hadd2u(uint32_t a, uint32_t b) {
    __half2 r = __hadd2(*reinterpret_cast<__half2*>(&a), *reinterpret_cast<__half2*>(&b));
    return *reinterpret_cast<uint32_t*>(&r);
}
__device__ __forceinline__ float h2sum_f32(uint32_t a) {
    __half2 h = *reinterpret_cast<__half2*>(&a);
    return __low2float(h) + __high2float(h);
}

// ---------------- kernel 1 ----------------
__global__ void zero_kernel() {
    int t = threadIdx.x;
    if (t < 128) ((float*)g_S)[t] = 0.f;
}

// ---------------- kernel 2: hidden (mma.sync bf16) + keys f16 row-major + S --------------
__global__ void __launch_bounds__(256) hidden_kernel(
    const float* __restrict__ user_emb, const float* __restrict__ item_emb,
    const int* __restrict__ all_user_ids, const int* __restrict__ all_item_ids,
    const float* __restrict__ uW, const float* __restrict__ ub,
    const float* __restrict__ iW, const float* __restrict__ ib,
    int Ni, int Nu)
{
    int l = blockIdx.y;
    const float* emb = (l == 0) ? item_emb : user_emb;
    const int*   ids = (l == 0) ? all_item_ids : all_user_ids;
    const float* W   = (l == 0) ? uW : iW;
    const float* bb  = (l == 0) ? ub : ib;
    int Nk = (l == 0) ? Ni : Nu;

    __shared__ __nv_bfloat16 sW[64 * 72];
    __shared__ __nv_bfloat16 sK[128 * 72];
    __shared__ float sSum[8][64];
    __shared__ float sB[64];

    int tid = threadIdx.x, lane = tid & 31, warp = tid >> 5;
    for (int e = tid; e < 64 * 64; e += 256) {
        int o = e >> 6, d = e & 63;
        sW[o * 72 + d] = __float2bfloat16(W[e]);
    }
    if (tid < 64) sB[tid] = bb[tid];

    int c4 = lane & 15, r0 = lane >> 4;
    float4 csum = make_float4(0.f, 0.f, 0.f, 0.f);

    int ntiles = (Nk + 127) >> 7;
    for (int t = blockIdx.x; t < ntiles; t += gridDim.x) {
        int base = t << 7;
        __syncthreads();
        #pragma unroll
        for (int k = 0; k < 8; k++) {
            int rl = warp * 16 + r0 + 2 * k;
            int j = base + rl;
            float4 v = make_float4(0.f, 0.f, 0.f, 0.f);
            if (j < Nk) v = *(const float4*)&emb[(size_t)ids[j] * 64 + c4 * 4];
            csum.x += v.x; csum.y += v.y; csum.z += v.z; csum.w += v.w;
            uint2 u; u.x = pack_bf2(v.x, v.y); u.y = pack_bf2(v.z, v.w);
            *(uint2*)&sK[rl * 72 + c4 * 4] = u;
            if (j < Nk) {   // f16 keys, row-major, straight from registers (no transpose)
                uint2 w; w.x = pack_h2(v.x, v.y); w.y = pack_h2(v.z, v.w);
                *(uint2*)&g_keys16[l][(size_t)j * 64 + c4 * 4] = w;
            }
        }
        __syncthreads();
        uint32_t afr[4][4];
        #pragma unroll
        for (int kk = 0; kk < 4; kk++) {
            uint32_t a = smem_u32(&sK[(warp * 16 + (lane & 15)) * 72 + kk * 16 + (lane >> 4) * 8]);
            ldsm_x4(afr[kk][0], afr[kk][1], afr[kk][2], afr[kk][3], a);
        }
        int gid = lane >> 2, tig = lane & 3;
        int row0 = base + warp * 16 + gid, row1 = row0 + 8;
        #pragma unroll
        for (int j = 0; j < 8; j++) {
            float acc[4] = {0.f, 0.f, 0.f, 0.f};
            uint32_t b0, b1, b2, b3, b4, b5, b6, b7;
            uint32_t a = smem_u32(&sW[(8 * j + (lane & 7)) * 72 + (lane >> 3) * 8]);
            ldsm_x4(b0, b1, b2, b3, a);
            ldsm_x4(b4, b5, b6, b7, a + 32 * 2);
            mma16816(acc, afr[0][0], afr[0][1], afr[0][2], afr[0][3], b0, b1);
            mma16816(acc, afr[1][0], afr[1][1], afr[1][2], afr[1][3], b2, b3);
            mma16816(acc, afr[2][0], afr[2][1], afr[2][2], afr[2][3], b4, b5);
            mma16816(acc, afr[3][0], afr[3][1], afr[3][2], afr[3][3], b6, b7);
            int c = 8 * j + 2 * tig;
            float bz0 = sB[c], bz1 = sB[c + 1];
            if (row0 < Nk)
                *(uint32_t*)&g_hidden_bf[l][(size_t)row0 * 64 + c] =
                    pack_bf2(fmaxf(acc[0] + bz0, 0.f), fmaxf(acc[1] + bz1, 0.f));
            if (row1 < Nk)
                *(uint32_t*)&g_hidden_bf[l][(size_t)row1 * 64 + c] =
                    pack_bf2(fmaxf(acc[2] + bz0, 0.f), fmaxf(acc[3] + bz1, 0.f));
        }
    }
    csum.x += __shfl_xor_sync(0xffffffffu, csum.x, 16);
    csum.y += __shfl_xor_sync(0xffffffffu, csum.y, 16);
    csum.z += __shfl_xor_sync(0xffffffffu, csum.z, 16);
    csum.w += __shfl_xor_sync(0xffffffffu, csum.w, 16);
    if (lane < 16) *(float4*)&sSum[warp][c4 * 4] = csum;
    __syncthreads();
    if (tid < 64) {
        float s = 0.f;
        #pragma unroll
        for (int w = 0; w < 8; w++) s += sSum[w][tid];
        atomicAdd(&g_S[l][tid], s);
    }
}

// ---------------- kernel 3: gather queries (bf16 copy scaled by log2e) ----------------
__global__ void gather_q_kernel(
    const float* __restrict__ user_emb, const float* __restrict__ item_emb,
    const int* __restrict__ user_id, const int* __restrict__ item_id,
    const int* __restrict__ all_user_ids, const int* __restrict__ all_item_ids, int B)
{
    int idx = blockIdx.x * blockDim.x + threadIdx.x;
    int total = B * 64;
    if (idx < 2 * total) {
        int l = idx / total;
        int e = idx - l * total;
        int b = e >> 6, d = e & 63;
        float v;
        if (l == 0) v = user_emb[(size_t)all_user_ids[user_id[b]] * 64 + d];
        else        v = item_emb[(size_t)all_item_ids[item_id[b]] * 64 + d];
        g_q[l][e]   = v;
        g_qbf[l][e] = __float2bfloat16(v * 1.4426950408889634f);  // log2(e)
    }
}

// ---------------- kernel 4: flash attention (M=32/warp, 3-stage ring, trans-ldsm V) -----
// tile = 64 rows x 128 bytes, XOR-swizzled 16B chunks: phys_chunk = ch ^ (row & 7)
#define TILE_B 8192

__device__ __forceinline__ void load_tiles(const __nv_bfloat16* __restrict__ Hs,
                                           const __half* __restrict__ Vs,
                                           uint32_t sHb, uint32_t sVb,
                                           int kv, int tid)
{
    #pragma unroll
    for (int i = 0; i < 4; i++) {
        int c = tid + i * 128;          // 512 chunks per tile
        int row = c >> 3, ch = c & 7;
        uint32_t off = (uint32_t)(row * 128 + ((ch ^ (row & 7)) << 4));
        cp16(sHb + off, Hs + (size_t)(kv + row) * 64 + ch * 8);
        cp16(sVb + off, Vs + (size_t)(kv + row) * 64 + ch * 8);
    }
}

__global__ void __launch_bounds__(128, 3) flash_kernel(int B, int Ni, int Nu) {
    int l  = blockIdx.z;
    int Nk = (l == 0) ? Ni : Nu;
    int qb = blockIdx.x, split = blockIdx.y;

    const __nv_bfloat16* __restrict__ Hs = g_hidden_bf[l];
    const __half* __restrict__ Vs = g_keys16[l];
    const __nv_bfloat16* __restrict__ Qs = g_qbf[l];

    __shared__ __align__(128) unsigned char sH[3][TILE_B];
    __shared__ __align__(128) unsigned char sV[3][TILE_B];

    int tid = threadIdx.x, lane = tid & 31, warp = tid >> 5;   // 4 warps
    int gid = lane >> 2, tig = lane & 3;
    int lm_r = lane & 7, lm_m = lane >> 3;

    // CTA covers 128 query rows; each warp covers 32 (two m16 tiles A/B)
    int rowA0 = qb * 128 + warp * 32 + gid;
    int rowA1 = rowA0 + 8;
    int rowB0 = rowA0 + 16;
    int rowB1 = rowA0 + 24;

    uint32_t qaA[4][4], qaB[4][4];
    #pragma unroll
    for (int kk = 0; kk < 4; kk++) {
        int kc = kk * 16 + 2 * tig;
        qaA[kk][0] = (rowA0 < B) ? *(const uint32_t*)&Qs[(size_t)rowA0 * 64 + kc]     : 0u;
        qaA[kk][1] = (rowA1 < B) ? *(const uint32_t*)&Qs[(size_t)rowA1 * 64 + kc]     : 0u;
        qaA[kk][2] = (rowA0 < B) ? *(const uint32_t*)&Qs[(size_t)rowA0 * 64 + kc + 8] : 0u;
        qaA[kk][3] = (rowA1 < B) ? *(const uint32_t*)&Qs[(size_t)rowA1 * 64 + kc + 8] : 0u;
        qaB[kk][0] = (rowB0 < B) ? *(const uint32_t*)&Qs[(size_t)rowB0 * 64 + kc]     : 0u;
        qaB[kk][1] = (rowB1 < B) ? *(const uint32_t*)&Qs[(size_t)rowB1 * 64 + kc]     : 0u;
        qaB[kk][2] = (rowB0 < B) ? *(const uint32_t*)&Qs[(size_t)rowB0 * 64 + kc + 8] : 0u;
        qaB[kk][3] = (rowB1 < B) ? *(const uint32_t*)&Qs[(size_t)rowB1 * 64 + kc + 8] : 0u;
    }

    // split bounds: 64-aligned chunks
    int ntiles_all = (Nk + 63) >> 6;
    int tiles_per  = (ntiles_all + NSPLIT - 1) / NSPLIT;
    int chunk = tiles_per << 6;
    int kv0   = split * chunk;
    int kvend = min(kv0 + chunk, Nk);
    int ntile = (kvend > kv0) ? ((kvend - kv0 + 63) >> 6) : 0;

    float oA[8][4], oB[8][4];
    #pragma unroll
    for (int j = 0; j < 8; j++)
        #pragma unroll
        for (int q = 0; q < 4; q++) { oA[j][q] = 0.f; oB[j][q] = 0.f; }
    float dA0 = 0.f, dA1 = 0.f, dB0 = 0.f, dB1 = 0.f;

    // prologue: tiles 0 and 1 into stages 0 and 1 (always two commits)
    if (ntile > 0) load_tiles(Hs, Vs, smem_u32(sH[0]), smem_u32(sV[0]), kv0, tid);
    CP_COMMIT();
    if (ntile > 1) load_tiles(Hs, Vs, smem_u32(sH[1]), smem_u32(sV[1]), kv0 + 64, tid);
    CP_COMMIT();

    for (int t = 0; t < ntile; t++) {
        CP_WAIT1();
        __syncthreads();   // tile t visible; stage (t+2)%3 free of readers

        if (t + 2 < ntile) {
            int st = (t + 2) % 3;
            load_tiles(Hs, Vs, smem_u32(sH[st]), smem_u32(sV[st]), kv0 + (t + 2) * 64, tid);
        }
        CP_COMMIT();

        uint32_t hb = smem_u32(sH[t % 3]);
        uint32_t vb = smem_u32(sV[t % 3]);

        // ---- S = Q @ H^T for both m16 halves; ex2 -> f16x2 P fragments ----
        uint32_t pAlo[8], pAhi[8], pBlo[8], pBhi[8];
        #pragma unroll
        for (int j = 0; j < 8; j++) {
            uint32_t hb0, hb1, hb2, hb3, hb4, hb5, hb6, hb7;
            uint32_t rowoff = hb + (uint32_t)((8 * j + lm_r) * 128);
            ldsm_x4(hb0, hb1, hb2, hb3, rowoff + (uint32_t)(( lm_m      ^ lm_r) << 4));
            ldsm_x4(hb4, hb5, hb6, hb7, rowoff + (uint32_t)(((lm_m + 4) ^ lm_r) << 4));
            float sA[4] = {0.f, 0.f, 0.f, 0.f};
            mma16816(sA, qaA[0][0], qaA[0][1], qaA[0][2], qaA[0][3], hb0, hb1);
            mma16816(sA, qaA[1][0], qaA[1][1], qaA[1][2], qaA[1][3], hb2, hb3);
            mma16816(sA, qaA[2][0], qaA[2][1], qaA[2][2], qaA[2][3], hb4, hb5);
            mma16816(sA, qaA[3][0], qaA[3][1], qaA[3][2], qaA[3][3], hb6, hb7);
            float sB[4] = {0.f, 0.f, 0.f, 0.f};
            mma16816(sB, qaB[0][0], qaB[0][1], qaB[0][2], qaB[0][3], hb0, hb1);
            mma16816(sB, qaB[1][0], qaB[1][1], qaB[1][2], qaB[1][3], hb2, hb3);
            mma16816(sB, qaB[2][0], qaB[2][1], qaB[2][2], qaB[2][3], hb4, hb5);
            mma16816(sB, qaB[3][0], qaB[3][1], qaB[3][2], qaB[3][3], hb6, hb7);
            pAlo[j] = ex2_h2(h2_from_f2(sA[0], sA[1]));
            pAhi[j] = ex2_h2(h2_from_f2(sA[2], sA[3]));
            pBlo[j] = ex2_h2(h2_from_f2(sB[0], sB[1]));
            pBhi[j] = ex2_h2(h2_from_f2(sB[2], sB[3]));
        }

        // ---- O += P @ V   (V row-major [key][dim]; B-frags via ldmatrix.trans) ----
        #pragma unroll
        for (int kk = 0; kk < 4; kk++) {
            uint32_t aA0 = pAlo[2 * kk], aA1 = pAhi[2 * kk];
            uint32_t aA2 = pAlo[2 * kk + 1], aA3 = pAhi[2 * kk + 1];
            uint32_t aB0 = pBlo[2 * kk], aB1 = pBhi[2 * kk];
            uint32_t aB2 = pBlo[2 * kk + 1], aB3 = pBhi[2 * kk + 1];
            int vrow = 16 * kk + (lm_m & 1) * 8 + lm_r;   // key row; vrow&7 == lm_r
            uint32_t rowoff = vb + (uint32_t)(vrow * 128);
            #pragma unroll
            for (int j0 = 0; j0 < 8; j0 += 2) {
                int ch = j0 + (lm_m >> 1);
                uint32_t v0, v1, v2, v3;
                ldsm_x4t(v0, v1, v2, v3, rowoff + (uint32_t)((ch ^ lm_r) << 4));
                mma16816h(oA[j0],     aA0, aA1, aA2, aA3, v0, v1);
                mma16816h(oA[j0 + 1], aA0, aA1, aA2, aA3, v2, v3);
                mma16816h(oB[j0],     aB0, aB1, aB2, aB3, v0, v1);
                mma16816h(oB[j0 + 1], aB0, aB1, aB2, aB3, v2, v3);
            }
        }

        // ---- den trees (after PV issue; fma pipe overlaps tensor) ----
        dA0 += h2sum_f32(hadd2u(hadd2u(hadd2u(pAlo[0], pAlo[1]), hadd2u(pAlo[2], pAlo[3])),
                                hadd2u(hadd2u(pAlo[4], pAlo[5]), hadd2u(pAlo[6], pAlo[7]))));
        dA1 += h2sum_f32(hadd2u(hadd2u(hadd2u(pAhi[0], pAhi[1]), hadd2u(pAhi[2], pAhi[3])),
                                hadd2u(hadd2u(pAhi[4], pAhi[5]), hadd2u(pAhi[6], pAhi[7]))));
        dB0 += h2sum_f32(hadd2u(hadd2u(hadd2u(pBlo[0], pBlo[1]), hadd2u(pBlo[2], pBlo[3])),
                                hadd2u(hadd2u(pBlo[4], pBlo[5]), hadd2u(pBlo[6], pBlo[7]))));
        dB1 += h2sum_f32(hadd2u(hadd2u(hadd2u(pBhi[0], pBhi[1]), hadd2u(pBhi[2], pBhi[3])),
                                hadd2u(hadd2u(pBhi[4], pBhi[5]), hadd2u(pBhi[6], pBhi[7]))));
    }

    // reduce den across the 4 lanes sharing a row; subtract exact padding count
    dA0 += __shfl_xor_sync(0xffffffffu, dA0, 1);
    dA0 += __shfl_xor_sync(0xffffffffu, dA0, 2);
    dA1 += __shfl_xor_sync(0xffffffffu, dA1, 1);
    dA1 += __shfl_xor_sync(0xffffffffu, dA1, 2);
    dB0 += __shfl_xor_sync(0xffffffffu, dB0, 1);
    dB0 += __shfl_xor_sync(0xffffffffu, dB0, 2);
    dB1 += __shfl_xor_sync(0xffffffffu, dB1, 1);
    dB1 += __shfl_xor_sync(0xffffffffu, dB1, 2);
    float npad = (float)(ntile * 64 - (kvend - kv0));
    dA0 -= npad; dA1 -= npad; dB0 -= npad; dB1 -= npad;

    if (tig == 0) {
        if (rowA0 < B) g_den[l][split][rowA0] = dA0;
        if (rowA1 < B) g_den[l][split][rowA1] = dA1;
        if (rowB0 < B) g_den[l][split][rowB0] = dB0;
        if (rowB1 < B) g_den[l][split][rowB1] = dB1;
    }
    #pragma unroll
    for (int j = 0; j < 8; j++) {
        int c = 8 * j + 2 * tig;
        if (rowA0 < B) {
            g_num[l][split][rowA0 * 64 + c]     = oA[j][0];
            g_num[l][split][rowA0 * 64 + c + 1] = oA[j][1];
        }
        if (rowA1 < B) {
            g_num[l][split][rowA1 * 64 + c]     = oA[j][2];
            g_num[l][split][rowA1 * 64 + c + 1] = oA[j][3];
        }
        if (rowB0 < B) {
            g_num[l][split][rowB0 * 64 + c]     = oB[j][0];
            g_num[l][split][rowB0 * 64 + c + 1] = oB[j][1];
        }
        if (rowB1 < B) {
            g_num[l][split][rowB1 * 64 + c]     = oB[j][2];
            g_num[l][split][rowB1 * 64 + c + 1] = oB[j][3];
        }
    }
}

// ---------------- kernel 5: combine + epilogue ----------------
__global__ void __launch_bounds__(256) epilogue_kernel(
    const float* __restrict__ uW1, const float* __restrict__ uW2,
    const float* __restrict__ iW1, const float* __restrict__ iW2, int B)
{
    int l = blockIdx.y;
    const float* W1 = (l == 0) ? uW1 : iW1;
    const float* W2 = (l == 0) ? uW2 : iW2;

    __shared__ float sW1[64 * 68];
    __shared__ float sW2[64 * 68];
    __shared__ float sS[64];
    __shared__ float st1[16 * 64];
    __shared__ float st2[16 * 64];
    __shared__ float sden[16];

    int tid = threadIdx.x;
    for (int e = tid; e < 64 * 64; e += 256) {
        int o = e >> 6, d = e & 63;
        sW1[o * 68 + d] = W1[e];
        sW2[o * 68 + d] = W2[e];
    }
    if (tid < 64) sS[tid] = g_S[l][tid];

    int r0 = blockIdx.x * 16;
    if (tid < 16) {
        float dsum = 0.f;
        #pragma unroll
        for (int s = 0; s < NSPLIT; s++) dsum += g_den[l][s][r0 + tid];
        sden[tid] = dsum;
    }
    __syncthreads();

    for (int e = tid; e < 16 * 64; e += 256) {
        int rl = e >> 6, d = e & 63;
        int r = r0 + rl;
        float nsum = 0.f;
        #pragma unroll
        for (int s = 0; s < NSPLIT; s++) nsum += g_num[l][s][r * 64 + d];
        float q  = g_q[l][r * 64 + d];
        float q2 = q + nsum / sden[rl];
        st1[e] = q2 + sS[d];
        st2[e] = q2 * sS[d];
        g_og[l][r * 128 + d] = q;
    }
    __syncthreads();

    int o = tid & 63, rl0 = tid >> 6;
    for (int rl = rl0; rl < 16; rl += 4) {
        float acc = 0.f;
        const float4* t1 = (const float4*)&st1[rl * 64];
        const float4* t2 = (const float4*)&st2[rl * 64];
        const float4* w1 = (const float4*)&sW1[o * 68];
        const float4* w2 = (const float4*)&sW2[o * 68];
        #pragma unroll
        for (int d4 = 0; d4 < 16; d4++) {
            float4 a = t1[d4], b = w1[d4], c = t2[d4], e4 = w2[d4];
            acc += a.x*b.x + a.y*b.y + a.z*b.z + a.w*b.w
                 + c.x*e4.x + c.y*e4.y + c.z*e4.z + c.w*e4.w;
        }
        float out = (acc > 0.f) ? acc : 0.01f * acc;
        g_og[l][(r0 + rl) * 128 + 64 + o] = out;
    }
}

// ---------------- kernel 6: final 128x128 GEMM ----------------
__global__ void __launch_bounds__(256) final_kernel(float* __restrict__ out, int B) {
    int bi = blockIdx.x & 7, bj = blockIdx.x >> 3;
    __shared__ float sU[64 * 16];
    __shared__ float sI[64 * 16];
    int tid = threadIdx.x;
    int ty = tid >> 4, tx = tid & 15;
    float acc = 0.f;
    for (int k0 = 0; k0 < B; k0 += 64) {
        __syncthreads();
        for (int e = tid; e < 64 * 16; e += 256) {
            int kk = e >> 4, c = e & 15;
            sU[e] = g_og[0][(k0 + kk) * 128 + bi * 16 + c];
            sI[e] = g_og[1][(k0 + kk) * 128 + bj * 16 + c];
        }
        __syncthreads();
        #pragma unroll
        for (int kk = 0; kk < 64; kk++)
            acc += sU[kk * 16 + ty] * sI[kk * 16 + tx];
    }
    out[(bi * 16 + ty) * 128 + bj * 16 + tx] = acc;
}

// ---------------- launch ----------------
extern "C" void kernel_launch(void* const* d_in, const int* in_sizes, int n_in,
                              void* d_out, int out_size) {
    const float* user_emb  = (const float*)d_in[0];
    const float* item_emb  = (const float*)d_in[1];
    const float* u_attn_W  = (const float*)d_in[2];
    const float* u_attn_b  = (const float*)d_in[3];
    const float* u_W1      = (const float*)d_in[4];
    const float* u_W2      = (const float*)d_in[5];
    const float* i_attn_W  = (const float*)d_in[6];
    const float* i_attn_b  = (const float*)d_in[7];
    const float* i_W1      = (const float*)d_in[8];
    const float* i_W2      = (const float*)d_in[9];
    const int*   user_id   = (const int*)d_in[10];
    const int*   item_id   = (const int*)d_in[11];
    const int*   all_user_ids = (const int*)d_in[12];
    const int*   all_item_ids = (const int*)d_in[13];

    int B  = in_sizes[10]; if (B > BMAX) B = BMAX;
    int Nu = in_sizes[12]; if (Nu > NMAX) Nu = NMAX;
    int Ni = in_sizes[13]; if (Ni > NMAX) Ni = NMAX;
    float* out = (float*)d_out;

    zero_kernel<<<1, 128>>>();
    hidden_kernel<<<dim3(148, 2), 256>>>(user_emb, item_emb, all_user_ids, all_item_ids,
                                         u_attn_W, u_attn_b, i_attn_W, i_attn_b, Ni, Nu);
    int total = B * 64;
    gather_q_kernel<<<(2 * total + 255) / 256, 256>>>(user_emb, item_emb, user_id, item_id,
                                                      all_user_ids, all_item_ids, B);
    int qblocks = (B + 127) / 128;   // CTA covers 128 query rows (4 warps x 32)
    flash_kernel<<<dim3(qblocks, NSPLIT, 2), 128>>>(B, Ni, Nu);
    epilogue_kernel<<<dim3(B / 16, 2), 256>>>(u_W1, u_W2, i_W1, i_W2, B);
    final_kernel<<<64, 256>>>(out, B);
}

// round 14
// speedup vs baseline: 4.1726x; 1.0617x over previous
#include <cuda_runtime.h>
#include <cuda_bf16.h>
#include <cuda_fp16.h>
#include <cstdint>

#define NMAX   100000
#define NPADH  (NMAX + 128)
#define BMAX   2048
#define NSPLIT 9

// ---------------- scratch (zero-initialized device globals; padding never written) -------
__device__ __align__(16) __nv_bfloat16 g_hidden_bf[2][NPADH * 64]; // [key][dim] bf16
__device__ __align__(16) __half        g_keys16[2][NPADH * 64];    // [key][dim] f16
__device__ float g_S[2][64];
__device__ float g_q[2][BMAX * 64];
__device__ __align__(16) __nv_bfloat16 g_qbf[2][BMAX * 64];        // Q * log2(e), bf16
__device__ float g_num[2][NSPLIT][BMAX * 64];
__device__ float g_den[2][NSPLIT][BMAX];
__device__ float g_og[2][BMAX * 128];

// ---------------- helpers ----------------
__device__ __forceinline__ uint32_t smem_u32(const void* p) {
    return (uint32_t)__cvta_generic_to_shared(p);
}
__device__ __forceinline__ uint32_t pack_bf2(float lo, float hi) {
    __nv_bfloat162 h = __floats2bfloat162_rn(lo, hi);
    return *reinterpret_cast<uint32_t*>(&h);
}
__device__ __forceinline__ uint32_t pack_h2(float lo, float hi) {
    __half2 h = __floats2half2_rn(lo, hi);
    return *reinterpret_cast<uint32_t*>(&h);
}
__device__ __forceinline__ void mma16816(float c[4],
                                         uint32_t a0, uint32_t a1, uint32_t a2, uint32_t a3,
                                         uint32_t b0, uint32_t b1) {
    asm volatile(
        "mma.sync.aligned.m16n8k16.row.col.f32.bf16.bf16.f32 "
        "{%0,%1,%2,%3}, {%4,%5,%6,%7}, {%8,%9}, {%0,%1,%2,%3};"
        : "+f"(c[0]), "+f"(c[1]), "+f"(c[2]), "+f"(c[3])
        : "r"(a0), "r"(a1), "r"(a2), "r"(a3), "r"(b0), "r"(b1));
}
__device__ __forceinline__ void mma16816h(float c[4],
                                          uint32_t a0, uint32_t a1, uint32_t a2, uint32_t a3,
                                          uint32_t b0, uint32_t b1) {
    asm volatile(
        "mma.sync.aligned.m16n8k16.row.col.f32.f16.f16.f32 "
        "{%0,%1,%2,%3}, {%4,%5,%6,%7}, {%8,%9}, {%0,%1,%2,%3};"
        : "+f"(c[0]), "+f"(c[1]), "+f"(c[2]), "+f"(c[3])
        : "r"(a0), "r"(a1), "r"(a2), "r"(a3), "r"(b0), "r"(b1));
}
__device__ __forceinline__ void ldsm_x4(uint32_t& d0, uint32_t& d1, uint32_t& d2, uint32_t& d3,
                                        uint32_t a) {
    asm volatile("ldmatrix.sync.aligned.m8n8.x4.shared.b16 {%0,%1,%2,%3}, [%4];"
                 : "=r"(d0), "=r"(d1), "=r"(d2), "=r"(d3) : "r"(a));
}
__device__ __forceinline__ void ldsm_x4t(uint32_t& d0, uint32_t& d1, uint32_t& d2, uint32_t& d3,
                                         uint32_t a) {
    asm volatile("ldmatrix.sync.aligned.m8n8.x4.trans.shared.b16 {%0,%1,%2,%3}, [%4];"
                 : "=r"(d0), "=r"(d1), "=r"(d2), "=r"(d3) : "r"(a));
}
__device__ __forceinline__ void cp16(uint32_t saddr, const void* g) {
    asm volatile("cp.async.cg.shared.global [%0], [%1], 16;" :: "r"(saddr), "l"(g));
}
#define CP_COMMIT() asm volatile("cp.async.commit_group;" ::: "memory")
#define CP_WAIT1()  asm volatile("cp.async.wait_group 1;" ::: "memory")
#define CP_WAIT0()  asm volatile("cp.async.wait_group 0;" ::: "memory")

__device__ __forceinline__ uint32_t ex2_h2(uint32_t x) {
    uint32_t r;
    asm("ex2.approx.f16x2 %0, %1;" : "=r"(r) : "r"(x));
    return r;
}
__device__ __forceinline__ uint32_t hadd2u(uint32_t a, uint32_t b) {
    __half2 r = __hadd2(*reinterpret_cast<__half2*>(&a), *reinterpret_cast<__half2*>(&b));
    return *reinterpret_cast<uint32_t*>(&r);
}
__device__ __forceinline__ float h2sum_f32(uint32_t a) {
    __half2 h = *reinterpret_cast<__half2*>(&a);
    return __low2float(h) + __high2float(h);
}

// ---------------- kernel 1 ----------------
__global__ void zero_kernel() {
    int t = threadIdx.x;
    if (t < 128) ((float*)g_S)[t] = 0.f;
}

// ---------------- kernel 2: hidden (mma.sync bf16) + keys f16 row-major + S --------------
__global__ void __launch_bounds__(256) hidden_kernel(
    const float* __restrict__ user_emb, const float* __restrict__ item_emb,
    const int* __restrict__ all_user_ids, const int* __restrict__ all_item_ids,
    const float* __restrict__ uW, const float* __restrict__ ub,
    const float* __restrict__ iW, const float* __restrict__ ib,
    int Ni, int Nu)
{
    int l = blockIdx.y;
    const float* emb = (l == 0) ? item_emb : user_emb;
    const int*   ids = (l == 0) ? all_item_ids : all_user_ids;
    const float* W   = (l == 0) ? uW : iW;
    const float* bb  = (l == 0) ? ub : ib;
    int Nk = (l == 0) ? Ni : Nu;

    __shared__ __nv_bfloat16 sW[64 * 72];
    __shared__ __nv_bfloat16 sK[128 * 72];
    __shared__ float sSum[8][64];
    __shared__ float sB[64];

    int tid = threadIdx.x, lane = tid & 31, warp = tid >> 5;
    for (int e = tid; e < 64 * 64; e += 256) {
        int o = e >> 6, d = e & 63;
        sW[o * 72 + d] = __float2bfloat16(W[e]);
    }
    if (tid < 64) sB[tid] = bb[tid];

    int c4 = lane & 15, r0 = lane >> 4;
    float4 csum = make_float4(0.f, 0.f, 0.f, 0.f);

    int ntiles = (Nk + 127) >> 7;
    for (int t = blockIdx.x; t < ntiles; t += gridDim.x) {
        int base = t << 7;
        __syncthreads();
        #pragma unroll
        for (int k = 0; k < 8; k++) {
            int rl = warp * 16 + r0 + 2 * k;
            int j = base + rl;
            float4 v = make_float4(0.f, 0.f, 0.f, 0.f);
            if (j < Nk) v = *(const float4*)&emb[(size_t)ids[j] * 64 + c4 * 4];
            csum.x += v.x; csum.y += v.y; csum.z += v.z; csum.w += v.w;
            uint2 u; u.x = pack_bf2(v.x, v.y); u.y = pack_bf2(v.z, v.w);
            *(uint2*)&sK[rl * 72 + c4 * 4] = u;
            if (j < Nk) {
                uint2 w; w.x = pack_h2(v.x, v.y); w.y = pack_h2(v.z, v.w);
                *(uint2*)&g_keys16[l][(size_t)j * 64 + c4 * 4] = w;
            }
        }
        __syncthreads();
        uint32_t afr[4][4];
        #pragma unroll
        for (int kk = 0; kk < 4; kk++) {
            uint32_t a = smem_u32(&sK[(warp * 16 + (lane & 15)) * 72 + kk * 16 + (lane >> 4) * 8]);
            ldsm_x4(afr[kk][0], afr[kk][1], afr[kk][2], afr[kk][3], a);
        }
        int gid = lane >> 2, tig = lane & 3;
        int row0 = base + warp * 16 + gid, row1 = row0 + 8;
        #pragma unroll
        for (int j = 0; j < 8; j++) {
            float acc[4] = {0.f, 0.f, 0.f, 0.f};
            uint32_t b0, b1, b2, b3, b4, b5, b6, b7;
            uint32_t a = smem_u32(&sW[(8 * j + (lane & 7)) * 72 + (lane >> 3) * 8]);
            ldsm_x4(b0, b1, b2, b3, a);
            ldsm_x4(b4, b5, b6, b7, a + 32 * 2);
            mma16816(acc, afr[0][0], afr[0][1], afr[0][2], afr[0][3], b0, b1);
            mma16816(acc, afr[1][0], afr[1][1], afr[1][2], afr[1][3], b2, b3);
            mma16816(acc, afr[2][0], afr[2][1], afr[2][2], afr[2][3], b4, b5);
            mma16816(acc, afr[3][0], afr[3][1], afr[3][2], afr[3][3], b6, b7);
            int c = 8 * j + 2 * tig;
            float bz0 = sB[c], bz1 = sB[c + 1];
            if (row0 < Nk)
                *(uint32_t*)&g_hidden_bf[l][(size_t)row0 * 64 + c] =
                    pack_bf2(fmaxf(acc[0] + bz0, 0.f), fmaxf(acc[1] + bz1, 0.f));
            if (row1 < Nk)
                *(uint32_t*)&g_hidden_bf[l][(size_t)row1 * 64 + c] =
                    pack_bf2(fmaxf(acc[2] + bz0, 0.f), fmaxf(acc[3] + bz1, 0.f));
        }
    }
    csum.x += __shfl_xor_sync(0xffffffffu, csum.x, 16);
    csum.y += __shfl_xor_sync(0xffffffffu, csum.y, 16);
    csum.z += __shfl_xor_sync(0xffffffffu, csum.z, 16);
    csum.w += __shfl_xor_sync(0xffffffffu, csum.w, 16);
    if (lane < 16) *(float4*)&sSum[warp][c4 * 4] = csum;
    __syncthreads();
    if (tid < 64) {
        float s = 0.f;
        #pragma unroll
        for (int w = 0; w < 8; w++) s += sSum[w][tid];
        atomicAdd(&g_S[l][tid], s);
    }
}

// ---------------- kernel 3: gather queries (bf16 copy scaled by log2e) ----------------
__global__ void gather_q_kernel(
    const float* __restrict__ user_emb, const float* __restrict__ item_emb,
    const int* __restrict__ user_id, const int* __restrict__ item_id,
    const int* __restrict__ all_user_ids, const int* __restrict__ all_item_ids, int B)
{
    int idx = blockIdx.x * blockDim.x + threadIdx.x;
    int total = B * 64;
    if (idx < 2 * total) {
        int l = idx / total;
        int e = idx - l * total;
        int b = e >> 6, d = e & 63;
        float v;
        if (l == 0) v = user_emb[(size_t)all_user_ids[user_id[b]] * 64 + d];
        else        v = item_emb[(size_t)all_item_ids[item_id[b]] * 64 + d];
        g_q[l][e]   = v;
        g_qbf[l][e] = __float2bfloat16(v * 1.4426950408889634f);  // log2(e)
    }
}

// ---------------- kernel 4: flash attention (cross-tile software pipeline) --------------
// tile = 64 rows x 128 bytes, XOR-swizzled 16B chunks: phys_chunk = ch ^ (row & 7)
#define TILE_B 8192

__device__ __forceinline__ void load_tiles(const __nv_bfloat16* __restrict__ Hs,
                                           const __half* __restrict__ Vs,
                                           uint32_t sHb, uint32_t sVb,
                                           int kv, int tid)
{
    #pragma unroll
    for (int i = 0; i < 4; i++) {
        int c = tid + i * 128;
        int row = c >> 3, ch = c & 7;
        uint32_t off = (uint32_t)(row * 128 + ((ch ^ (row & 7)) << 4));
        cp16(sHb + off, Hs + (size_t)(kv + row) * 64 + ch * 8);
        cp16(sVb + off, Vs + (size_t)(kv + row) * 64 + ch * 8);
    }
}

// QK for one tile: S = Q @ H^T (both m16 halves), packed to f16x2 (pre-ex2) in sp arrays
__device__ __forceinline__ void qk_tile(uint32_t hb, int lm_r, int lm_m,
                                        const uint32_t qaA[4][4], const uint32_t qaB[4][4],
                                        uint32_t spAlo[8], uint32_t spAhi[8],
                                        uint32_t spBlo[8], uint32_t spBhi[8])
{
    #pragma unroll
    for (int j = 0; j < 8; j++) {
        uint32_t hb0, hb1, hb2, hb3, hb4, hb5, hb6, hb7;
        uint32_t rowoff = hb + (uint32_t)((8 * j + lm_r) * 128);
        ldsm_x4(hb0, hb1, hb2, hb3, rowoff + (uint32_t)(( lm_m      ^ lm_r) << 4));
        ldsm_x4(hb4, hb5, hb6, hb7, rowoff + (uint32_t)(((lm_m + 4) ^ lm_r) << 4));
        float sA[4] = {0.f, 0.f, 0.f, 0.f};
        mma16816(sA, qaA[0][0], qaA[0][1], qaA[0][2], qaA[0][3], hb0, hb1);
        mma16816(sA, qaA[1][0], qaA[1][1], qaA[1][2], qaA[1][3], hb2, hb3);
        mma16816(sA, qaA[2][0], qaA[2][1], qaA[2][2], qaA[2][3], hb4, hb5);
        mma16816(sA, qaA[3][0], qaA[3][1], qaA[3][2], qaA[3][3], hb6, hb7);
        float sB[4] = {0.f, 0.f, 0.f, 0.f};
        mma16816(sB, qaB[0][0], qaB[0][1], qaB[0][2], qaB[0][3], hb0, hb1);
        mma16816(sB, qaB[1][0], qaB[1][1], qaB[1][2], qaB[1][3], hb2, hb3);
        mma16816(sB, qaB[2][0], qaB[2][1], qaB[2][2], qaB[2][3], hb4, hb5);
        mma16816(sB, qaB[3][0], qaB[3][1], qaB[3][2], qaB[3][3], hb6, hb7);
        spAlo[j] = pack_h2(sA[0], sA[1]);
        spAhi[j] = pack_h2(sA[2], sA[3]);
        spBlo[j] = pack_h2(sB[0], sB[1]);
        spBhi[j] = pack_h2(sB[2], sB[3]);
    }
}

__global__ void __launch_bounds__(128, 2) flash_kernel(int B, int Ni, int Nu) {
    int l  = blockIdx.z;
    int Nk = (l == 0) ? Ni : Nu;
    int qb = blockIdx.x, split = blockIdx.y;

    const __nv_bfloat16* __restrict__ Hs = g_hidden_bf[l];
    const __half* __restrict__ Vs = g_keys16[l];
    const __nv_bfloat16* __restrict__ Qs = g_qbf[l];

    __shared__ __align__(128) unsigned char sH[3][TILE_B];
    __shared__ __align__(128) unsigned char sV[3][TILE_B];

    int tid = threadIdx.x, lane = tid & 31, warp = tid >> 5;   // 4 warps
    int gid = lane >> 2, tig = lane & 3;
    int lm_r = lane & 7, lm_m = lane >> 3;

    int rowA0 = qb * 128 + warp * 32 + gid;
    int rowA1 = rowA0 + 8;
    int rowB0 = rowA0 + 16;
    int rowB1 = rowA0 + 24;

    uint32_t qaA[4][4], qaB[4][4];
    #pragma unroll
    for (int kk = 0; kk < 4; kk++) {
        int kc = kk * 16 + 2 * tig;
        qaA[kk][0] = (rowA0 < B) ? *(const uint32_t*)&Qs[(size_t)rowA0 * 64 + kc]     : 0u;
        qaA[kk][1] = (rowA1 < B) ? *(const uint32_t*)&Qs[(size_t)rowA1 * 64 + kc]     : 0u;
        qaA[kk][2] = (rowA0 < B) ? *(const uint32_t*)&Qs[(size_t)rowA0 * 64 + kc + 8] : 0u;
        qaA[kk][3] = (rowA1 < B) ? *(const uint32_t*)&Qs[(size_t)rowA1 * 64 + kc + 8] : 0u;
        qaB[kk][0] = (rowB0 < B) ? *(const uint32_t*)&Qs[(size_t)rowB0 * 64 + kc]     : 0u;
        qaB[kk][1] = (rowB1 < B) ? *(const uint32_t*)&Qs[(size_t)rowB1 * 64 + kc]     : 0u;
        qaB[kk][2] = (rowB0 < B) ? *(const uint32_t*)&Qs[(size_t)rowB0 * 64 + kc + 8] : 0u;
        qaB[kk][3] = (rowB1 < B) ? *(const uint32_t*)&Qs[(size_t)rowB1 * 64 + kc + 8] : 0u;
    }

    int ntiles_all = (Nk + 63) >> 6;
    int tiles_per  = (ntiles_all + NSPLIT - 1) / NSPLIT;
    int chunk = tiles_per << 6;
    int kv0   = split * chunk;
    int kvend = min(kv0 + chunk, Nk);
    int ntile = (kvend > kv0) ? ((kvend - kv0 + 63) >> 6) : 0;

    float oA[8][4], oB[8][4];
    #pragma unroll
    for (int j = 0; j < 8; j++)
        #pragma unroll
        for (int q = 0; q < 4; q++) { oA[j][q] = 0.f; oB[j][q] = 0.f; }
    float dA0 = 0.f, dA1 = 0.f, dB0 = 0.f, dB1 = 0.f;

    uint32_t scAlo[8], scAhi[8], scBlo[8], scBhi[8];   // s (packed f16x2) for current tile
    uint32_t snAlo[8], snAhi[8], snBlo[8], snBhi[8];   // s for next tile

    // prologue: load tiles 0,1; QK(0)
    if (ntile > 0) load_tiles(Hs, Vs, smem_u32(sH[0]), smem_u32(sV[0]), kv0, tid);
    CP_COMMIT();
    if (ntile > 1) load_tiles(Hs, Vs, smem_u32(sH[1]), smem_u32(sV[1]), kv0 + 64, tid);
    CP_COMMIT();
    if (ntile > 0) {
        CP_WAIT1();
        __syncthreads();
        qk_tile(smem_u32(sH[0]), lm_r, lm_m, qaA, qaB, scAlo, scAhi, scBlo, scBhi);
    }

    for (int t = 0; t < ntile; t++) {
        CP_WAIT0();          // all issued loads done: tiles t and t+1 resident
        __syncthreads();     // visible to all threads; stage (t+2)%3 has no pending readers

        if (t + 2 < ntile) {
            int st = (t + 2) % 3;
            load_tiles(Hs, Vs, smem_u32(sH[st]), smem_u32(sV[st]), kv0 + (t + 2) * 64, tid);
        }
        CP_COMMIT();

        // ---- QK(t+1) -> sn (independent tensor work; fills stall gaps below) ----
        if (t + 1 < ntile)
            qk_tile(smem_u32(sH[(t + 1) % 3]), lm_r, lm_m, qaA, qaB,
                    snAlo, snAhi, snBlo, snBhi);

        // ---- exp(t): p = 2^s (in place on sc) + den trees ----
        #pragma unroll
        for (int j = 0; j < 8; j++) {
            scAlo[j] = ex2_h2(scAlo[j]);
            scAhi[j] = ex2_h2(scAhi[j]);
            scBlo[j] = ex2_h2(scBlo[j]);
            scBhi[j] = ex2_h2(scBhi[j]);
        }
        dA0 += h2sum_f32(hadd2u(hadd2u(hadd2u(scAlo[0], scAlo[1]), hadd2u(scAlo[2], scAlo[3])),
                                hadd2u(hadd2u(scAlo[4], scAlo[5]), hadd2u(scAlo[6], scAlo[7]))));
        dA1 += h2sum_f32(hadd2u(hadd2u(hadd2u(scAhi[0], scAhi[1]), hadd2u(scAhi[2], scAhi[3])),
                                hadd2u(hadd2u(scAhi[4], scAhi[5]), hadd2u(scAhi[6], scAhi[7]))));
        dB0 += h2sum_f32(hadd2u(hadd2u(hadd2u(scBlo[0], scBlo[1]), hadd2u(scBlo[2], scBlo[3])),
                                hadd2u(hadd2u(scBlo[4], scBlo[5]), hadd2u(scBlo[6], scBlo[7]))));
        dB1 += h2sum_f32(hadd2u(hadd2u(hadd2u(scBhi[0], scBhi[1]), hadd2u(scBhi[2], scBhi[3])),
                                hadd2u(hadd2u(scBhi[4], scBhi[5]), hadd2u(scBhi[6], scBhi[7]))));

        // ---- PV(t): O += P @ V (V row-major, trans-ldsm B-frags) ----
        uint32_t vb = smem_u32(sV[t % 3]);
        #pragma unroll
        for (int kk = 0; kk < 4; kk++) {
            uint32_t aA0 = scAlo[2 * kk], aA1 = scAhi[2 * kk];
            uint32_t aA2 = scAlo[2 * kk + 1], aA3 = scAhi[2 * kk + 1];
            uint32_t aB0 = scBlo[2 * kk], aB1 = scBhi[2 * kk];
            uint32_t aB2 = scBlo[2 * kk + 1], aB3 = scBhi[2 * kk + 1];
            int vrow = 16 * kk + (lm_m & 1) * 8 + lm_r;   // vrow & 7 == lm_r
            uint32_t rowoff = vb + (uint32_t)(vrow * 128);
            #pragma unroll
            for (int j0 = 0; j0 < 8; j0 += 2) {
                int ch = j0 + (lm_m >> 1);
                uint32_t v0, v1, v2, v3;
                ldsm_x4t(v0, v1, v2, v3, rowoff + (uint32_t)((ch ^ lm_r) << 4));
                mma16816h(oA[j0],     aA0, aA1, aA2, aA3, v0, v1);
                mma16816h(oA[j0 + 1], aA0, aA1, aA2, aA3, v2, v3);
                mma16816h(oB[j0],     aB0, aB1, aB2, aB3, v0, v1);
                mma16816h(oB[j0 + 1], aB0, aB1, aB2, aB3, v2, v3);
            }
        }

        // rotate s buffers
        #pragma unroll
        for (int j = 0; j < 8; j++) {
            scAlo[j] = snAlo[j]; scAhi[j] = snAhi[j];
            scBlo[j] = snBlo[j]; scBhi[j] = snBhi[j];
        }
    }

    // reduce den across the 4 lanes sharing a row; subtract exact padding count
    dA0 += __shfl_xor_sync(0xffffffffu, dA0, 1);
    dA0 += __shfl_xor_sync(0xffffffffu, dA0, 2);
    dA1 += __shfl_xor_sync(0xffffffffu, dA1, 1);
    dA1 += __shfl_xor_sync(0xffffffffu, dA1, 2);
    dB0 += __shfl_xor_sync(0xffffffffu, dB0, 1);
    dB0 += __shfl_xor_sync(0xffffffffu, dB0, 2);
    dB1 += __shfl_xor_sync(0xffffffffu, dB1, 1);
    dB1 += __shfl_xor_sync(0xffffffffu, dB1, 2);
    float npad = (float)(ntile * 64 - (kvend - kv0));
    dA0 -= npad; dA1 -= npad; dB0 -= npad; dB1 -= npad;

    if (tig == 0) {
        if (rowA0 < B) g_den[l][split][rowA0] = dA0;
        if (rowA1 < B) g_den[l][split][rowA1] = dA1;
        if (rowB0 < B) g_den[l][split][rowB0] = dB0;
        if (rowB1 < B) g_den[l][split][rowB1] = dB1;
    }
    #pragma unroll
    for (int j = 0; j < 8; j++) {
        int c = 8 * j + 2 * tig;
        if (rowA0 < B) {
            g_num[l][split][rowA0 * 64 + c]     = oA[j][0];
            g_num[l][split][rowA0 * 64 + c + 1] = oA[j][1];
        }
        if (rowA1 < B) {
            g_num[l][split][rowA1 * 64 + c]     = oA[j][2];
            g_num[l][split][rowA1 * 64 + c + 1] = oA[j][3];
        }
        if (rowB0 < B) {
            g_num[l][split][rowB0 * 64 + c]     = oB[j][0];
            g_num[l][split][rowB0 * 64 + c + 1] = oB[j][1];
        }
        if (rowB1 < B) {
            g_num[l][split][rowB1 * 64 + c]     = oB[j][2];
            g_num[l][split][rowB1 * 64 + c + 1] = oB[j][3];
        }
    }
}

// ---------------- kernel 5: combine + epilogue ----------------
__global__ void __launch_bounds__(256) epilogue_kernel(
    const float* __restrict__ uW1, const float* __restrict__ uW2,
    const float* __restrict__ iW1, const float* __restrict__ iW2, int B)
{
    int l = blockIdx.y;
    const float* W1 = (l == 0) ? uW1 : iW1;
    const float* W2 = (l == 0) ? uW2 : iW2;

    __shared__ float sW1[64 * 68];
    __shared__ float sW2[64 * 68];
    __shared__ float sS[64];
    __shared__ float st1[16 * 64];
    __shared__ float st2[16 * 64];
    __shared__ float sden[16];

    int tid = threadIdx.x;
    for (int e = tid; e < 64 * 64; e += 256) {
        int o = e >> 6, d = e & 63;
        sW1[o * 68 + d] = W1[e];
        sW2[o * 68 + d] = W2[e];
    }
    if (tid < 64) sS[tid] = g_S[l][tid];

    int r0 = blockIdx.x * 16;
    if (tid < 16) {
        float dsum = 0.f;
        #pragma unroll
        for (int s = 0; s < NSPLIT; s++) dsum += g_den[l][s][r0 + tid];
        sden[tid] = dsum;
    }
    __syncthreads();

    for (int e = tid; e < 16 * 64; e += 256) {
        int rl = e >> 6, d = e & 63;
        int r = r0 + rl;
        float nsum = 0.f;
        #pragma unroll
        for (int s = 0; s < NSPLIT; s++) nsum += g_num[l][s][r * 64 + d];
        float q  = g_q[l][r * 64 + d];
        float q2 = q + nsum / sden[rl];
        st1[e] = q2 + sS[d];
        st2[e] = q2 * sS[d];
        g_og[l][r * 128 + d] = q;
    }
    __syncthreads();

    int o = tid & 63, rl0 = tid >> 6;
    for (int rl = rl0; rl < 16; rl += 4) {
        float acc = 0.f;
        const float4* t1 = (const float4*)&st1[rl * 64];
        const float4* t2 = (const float4*)&st2[rl * 64];
        const float4* w1 = (const float4*)&sW1[o * 68];
        const float4* w2 = (const float4*)&sW2[o * 68];
        #pragma unroll
        for (int d4 = 0; d4 < 16; d4++) {
            float4 a = t1[d4], b = w1[d4], c = t2[d4], e4 = w2[d4];
            acc += a.x*b.x + a.y*b.y + a.z*b.z + a.w*b.w
                 + c.x*e4.x + c.y*e4.y + c.z*e4.z + c.w*e4.w;
        }
        float out = (acc > 0.f) ? acc : 0.01f * acc;
        g_og[l][(r0 + rl) * 128 + 64 + o] = out;
    }
}

// ---------------- kernel 6: final 128x128 GEMM ----------------
__global__ void __launch_bounds__(256) final_kernel(float* __restrict__ out, int B) {
    int bi = blockIdx.x & 7, bj = blockIdx.x >> 3;
    __shared__ float sU[64 * 16];
    __shared__ float sI[64 * 16];
    int tid = threadIdx.x;
    int ty = tid >> 4, tx = tid & 15;
    float acc = 0.f;
    for (int k0 = 0; k0 < B; k0 += 64) {
        __syncthreads();
        for (int e = tid; e < 64 * 16; e += 256) {
            int kk = e >> 4, c = e & 15;
            sU[e] = g_og[0][(k0 + kk) * 128 + bi * 16 + c];
            sI[e] = g_og[1][(k0 + kk) * 128 + bj * 16 + c];
        }
        __syncthreads();
        #pragma unroll
        for (int kk = 0; kk < 64; kk++)
            acc += sU[kk * 16 + ty] * sI[kk * 16 + tx];
    }
    out[(bi * 16 + ty) * 128 + bj * 16 + tx] = acc;
}

// ---------------- launch ----------------
extern "C" void kernel_launch(void* const* d_in, const int* in_sizes, int n_in,
                              void* d_out, int out_size) {
    const float* user_emb  = (const float*)d_in[0];
    const float* item_emb  = (const float*)d_in[1];
    const float* u_attn_W  = (const float*)d_in[2];
    const float* u_attn_b  = (const float*)d_in[3];
    const float* u_W1      = (const float*)d_in[4];
    const float* u_W2      = (const float*)d_in[5];
    const float* i_attn_W  = (const float*)d_in[6];
    const float* i_attn_b  = (const float*)d_in[7];
    const float* i_W1      = (const float*)d_in[8];
    const float* i_W2      = (const float*)d_in[9];
    const int*   user_id   = (const int*)d_in[10];
    const int*   item_id   = (const int*)d_in[11];
    const int*   all_user_ids = (const int*)d_in[12];
    const int*   all_item_ids = (const int*)d_in[13];

    int B  = in_sizes[10]; if (B > BMAX) B = BMAX;
    int Nu = in_sizes[12]; if (Nu > NMAX) Nu = NMAX;
    int Ni = in_sizes[13]; if (Ni > NMAX) Ni = NMAX;
    float* out = (float*)d_out;

    zero_kernel<<<1, 128>>>();
    hidden_kernel<<<dim3(148, 2), 256>>>(user_emb, item_emb, all_user_ids, all_item_ids,
                                         u_attn_W, u_attn_b, i_attn_W, i_attn_b, Ni, Nu);
    int total = B * 64;
    gather_q_kernel<<<(2 * total + 255) / 256, 256>>>(user_emb, item_emb, user_id, item_id,
                                                      all_user_ids, all_item_ids, B);
    int qblocks = (B + 127) / 128;
    flash_kernel<<<dim3(qblocks, NSPLIT, 2), 128>>>(B, Ni, Nu);
    epilogue_kernel<<<dim3(B / 16, 2), 256>>>(u_W1, u_W2, i_W1, i_W2, B);
    final_kernel<<<64, 256>>>(out, B);
}

// round 15
// speedup vs baseline: 4.2633x; 1.0217x over previous
#include <cuda_runtime.h>
#include <cuda_bf16.h>
#include <cuda_fp16.h>
#include <cstdint>

#define NMAX   100000
#define NPADH  (NMAX + 128)
#define BMAX   2048
#define NSPLIT 9

// ---------------- scratch (zero-initialized device globals; padding never written) -------
__device__ __align__(16) __nv_bfloat16 g_hidden_bf[2][NPADH * 64]; // [key][dim] bf16
__device__ __align__(16) __half        g_keys16[2][NPADH * 64];    // [key][dim] f16
__device__ float g_S[2][64];
__device__ float g_q[2][BMAX * 64];
__device__ __align__(16) __nv_bfloat16 g_qbf[2][BMAX * 64];        // Q * log2(e), bf16
__device__ float g_num[2][NSPLIT][BMAX * 64];
__device__ float g_den[2][NSPLIT][BMAX];
__device__ float g_og[2][BMAX * 128];

// ---------------- helpers ----------------
__device__ __forceinline__ uint32_t smem_u32(const void* p) {
    return (uint32_t)__cvta_generic_to_shared(p);
}
__device__ __forceinline__ uint32_t pack_bf2(float lo, float hi) {
    __nv_bfloat162 h = __floats2bfloat162_rn(lo, hi);
    return *reinterpret_cast<uint32_t*>(&h);
}
__device__ __forceinline__ uint32_t pack_h2(float lo, float hi) {
    __half2 h = __floats2half2_rn(lo, hi);
    return *reinterpret_cast<uint32_t*>(&h);
}
__device__ __forceinline__ void mma16816(float c[4],
                                         uint32_t a0, uint32_t a1, uint32_t a2, uint32_t a3,
                                         uint32_t b0, uint32_t b1) {
    asm volatile(
        "mma.sync.aligned.m16n8k16.row.col.f32.bf16.bf16.f32 "
        "{%0,%1,%2,%3}, {%4,%5,%6,%7}, {%8,%9}, {%0,%1,%2,%3};"
        : "+f"(c[0]), "+f"(c[1]), "+f"(c[2]), "+f"(c[3])
        : "r"(a0), "r"(a1), "r"(a2), "r"(a3), "r"(b0), "r"(b1));
}
__device__ __forceinline__ void mma16816h(float c[4],
                                          uint32_t a0, uint32_t a1, uint32_t a2, uint32_t a3,
                                          uint32_t b0, uint32_t b1) {
    asm volatile(
        "mma.sync.aligned.m16n8k16.row.col.f32.f16.f16.f32 "
        "{%0,%1,%2,%3}, {%4,%5,%6,%7}, {%8,%9}, {%0,%1,%2,%3};"
        : "+f"(c[0]), "+f"(c[1]), "+f"(c[2]), "+f"(c[3])
        : "r"(a0), "r"(a1), "r"(a2), "r"(a3), "r"(b0), "r"(b1));
}
__device__ __forceinline__ void ldsm_x4(uint32_t& d0, uint32_t& d1, uint32_t& d2, uint32_t& d3,
                                        uint32_t a) {
    asm volatile("ldmatrix.sync.aligned.m8n8.x4.shared.b16 {%0,%1,%2,%3}, [%4];"
                 : "=r"(d0), "=r"(d1), "=r"(d2), "=r"(d3) : "r"(a));
}
__device__ __forceinline__ void ldsm_x4t(uint32_t& d0, uint32_t& d1, uint32_t& d2, uint32_t& d3,
                                         uint32_t a) {
    asm volatile("ldmatrix.sync.aligned.m8n8.x4.trans.shared.b16 {%0,%1,%2,%3}, [%4];"
                 : "=r"(d0), "=r"(d1), "=r"(d2), "=r"(d3) : "r"(a));
}
__device__ __forceinline__ void cp16(uint32_t saddr, const void* g) {
    asm volatile("cp.async.cg.shared.global [%0], [%1], 16;" :: "r"(saddr), "l"(g));
}
#define CP_COMMIT() asm volatile("cp.async.commit_group;" ::: "memory")
#define CP_WAIT0()  asm volatile("cp.async.wait_group 0;" ::: "memory")
#define CP_WAIT1()  asm volatile("cp.async.wait_group 1;" ::: "memory")

__device__ __forceinline__ uint32_t ex2_h2(uint32_t x) {
    uint32_t r;
    asm("ex2.approx.f16x2 %0, %1;" : "=r"(r) : "r"(x));
    return r;
}
__device__ __forceinline__ uint32_t hadd2u(uint32_t a, uint32_t b) {
    __half2 r = __hadd2(*reinterpret_cast<__half2*>(&a), *reinterpret_cast<__half2*>(&b));
    return *reinterpret_cast<uint32_t*>(&r);
}
__device__ __forceinline__ float h2sum_f32(uint32_t a) {
    __half2 h = *reinterpret_cast<__half2*>(&a);
    return __low2float(h) + __high2float(h);
}

// ---------------- kernel 1 ----------------
__global__ void zero_kernel() {
    int t = threadIdx.x;
    if (t < 128) ((float*)g_S)[t] = 0.f;
}

// ---------------- kernel 2: hidden (mma.sync bf16) + keys f16 row-major + S --------------
__global__ void __launch_bounds__(256) hidden_kernel(
    const float* __restrict__ user_emb, const float* __restrict__ item_emb,
    const int* __restrict__ all_user_ids, const int* __restrict__ all_item_ids,
    const float* __restrict__ uW, const float* __restrict__ ub,
    const float* __restrict__ iW, const float* __restrict__ ib,
    int Ni, int Nu)
{
    int l = blockIdx.y;
    const float* emb = (l == 0) ? item_emb : user_emb;
    const int*   ids = (l == 0) ? all_item_ids : all_user_ids;
    const float* W   = (l == 0) ? uW : iW;
    const float* bb  = (l == 0) ? ub : ib;
    int Nk = (l == 0) ? Ni : Nu;

    __shared__ __nv_bfloat16 sW[64 * 72];
    __shared__ __nv_bfloat16 sK[128 * 72];
    __shared__ float sSum[8][64];
    __shared__ float sB[64];

    int tid = threadIdx.x, lane = tid & 31, warp = tid >> 5;
    for (int e = tid; e < 64 * 64; e += 256) {
        int o = e >> 6, d = e & 63;
        sW[o * 72 + d] = __float2bfloat16(W[e]);
    }
    if (tid < 64) sB[tid] = bb[tid];

    int c4 = lane & 15, r0 = lane >> 4;
    float4 csum = make_float4(0.f, 0.f, 0.f, 0.f);

    int ntiles = (Nk + 127) >> 7;
    for (int t = blockIdx.x; t < ntiles; t += gridDim.x) {
        int base = t << 7;
        __syncthreads();
        #pragma unroll
        for (int k = 0; k < 8; k++) {
            int rl = warp * 16 + r0 + 2 * k;
            int j = base + rl;
            float4 v = make_float4(0.f, 0.f, 0.f, 0.f);
            if (j < Nk) v = *(const float4*)&emb[(size_t)ids[j] * 64 + c4 * 4];
            csum.x += v.x; csum.y += v.y; csum.z += v.z; csum.w += v.w;
            uint2 u; u.x = pack_bf2(v.x, v.y); u.y = pack_bf2(v.z, v.w);
            *(uint2*)&sK[rl * 72 + c4 * 4] = u;
            if (j < Nk) {
                uint2 w; w.x = pack_h2(v.x, v.y); w.y = pack_h2(v.z, v.w);
                *(uint2*)&g_keys16[l][(size_t)j * 64 + c4 * 4] = w;
            }
        }
        __syncthreads();
        uint32_t afr[4][4];
        #pragma unroll
        for (int kk = 0; kk < 4; kk++) {
            uint32_t a = smem_u32(&sK[(warp * 16 + (lane & 15)) * 72 + kk * 16 + (lane >> 4) * 8]);
            ldsm_x4(afr[kk][0], afr[kk][1], afr[kk][2], afr[kk][3], a);
        }
        int gid = lane >> 2, tig = lane & 3;
        int row0 = base + warp * 16 + gid, row1 = row0 + 8;
        #pragma unroll
        for (int j = 0; j < 8; j++) {
            float acc[4] = {0.f, 0.f, 0.f, 0.f};
            uint32_t b0, b1, b2, b3, b4, b5, b6, b7;
            uint32_t a = smem_u32(&sW[(8 * j + (lane & 7)) * 72 + (lane >> 3) * 8]);
            ldsm_x4(b0, b1, b2, b3, a);
            ldsm_x4(b4, b5, b6, b7, a + 32 * 2);
            mma16816(acc, afr[0][0], afr[0][1], afr[0][2], afr[0][3], b0, b1);
            mma16816(acc, afr[1][0], afr[1][1], afr[1][2], afr[1][3], b2, b3);
            mma16816(acc, afr[2][0], afr[2][1], afr[2][2], afr[2][3], b4, b5);
            mma16816(acc, afr[3][0], afr[3][1], afr[3][2], afr[3][3], b6, b7);
            int c = 8 * j + 2 * tig;
            float bz0 = sB[c], bz1 = sB[c + 1];
            if (row0 < Nk)
                *(uint32_t*)&g_hidden_bf[l][(size_t)row0 * 64 + c] =
                    pack_bf2(fmaxf(acc[0] + bz0, 0.f), fmaxf(acc[1] + bz1, 0.f));
            if (row1 < Nk)
                *(uint32_t*)&g_hidden_bf[l][(size_t)row1 * 64 + c] =
                    pack_bf2(fmaxf(acc[2] + bz0, 0.f), fmaxf(acc[3] + bz1, 0.f));
        }
    }
    csum.x += __shfl_xor_sync(0xffffffffu, csum.x, 16);
    csum.y += __shfl_xor_sync(0xffffffffu, csum.y, 16);
    csum.z += __shfl_xor_sync(0xffffffffu, csum.z, 16);
    csum.w += __shfl_xor_sync(0xffffffffu, csum.w, 16);
    if (lane < 16) *(float4*)&sSum[warp][c4 * 4] = csum;
    __syncthreads();
    if (tid < 64) {
        float s = 0.f;
        #pragma unroll
        for (int w = 0; w < 8; w++) s += sSum[w][tid];
        atomicAdd(&g_S[l][tid], s);
    }
}

// ---------------- kernel 3: gather queries (bf16 copy scaled by log2e) ----------------
__global__ void gather_q_kernel(
    const float* __restrict__ user_emb, const float* __restrict__ item_emb,
    const int* __restrict__ user_id, const int* __restrict__ item_id,
    const int* __restrict__ all_user_ids, const int* __restrict__ all_item_ids, int B)
{
    int idx = blockIdx.x * blockDim.x + threadIdx.x;
    int total = B * 64;
    if (idx < 2 * total) {
        int l = idx / total;
        int e = idx - l * total;
        int b = e >> 6, d = e & 63;
        float v;
        if (l == 0) v = user_emb[(size_t)all_user_ids[user_id[b]] * 64 + d];
        else        v = item_emb[(size_t)all_item_ids[item_id[b]] * 64 + d];
        g_q[l][e]   = v;
        g_qbf[l][e] = __float2bfloat16(v * 1.4426950408889634f);  // log2(e)
    }
}

// ---------------- kernel 4: flash attention (ping-pong cross-tile pipeline) -------------
// tile = 64 rows x 128 bytes, XOR-swizzled 16B chunks: phys_chunk = ch ^ (row & 7)
#define TILE_B 8192

__device__ __forceinline__ void load_tiles(const __nv_bfloat16* __restrict__ Hs,
                                           const __half* __restrict__ Vs,
                                           uint32_t sHb, uint32_t sVb,
                                           int kv, int tid)
{
    #pragma unroll
    for (int i = 0; i < 4; i++) {
        int c = tid + i * 128;
        int row = c >> 3, ch = c & 7;
        uint32_t off = (uint32_t)(row * 128 + ((ch ^ (row & 7)) << 4));
        cp16(sHb + off, Hs + (size_t)(kv + row) * 64 + ch * 8);
        cp16(sVb + off, Vs + (size_t)(kv + row) * 64 + ch * 8);
    }
}

// QK for one tile: S = Q @ H^T (both m16 halves), packed to f16x2 (pre-ex2)
__device__ __forceinline__ void qk_tile(uint32_t hb, int lm_r, int lm_m,
                                        const uint32_t qaA[4][4], const uint32_t qaB[4][4],
                                        uint32_t spAlo[8], uint32_t spAhi[8],
                                        uint32_t spBlo[8], uint32_t spBhi[8])
{
    #pragma unroll
    for (int j = 0; j < 8; j++) {
        uint32_t hb0, hb1, hb2, hb3, hb4, hb5, hb6, hb7;
        uint32_t rowoff = hb + (uint32_t)((8 * j + lm_r) * 128);
        ldsm_x4(hb0, hb1, hb2, hb3, rowoff + (uint32_t)(( lm_m      ^ lm_r) << 4));
        ldsm_x4(hb4, hb5, hb6, hb7, rowoff + (uint32_t)(((lm_m + 4) ^ lm_r) << 4));
        float sA[4] = {0.f, 0.f, 0.f, 0.f};
        mma16816(sA, qaA[0][0], qaA[0][1], qaA[0][2], qaA[0][3], hb0, hb1);
        mma16816(sA, qaA[1][0], qaA[1][1], qaA[1][2], qaA[1][3], hb2, hb3);
        mma16816(sA, qaA[2][0], qaA[2][1], qaA[2][2], qaA[2][3], hb4, hb5);
        mma16816(sA, qaA[3][0], qaA[3][1], qaA[3][2], qaA[3][3], hb6, hb7);
        float sB[4] = {0.f, 0.f, 0.f, 0.f};
        mma16816(sB, qaB[0][0], qaB[0][1], qaB[0][2], qaB[0][3], hb0, hb1);
        mma16816(sB, qaB[1][0], qaB[1][1], qaB[1][2], qaB[1][3], hb2, hb3);
        mma16816(sB, qaB[2][0], qaB[2][1], qaB[2][2], qaB[2][3], hb4, hb5);
        mma16816(sB, qaB[3][0], qaB[3][1], qaB[3][2], qaB[3][3], hb6, hb7);
        spAlo[j] = pack_h2(sA[0], sA[1]);
        spAhi[j] = pack_h2(sA[2], sA[3]);
        spBlo[j] = pack_h2(sB[0], sB[1]);
        spBhi[j] = pack_h2(sB[2], sB[3]);
    }
}

// One pipeline step for tile t: consume sc (raw S), produce sn = S(t+1).
__device__ __forceinline__ void flash_step(
    int t, int ntile, int kv0, int tid, int lm_r, int lm_m,
    const __nv_bfloat16* __restrict__ Hs, const __half* __restrict__ Vs,
    unsigned char (*sH)[TILE_B], unsigned char (*sV)[TILE_B],
    const uint32_t qaA[4][4], const uint32_t qaB[4][4],
    uint32_t scAlo[8], uint32_t scAhi[8], uint32_t scBlo[8], uint32_t scBhi[8],
    uint32_t snAlo[8], uint32_t snAhi[8], uint32_t snBlo[8], uint32_t snBhi[8],
    float oA[8][4], float oB[8][4], float den[4])
{
    CP_WAIT0();
    __syncthreads();   // tiles t, t+1 visible; stage (t+2)%3 free of readers

    if (t + 2 < ntile) {
        int st = (t + 2) % 3;
        load_tiles(Hs, Vs, smem_u32(sH[st]), smem_u32(sV[st]), kv0 + (t + 2) * 64, tid);
    }
    CP_COMMIT();

    // exp(t): p = 2^s in place (critical path into PV)
    #pragma unroll
    for (int j = 0; j < 8; j++) {
        scAlo[j] = ex2_h2(scAlo[j]);
        scAhi[j] = ex2_h2(scAhi[j]);
        scBlo[j] = ex2_h2(scBlo[j]);
        scBhi[j] = ex2_h2(scBhi[j]);
    }

    // QK(t+1) -> sn (independent tensor work to fill PV stall gaps)
    if (t + 1 < ntile)
        qk_tile(smem_u32(sH[(t + 1) % 3]), lm_r, lm_m, qaA, qaB,
                snAlo, snAhi, snBlo, snBhi);

    // PV(t): O += P @ V (V row-major, trans-ldsm B-frags)
    uint32_t vb = smem_u32(sV[t % 3]);
    #pragma unroll
    for (int kk = 0; kk < 4; kk++) {
        uint32_t aA0 = scAlo[2 * kk], aA1 = scAhi[2 * kk];
        uint32_t aA2 = scAlo[2 * kk + 1], aA3 = scAhi[2 * kk + 1];
        uint32_t aB0 = scBlo[2 * kk], aB1 = scBhi[2 * kk];
        uint32_t aB2 = scBlo[2 * kk + 1], aB3 = scBhi[2 * kk + 1];
        int vrow = 16 * kk + (lm_m & 1) * 8 + lm_r;   // vrow & 7 == lm_r
        uint32_t rowoff = vb + (uint32_t)(vrow * 128);
        #pragma unroll
        for (int j0 = 0; j0 < 8; j0 += 2) {
            int ch = j0 + (lm_m >> 1);
            uint32_t v0, v1, v2, v3;
            ldsm_x4t(v0, v1, v2, v3, rowoff + (uint32_t)((ch ^ lm_r) << 4));
            mma16816h(oA[j0],     aA0, aA1, aA2, aA3, v0, v1);
            mma16816h(oA[j0 + 1], aA0, aA1, aA2, aA3, v2, v3);
            mma16816h(oB[j0],     aB0, aB1, aB2, aB3, v0, v1);
            mma16816h(oB[j0 + 1], aB0, aB1, aB2, aB3, v2, v3);
        }
    }

    // den trees last (fma pipe overlaps tensor tail)
    den[0] += h2sum_f32(hadd2u(hadd2u(hadd2u(scAlo[0], scAlo[1]), hadd2u(scAlo[2], scAlo[3])),
                               hadd2u(hadd2u(scAlo[4], scAlo[5]), hadd2u(scAlo[6], scAlo[7]))));
    den[1] += h2sum_f32(hadd2u(hadd2u(hadd2u(scAhi[0], scAhi[1]), hadd2u(scAhi[2], scAhi[3])),
                               hadd2u(hadd2u(scAhi[4], scAhi[5]), hadd2u(scAhi[6], scAhi[7]))));
    den[2] += h2sum_f32(hadd2u(hadd2u(hadd2u(scBlo[0], scBlo[1]), hadd2u(scBlo[2], scBlo[3])),
                               hadd2u(hadd2u(scBlo[4], scBlo[5]), hadd2u(scBlo[6], scBlo[7]))));
    den[3] += h2sum_f32(hadd2u(hadd2u(hadd2u(scBhi[0], scBhi[1]), hadd2u(scBhi[2], scBhi[3])),
                               hadd2u(hadd2u(scBhi[4], scBhi[5]), hadd2u(scBhi[6], scBhi[7]))));
}

__global__ void __launch_bounds__(128, 2) flash_kernel(int B, int Ni, int Nu) {
    int l  = blockIdx.z;
    int Nk = (l == 0) ? Ni : Nu;
    int qb = blockIdx.x, split = blockIdx.y;

    const __nv_bfloat16* __restrict__ Hs = g_hidden_bf[l];
    const __half* __restrict__ Vs = g_keys16[l];
    const __nv_bfloat16* __restrict__ Qs = g_qbf[l];

    __shared__ __align__(128) unsigned char sH[3][TILE_B];
    __shared__ __align__(128) unsigned char sV[3][TILE_B];

    int tid = threadIdx.x, lane = tid & 31, warp = tid >> 5;   // 4 warps
    int gid = lane >> 2, tig = lane & 3;
    int lm_r = lane & 7, lm_m = lane >> 3;

    int rowA0 = qb * 128 + warp * 32 + gid;
    int rowA1 = rowA0 + 8;
    int rowB0 = rowA0 + 16;
    int rowB1 = rowA0 + 24;

    uint32_t qaA[4][4], qaB[4][4];
    #pragma unroll
    for (int kk = 0; kk < 4; kk++) {
        int kc = kk * 16 + 2 * tig;
        qaA[kk][0] = (rowA0 < B) ? *(const uint32_t*)&Qs[(size_t)rowA0 * 64 + kc]     : 0u;
        qaA[kk][1] = (rowA1 < B) ? *(const uint32_t*)&Qs[(size_t)rowA1 * 64 + kc]     : 0u;
        qaA[kk][2] = (rowA0 < B) ? *(const uint32_t*)&Qs[(size_t)rowA0 * 64 + kc + 8] : 0u;
        qaA[kk][3] = (rowA1 < B) ? *(const uint32_t*)&Qs[(size_t)rowA1 * 64 + kc + 8] : 0u;
        qaB[kk][0] = (rowB0 < B) ? *(const uint32_t*)&Qs[(size_t)rowB0 * 64 + kc]     : 0u;
        qaB[kk][1] = (rowB1 < B) ? *(const uint32_t*)&Qs[(size_t)rowB1 * 64 + kc]     : 0u;
        qaB[kk][2] = (rowB0 < B) ? *(const uint32_t*)&Qs[(size_t)rowB0 * 64 + kc + 8] : 0u;
        qaB[kk][3] = (rowB1 < B) ? *(const uint32_t*)&Qs[(size_t)rowB1 * 64 + kc + 8] : 0u;
    }

    int ntiles_all = (Nk + 63) >> 6;
    int tiles_per  = (ntiles_all + NSPLIT - 1) / NSPLIT;
    int chunk = tiles_per << 6;
    int kv0   = split * chunk;
    int kvend = min(kv0 + chunk, Nk);
    int ntile = (kvend > kv0) ? ((kvend - kv0 + 63) >> 6) : 0;

    float oA[8][4], oB[8][4];
    #pragma unroll
    for (int j = 0; j < 8; j++)
        #pragma unroll
        for (int q = 0; q < 4; q++) { oA[j][q] = 0.f; oB[j][q] = 0.f; }
    float den[4] = {0.f, 0.f, 0.f, 0.f};

    uint32_t s0Alo[8], s0Ahi[8], s0Blo[8], s0Bhi[8];
    uint32_t s1Alo[8], s1Ahi[8], s1Blo[8], s1Bhi[8];

    // prologue: load tiles 0,1; QK(0) -> s0
    if (ntile > 0) load_tiles(Hs, Vs, smem_u32(sH[0]), smem_u32(sV[0]), kv0, tid);
    CP_COMMIT();
    if (ntile > 1) load_tiles(Hs, Vs, smem_u32(sH[1]), smem_u32(sV[1]), kv0 + 64, tid);
    CP_COMMIT();
    if (ntile > 0) {
        CP_WAIT1();
        __syncthreads();
        qk_tile(smem_u32(sH[0]), lm_r, lm_m, qaA, qaB, s0Alo, s0Ahi, s0Blo, s0Bhi);
    }

    // ping-pong main loop (no register rotation)
    for (int t = 0; t < ntile; t += 2) {
        flash_step(t, ntile, kv0, tid, lm_r, lm_m, Hs, Vs, sH, sV, qaA, qaB,
                   s0Alo, s0Ahi, s0Blo, s0Bhi, s1Alo, s1Ahi, s1Blo, s1Bhi,
                   oA, oB, den);
        if (t + 1 < ntile)
            flash_step(t + 1, ntile, kv0, tid, lm_r, lm_m, Hs, Vs, sH, sV, qaA, qaB,
                       s1Alo, s1Ahi, s1Blo, s1Bhi, s0Alo, s0Ahi, s0Blo, s0Bhi,
                       oA, oB, den);
    }

    // reduce den across the 4 lanes sharing a row; subtract exact padding count
    #pragma unroll
    for (int i = 0; i < 4; i++) {
        den[i] += __shfl_xor_sync(0xffffffffu, den[i], 1);
        den[i] += __shfl_xor_sync(0xffffffffu, den[i], 2);
    }
    float npad = (float)(ntile * 64 - (kvend - kv0));
    #pragma unroll
    for (int i = 0; i < 4; i++) den[i] -= npad;

    if (tig == 0) {
        if (rowA0 < B) g_den[l][split][rowA0] = den[0];
        if (rowA1 < B) g_den[l][split][rowA1] = den[1];
        if (rowB0 < B) g_den[l][split][rowB0] = den[2];
        if (rowB1 < B) g_den[l][split][rowB1] = den[3];
    }
    #pragma unroll
    for (int j = 0; j < 8; j++) {
        int c = 8 * j + 2 * tig;
        if (rowA0 < B) {
            g_num[l][split][rowA0 * 64 + c]     = oA[j][0];
            g_num[l][split][rowA0 * 64 + c + 1] = oA[j][1];
        }
        if (rowA1 < B) {
            g_num[l][split][rowA1 * 64 + c]     = oA[j][2];
            g_num[l][split][rowA1 * 64 + c + 1] = oA[j][3];
        }
        if (rowB0 < B) {
            g_num[l][split][rowB0 * 64 + c]     = oB[j][0];
            g_num[l][split][rowB0 * 64 + c + 1] = oB[j][1];
        }
        if (rowB1 < B) {
            g_num[l][split][rowB1 * 64 + c]     = oB[j][2];
            g_num[l][split][rowB1 * 64 + c + 1] = oB[j][3];
        }
    }
}

// ---------------- kernel 5: combine + epilogue ----------------
__global__ void __launch_bounds__(256) epilogue_kernel(
    const float* __restrict__ uW1, const float* __restrict__ uW2,
    const float* __restrict__ iW1, const float* __restrict__ iW2, int B)
{
    int l = blockIdx.y;
    const float* W1 = (l == 0) ? uW1 : iW1;
    const float* W2 = (l == 0) ? uW2 : iW2;

    __shared__ float sW1[64 * 68];
    __shared__ float sW2[64 * 68];
    __shared__ float sS[64];
    __shared__ float st1[16 * 64];
    __shared__ float st2[16 * 64];
    __shared__ float sden[16];

    int tid = threadIdx.x;
    for (int e = tid; e < 64 * 64; e += 256) {
        int o = e >> 6, d = e & 63;
        sW1[o * 68 + d] = W1[e];
        sW2[o * 68 + d] = W2[e];
    }
    if (tid < 64) sS[tid] = g_S[l][tid];

    int r0 = blockIdx.x * 16;
    if (tid < 16) {
        float dsum = 0.f;
        #pragma unroll
        for (int s = 0; s < NSPLIT; s++) dsum += g_den[l][s][r0 + tid];
        sden[tid] = dsum;
    }
    __syncthreads();

    for (int e = tid; e < 16 * 64; e += 256) {
        int rl = e >> 6, d = e & 63;
        int r = r0 + rl;
        float nsum = 0.f;
        #pragma unroll
        for (int s = 0; s < NSPLIT; s++) nsum += g_num[l][s][r * 64 + d];
        float q  = g_q[l][r * 64 + d];
        float q2 = q + nsum / sden[rl];
        st1[e] = q2 + sS[d];
        st2[e] = q2 * sS[d];
        g_og[l][r * 128 + d] = q;
    }
    __syncthreads();

    int o = tid & 63, rl0 = tid >> 6;
    for (int rl = rl0; rl < 16; rl += 4) {
        float acc = 0.f;
        const float4* t1 = (const float4*)&st1[rl * 64];
        const float4* t2 = (const float4*)&st2[rl * 64];
        const float4* w1 = (const float4*)&sW1[o * 68];
        const float4* w2 = (const float4*)&sW2[o * 68];
        #pragma unroll
        for (int d4 = 0; d4 < 16; d4++) {
            float4 a = t1[d4], b = w1[d4], c = t2[d4], e4 = w2[d4];
            acc += a.x*b.x + a.y*b.y + a.z*b.z + a.w*b.w
                 + c.x*e4.x + c.y*e4.y + c.z*e4.z + c.w*e4.w;
        }
        float out = (acc > 0.f) ? acc : 0.01f * acc;
        g_og[l][(r0 + rl) * 128 + 64 + o] = out;
    }
}

// ---------------- kernel 6: final 128x128 GEMM ----------------
__global__ void __launch_bounds__(256) final_kernel(float* __restrict__ out, int B) {
    int bi = blockIdx.x & 7, bj = blockIdx.x >> 3;
    __shared__ float sU[64 * 16];
    __shared__ float sI[64 * 16];
    int tid = threadIdx.x;
    int ty = tid >> 4, tx = tid & 15;
    float acc = 0.f;
    for (int k0 = 0; k0 < B; k0 += 64) {
        __syncthreads();
        for (int e = tid; e < 64 * 16; e += 256) {
            int kk = e >> 4, c = e & 15;
            sU[e] = g_og[0][(k0 + kk) * 128 + bi * 16 + c];
            sI[e] = g_og[1][(k0 + kk) * 128 + bj * 16 + c];
        }
        __syncthreads();
        #pragma unroll
        for (int kk = 0; kk < 64; kk++)
            acc += sU[kk * 16 + ty] * sI[kk * 16 + tx];
    }
    out[(bi * 16 + ty) * 128 + bj * 16 + tx] = acc;
}

// ---------------- launch ----------------
extern "C" void kernel_launch(void* const* d_in, const int* in_sizes, int n_in,
                              void* d_out, int out_size) {
    const float* user_emb  = (const float*)d_in[0];
    const float* item_emb  = (const float*)d_in[1];
    const float* u_attn_W  = (const float*)d_in[2];
    const float* u_attn_b  = (const float*)d_in[3];
    const float* u_W1      = (const float*)d_in[4];
    const float* u_W2      = (const float*)d_in[5];
    const float* i_attn_W  = (const float*)d_in[6];
    const float* i_attn_b  = (const float*)d_in[7];
    const float* i_W1      = (const float*)d_in[8];
    const float* i_W2      = (const float*)d_in[9];
    const int*   user_id   = (const int*)d_in[10];
    const int*   item_id   = (const int*)d_in[11];
    const int*   all_user_ids = (const int*)d_in[12];
    const int*   all_item_ids = (const int*)d_in[13];

    int B  = in_sizes[10]; if (B > BMAX) B = BMAX;
    int Nu = in_sizes[12]; if (Nu > NMAX) Nu = NMAX;
    int Ni = in_sizes[13]; if (Ni > NMAX) Ni = NMAX;
    float* out = (float*)d_out;

    zero_kernel<<<1, 128>>>();
    hidden_kernel<<<dim3(148, 2), 256>>>(user_emb, item_emb, all_user_ids, all_item_ids,
                                         u_attn_W, u_attn_b, i_attn_W, i_attn_b, Ni, Nu);
    int total = B * 64;
    gather_q_kernel<<<(2 * total + 255) / 256, 256>>>(user_emb, item_emb, user_id, item_id,
                                                      all_user_ids, all_item_ids, B);
    int qblocks = (B + 127) / 128;
    flash_kernel<<<dim3(qblocks, NSPLIT, 2), 128>>>(B, Ni, Nu);
    epilogue_kernel<<<dim3(B / 16, 2), 256>>>(u_W1, u_W2, i_W1, i_W2, B);
    final_kernel<<<64, 256>>>(out, B);
}